// round 1
// baseline (speedup 1.0000x reference)
#include <cuda_runtime.h>
#include <cuda_bf16.h>
#include <cstdint>

// Problem constants
#define BATCH 4
#define SEQ   2048
#define DMODEL 1024
#define NHEAD 8
#define HD    128
#define MROWS (BATCH*SEQ)        // 8192
#define DFF   4096

// ---------------- scratch (no allocations allowed) ----------------
__device__ float g_Q[(size_t)MROWS * DMODEL];     // also reused as ff2 output
__device__ float g_K[(size_t)MROWS * DMODEL];
__device__ float g_V[(size_t)MROWS * DMODEL];
__device__ float g_mh[(size_t)MROWS * DMODEL];
__device__ float g_res1[(size_t)MROWS * DMODEL];
__device__ float g_ff1[(size_t)MROWS * DFF];

// =====================================================================
// SGEMM: C = A[M,K] @ B[K,N] + bias, 128x128 block tile, 8x8 thread tile
// mode 0: plain   mode 1: ReLU   mode 2: permute output to [B,H,S,hd]
// M,N,K all multiples of 128/8 for this problem — no bounds checks.
// =====================================================================
__global__ __launch_bounds__(256) void sgemm128(
    const float* __restrict__ A, const float* __restrict__ B,
    const float* __restrict__ bias, float* __restrict__ C,
    int M, int N, int K, int mode)
{
    __shared__ float As[8][128];
    __shared__ float Bs[8][128];

    const int tid  = threadIdx.x;
    const int trow = tid >> 4;      // 0..15 (M dir)
    const int tcol = tid & 15;      // 0..15 (N dir)

    const float* Ab = A + (size_t)blockIdx.y * 128 * K;
    const float* Bb = B + (size_t)blockIdx.x * 128;

    float acc[8][8];
    #pragma unroll
    for (int i = 0; i < 8; i++)
        #pragma unroll
        for (int j = 0; j < 8; j++) acc[i][j] = 0.f;

    const int aRow = tid >> 1;          // 128 rows, 2 threads/row
    const int aCol = (tid & 1) * 4;     // float4
    const int bRow = tid >> 5;          // 8 rows, 32 threads/row
    const int bCol = (tid & 31) * 4;

    for (int k0 = 0; k0 < K; k0 += 8) {
        float4 a4 = *(const float4*)(Ab + (size_t)aRow * K + k0 + aCol);
        As[aCol + 0][aRow] = a4.x;
        As[aCol + 1][aRow] = a4.y;
        As[aCol + 2][aRow] = a4.z;
        As[aCol + 3][aRow] = a4.w;
        float4 b4 = *(const float4*)(Bb + (size_t)(k0 + bRow) * N + bCol);
        *(float4*)&Bs[bRow][bCol] = b4;
        __syncthreads();

        #pragma unroll
        for (int kk = 0; kk < 8; kk++) {
            float ar[8], br[8];
            #pragma unroll
            for (int i = 0; i < 8; i++) ar[i] = As[kk][trow * 8 + i];
            #pragma unroll
            for (int j = 0; j < 8; j++) br[j] = Bs[kk][tcol * 8 + j];
            #pragma unroll
            for (int i = 0; i < 8; i++)
                #pragma unroll
                for (int j = 0; j < 8; j++)
                    acc[i][j] = fmaf(ar[i], br[j], acc[i][j]);
        }
        __syncthreads();
    }

    const int m0 = blockIdx.y * 128 + trow * 8;
    const int n0 = blockIdx.x * 128 + tcol * 8;

    #pragma unroll
    for (int i = 0; i < 8; i++) {
        #pragma unroll
        for (int j = 0; j < 8; j++) {
            float v = acc[i][j] + bias[n0 + j];
            if (mode == 1) v = fmaxf(v, 0.f);
            if (mode == 2) {
                int m = m0 + i, n = n0 + j;
                int b = m >> 11, s = m & (SEQ - 1);
                int h = n >> 7,  d = n & (HD - 1);
                C[(((size_t)b * NHEAD + h) * SEQ + s) * HD + d] = v;
            } else {
                C[(size_t)(m0 + i) * N + (n0 + j)] = v;
            }
        }
    }
}

// =====================================================================
// Attention: per (b,h), flash-style. 64-query x 64-key tiles, hd=128.
// Q,K,V in [B,H,S,hd]; output written merged to mh[B,S,D].
// 256 threads: ty=tid/16 (4 query rows each), tx=tid%16.
// =====================================================================
#define ALDQ 132   // padded leading dim for 64x128 tiles
#define ALDP 68    // padded leading dim for 64x64 P tile
#define ATTN_SMEM ((64*ALDQ*2 + 64*ALDP) * 4)

__global__ __launch_bounds__(256) void attn_kernel(
    const float* __restrict__ Q, const float* __restrict__ K,
    const float* __restrict__ V, float* __restrict__ mh)
{
    extern __shared__ float sm[];
    float* Qs  = sm;                    // [64][132]
    float* KVs = Qs + 64 * ALDQ;        // [64][132]
    float* Ps  = KVs + 64 * ALDQ;       // [64][68]

    const int tid = threadIdx.x;
    const int ty  = tid >> 4;     // 0..15
    const int tx  = tid & 15;     // 0..15
    const int qb  = blockIdx.x;   // query tile (32)
    const int bh  = blockIdx.y;   // b*H+h (32)
    const float scale = 0.08838834764831845f;   // 1/sqrt(128)

    // load + pre-scale Q tile
    const float* Qg = Q + ((size_t)bh * SEQ + qb * 64) * HD;
    for (int i = tid; i < 64 * (HD / 4); i += 256) {
        int r = i >> 5;            // /32 float4 per row
        int c4 = (i & 31) * 4;
        float4 v4 = *(const float4*)(Qg + (size_t)r * HD + c4);
        Qs[r * ALDQ + c4 + 0] = v4.x * scale;
        Qs[r * ALDQ + c4 + 1] = v4.y * scale;
        Qs[r * ALDQ + c4 + 2] = v4.z * scale;
        Qs[r * ALDQ + c4 + 3] = v4.w * scale;
    }

    float m_i[4], l_i[4], o[4][8];
    #pragma unroll
    for (int i = 0; i < 4; i++) {
        m_i[i] = -1e30f; l_i[i] = 0.f;
        #pragma unroll
        for (int c = 0; c < 8; c++) o[i][c] = 0.f;
    }
    __syncthreads();

    for (int kt = 0; kt < SEQ / 64; kt++) {
        // ---- load K tile ----
        const float* Kg = K + ((size_t)bh * SEQ + kt * 64) * HD;
        for (int i = tid; i < 64 * (HD / 4); i += 256) {
            int r = i >> 5;
            int c4 = (i & 31) * 4;
            *(float4*)&KVs[r * ALDQ + c4] = *(const float4*)(Kg + (size_t)r * HD + c4);
        }
        __syncthreads();

        // ---- scores S = Q K^T (4x4 per thread) ----
        float s[4][4];
        #pragma unroll
        for (int i = 0; i < 4; i++)
            #pragma unroll
            for (int j = 0; j < 4; j++) s[i][j] = 0.f;

        #pragma unroll 4
        for (int kk = 0; kk < HD; kk++) {
            float qr[4], kr[4];
            #pragma unroll
            for (int i = 0; i < 4; i++) qr[i] = Qs[(4 * ty + i) * ALDQ + kk];
            #pragma unroll
            for (int j = 0; j < 4; j++) kr[j] = KVs[(4 * tx + j) * ALDQ + kk];
            #pragma unroll
            for (int i = 0; i < 4; i++)
                #pragma unroll
                for (int j = 0; j < 4; j++)
                    s[i][j] = fmaf(qr[i], kr[j], s[i][j]);
        }

        // ---- online softmax ----
        #pragma unroll
        for (int i = 0; i < 4; i++) {
            float mt = fmaxf(fmaxf(s[i][0], s[i][1]), fmaxf(s[i][2], s[i][3]));
            #pragma unroll
            for (int off = 8; off > 0; off >>= 1)
                mt = fmaxf(mt, __shfl_xor_sync(0xffffffffu, mt, off, 16));
            float mnew = fmaxf(m_i[i], mt);
            float alpha = __expf(m_i[i] - mnew);
            m_i[i] = mnew;
            float rs = 0.f;
            #pragma unroll
            for (int j = 0; j < 4; j++) {
                float p = __expf(s[i][j] - mnew);
                Ps[(4 * ty + i) * ALDP + 4 * tx + j] = p;
                rs += p;
            }
            #pragma unroll
            for (int off = 8; off > 0; off >>= 1)
                rs += __shfl_xor_sync(0xffffffffu, rs, off, 16);
            l_i[i] = l_i[i] * alpha + rs;
            #pragma unroll
            for (int c = 0; c < 8; c++) o[i][c] *= alpha;
        }
        __syncthreads();   // Ps written; done reading K

        // ---- load V tile over K ----
        const float* Vg = V + ((size_t)bh * SEQ + kt * 64) * HD;
        for (int i = tid; i < 64 * (HD / 4); i += 256) {
            int r = i >> 5;
            int c4 = (i & 31) * 4;
            *(float4*)&KVs[r * ALDQ + c4] = *(const float4*)(Vg + (size_t)r * HD + c4);
        }
        __syncthreads();

        // ---- O += P V  (thread: rows 4ty+i, cols tx + 16*cc) ----
        #pragma unroll 4
        for (int jj = 0; jj < 64; jj++) {
            float vr[8];
            #pragma unroll
            for (int c = 0; c < 8; c++) vr[c] = KVs[jj * ALDQ + tx + 16 * c];
            #pragma unroll
            for (int i = 0; i < 4; i++) {
                float p = Ps[(4 * ty + i) * ALDP + jj];
                #pragma unroll
                for (int c = 0; c < 8; c++) o[i][c] = fmaf(p, vr[c], o[i][c]);
            }
        }
        __syncthreads();   // done reading V & Ps before next tile
    }

    // ---- write merged-head output to mh[B,S,D] ----
    const int b = bh >> 3, h = bh & 7;
    #pragma unroll
    for (int i = 0; i < 4; i++) {
        float inv = 1.f / l_i[i];
        int srow = qb * 64 + 4 * ty + i;
        float* dst = mh + ((size_t)b * SEQ + srow) * DMODEL + h * HD;
        #pragma unroll
        for (int c = 0; c < 8; c++) dst[tx + 16 * c] = o[i][c] * inv;
    }
}

// =====================================================================
// LayerNorm (ddof=1, no eps) + residual: out = res + (x-mean)/std(x)
// one block per row of D=1024
// =====================================================================
__global__ __launch_bounds__(256) void ln_res_kernel(
    const float* __restrict__ x, const float* __restrict__ res,
    float* __restrict__ out)
{
    const int D = DMODEL;
    const size_t row = blockIdx.x;
    const float* xr = x + row * D;

    float s = 0.f, ss = 0.f;
    for (int i = threadIdx.x; i < D; i += 256) {
        float v = xr[i];
        s += v; ss = fmaf(v, v, ss);
    }
    // block reduce (8 warps)
    #pragma unroll
    for (int off = 16; off > 0; off >>= 1) {
        s  += __shfl_xor_sync(0xffffffffu, s, off);
        ss += __shfl_xor_sync(0xffffffffu, ss, off);
    }
    __shared__ float sa[8], sb[8];
    int w = threadIdx.x >> 5, l = threadIdx.x & 31;
    if (l == 0) { sa[w] = s; sb[w] = ss; }
    __syncthreads();
    if (threadIdx.x < 32) {
        s  = (l < 8) ? sa[l] : 0.f;
        ss = (l < 8) ? sb[l] : 0.f;
        #pragma unroll
        for (int off = 4; off > 0; off >>= 1) {
            s  += __shfl_xor_sync(0xffffffffu, s, off);
            ss += __shfl_xor_sync(0xffffffffu, ss, off);
        }
        if (l == 0) { sa[0] = s; sb[0] = ss; }
    }
    __syncthreads();
    s = sa[0]; ss = sb[0];

    float mean = s / (float)D;
    float var  = (ss - s * s / (float)D) / (float)(D - 1);
    float rstd = rsqrtf(var);

    const float* rr = res + row * D;
    float* orow = out + row * D;
    for (int i = threadIdx.x; i < D; i += 256)
        orow[i] = rr[i] + (xr[i] - mean) * rstd;
}

// =====================================================================
extern "C" void kernel_launch(void* const* d_in, const int* in_sizes, int n_in,
                              void* d_out, int out_size)
{
    const float* q  = (const float*)d_in[0];
    const float* k  = (const float*)d_in[1];
    const float* v  = (const float*)d_in[2];
    const float* Wq = (const float*)d_in[3];
    const float* bq = (const float*)d_in[4];
    const float* Wk = (const float*)d_in[5];
    const float* bk = (const float*)d_in[6];
    const float* Wv = (const float*)d_in[7];
    const float* bv = (const float*)d_in[8];
    const float* W1 = (const float*)d_in[9];
    const float* b1 = (const float*)d_in[10];
    const float* W2 = (const float*)d_in[11];
    const float* b2 = (const float*)d_in[12];

    float *Qp, *Kp, *Vp, *mh, *res1, *ff1;
    cudaGetSymbolAddress((void**)&Qp,   g_Q);
    cudaGetSymbolAddress((void**)&Kp,   g_K);
    cudaGetSymbolAddress((void**)&Vp,   g_V);
    cudaGetSymbolAddress((void**)&mh,   g_mh);
    cudaGetSymbolAddress((void**)&res1, g_res1);
    cudaGetSymbolAddress((void**)&ff1,  g_ff1);

    cudaFuncSetAttribute(attn_kernel,
                         cudaFuncAttributeMaxDynamicSharedMemorySize, ATTN_SMEM);

    dim3 blk(256);
    dim3 gProj(DMODEL / 128, MROWS / 128);    // (8, 64)

    // NOTE input permutation: Encoder calls multihead(v, q, k):
    //   Q-proj input = v, K-proj input = q, V-proj input = k
    sgemm128<<<gProj, blk>>>(v, Wq, bq, Qp, MROWS, DMODEL, DMODEL, 2);
    sgemm128<<<gProj, blk>>>(q, Wk, bk, Kp, MROWS, DMODEL, DMODEL, 2);
    sgemm128<<<gProj, blk>>>(k, Wv, bv, Vp, MROWS, DMODEL, DMODEL, 2);

    attn_kernel<<<dim3(SEQ / 64, BATCH * NHEAD), blk, ATTN_SMEM>>>(Qp, Kp, Vp, mh);

    ln_res_kernel<<<MROWS, blk>>>(mh, q, res1);

    sgemm128<<<dim3(DFF / 128, MROWS / 128), blk>>>(res1, W1, b1, ff1,
                                                    MROWS, DFF, DMODEL, 1);
    // reuse g_Q as ff2 output
    sgemm128<<<gProj, blk>>>(ff1, W2, b2, Qp, MROWS, DMODEL, DFF, 0);

    ln_res_kernel<<<MROWS, blk>>>(Qp, res1, (float*)d_out);
}

// round 3
// speedup vs baseline: 1.8041x; 1.8041x over previous
#include <cuda_runtime.h>
#include <cuda_bf16.h>
#include <cstdint>

// Problem constants
#define BATCH 4
#define SEQ   2048
#define DMODEL 1024
#define NHEAD 8
#define HD    128
#define MROWS (BATCH*SEQ)        // 8192
#define DFF   4096

// ---------------- scratch (no allocations allowed) ----------------
__device__ float g_Q[(size_t)MROWS * DMODEL];     // also reused as ff2 output
__device__ float g_K[(size_t)MROWS * DMODEL];
__device__ float g_V[(size_t)MROWS * DMODEL];
__device__ float g_mh[(size_t)MROWS * DMODEL];
__device__ float g_res1[(size_t)MROWS * DMODEL];
__device__ float g_ff1[(size_t)MROWS * DFF];
__device__ __nv_bfloat16 g_Ahi[(size_t)MROWS * DFF];
__device__ __nv_bfloat16 g_Alo[(size_t)MROWS * DFF];
__device__ __nv_bfloat16 g_Bhi[(size_t)DFF * DMODEL];
__device__ __nv_bfloat16 g_Blo[(size_t)DFF * DMODEL];

// ======================= PTX helpers =======================
__device__ __forceinline__ uint32_t smem_u32(const void* p) {
    uint32_t a;
    asm("{ .reg .u64 t; cvta.to.shared.u64 t, %1; cvt.u32.u64 %0, t; }" : "=r"(a) : "l"(p));
    return a;
}
__device__ __forceinline__ void cp_async16(uint32_t saddr, const void* gaddr) {
    asm volatile("cp.async.cg.shared.global [%0], [%1], 16;" :: "r"(saddr), "l"(gaddr) : "memory");
}
#define CP_COMMIT() asm volatile("cp.async.commit_group;" ::: "memory")

__device__ __forceinline__ void ldmx4(uint32_t* r, uint32_t addr) {
    asm volatile("ldmatrix.sync.aligned.m8n8.x4.shared.b16 {%0,%1,%2,%3}, [%4];"
                 : "=r"(r[0]), "=r"(r[1]), "=r"(r[2]), "=r"(r[3]) : "r"(addr));
}
__device__ __forceinline__ void mma_bf16(float* c, const uint32_t* a,
                                         uint32_t b0, uint32_t b1) {
    asm volatile(
        "mma.sync.aligned.m16n8k16.row.col.f32.bf16.bf16.f32 "
        "{%0,%1,%2,%3}, {%4,%5,%6,%7}, {%8,%9}, {%0,%1,%2,%3};"
        : "+f"(c[0]), "+f"(c[1]), "+f"(c[2]), "+f"(c[3])
        : "r"(a[0]), "r"(a[1]), "r"(a[2]), "r"(a[3]), "r"(b0), "r"(b1));
}

// =====================================================================
// split conversion: x -> (hi, lo) bf16
// =====================================================================
__global__ __launch_bounds__(256) void conv_split(
    const float* __restrict__ x, __nv_bfloat16* __restrict__ hi,
    __nv_bfloat16* __restrict__ lo, int n4)
{
    int i = blockIdx.x * 256 + threadIdx.x;
    if (i >= n4) return;
    float4 v = ((const float4*)x)[i];
    __nv_bfloat16 h0 = __float2bfloat16(v.x), h1 = __float2bfloat16(v.y);
    __nv_bfloat16 h2 = __float2bfloat16(v.z), h3 = __float2bfloat16(v.w);
    __nv_bfloat16 l0 = __float2bfloat16(v.x - __bfloat162float(h0));
    __nv_bfloat16 l1 = __float2bfloat16(v.y - __bfloat162float(h1));
    __nv_bfloat16 l2 = __float2bfloat16(v.z - __bfloat162float(h2));
    __nv_bfloat16 l3 = __float2bfloat16(v.w - __bfloat162float(h3));
    __nv_bfloat162* hp = (__nv_bfloat162*)(hi + (size_t)i * 4);
    __nv_bfloat162* lp = (__nv_bfloat162*)(lo + (size_t)i * 4);
    hp[0] = __nv_bfloat162(h0, h1); hp[1] = __nv_bfloat162(h2, h3);
    lp[0] = __nv_bfloat162(l0, l1); lp[1] = __nv_bfloat162(l2, l3);
}

// =====================================================================
// weight transpose + split: W[K,N] -> Bt[N,K] hi/lo
// =====================================================================
__global__ __launch_bounds__(256) void conv_wt_T(
    const float* __restrict__ W, __nv_bfloat16* __restrict__ hi,
    __nv_bfloat16* __restrict__ lo, int K, int N)
{
    __shared__ float t[32][33];
    int k0 = blockIdx.y * 32, n0 = blockIdx.x * 32;
    int tx = threadIdx.x & 31, ty = threadIdx.x >> 5;   // 32 x 8
    #pragma unroll
    for (int i = ty; i < 32; i += 8)
        t[i][tx] = W[(size_t)(k0 + i) * N + n0 + tx];
    __syncthreads();
    #pragma unroll
    for (int i = ty; i < 32; i += 8) {
        float v = t[tx][i];                     // = W[k0+tx][n0+i]
        __nv_bfloat16 h = __float2bfloat16(v);
        __nv_bfloat16 l = __float2bfloat16(v - __bfloat162float(h));
        size_t idx = (size_t)(n0 + i) * K + k0 + tx;
        hi[idx] = h; lo[idx] = l;
    }
}

// =====================================================================
// mma.sync split-bf16 GEMM: C[M,N] = A[M,K] @ Bt[N,K]^T + bias
// BM=128, BN=128, BK=32. 8 warps, each 32(M)x64(N).
// modes: 0 plain, 1 ReLU, 2 permute to [B,H,S,hd]
// smem rows padded to 80B (20 words, gcd-free mod 32 -> conflict-free ldmatrix)
// =====================================================================
#define BM 128
#define BN 128
#define BK 32
#define ROWB 80                      // bytes per smem row (64 data + 16 pad)
#define OPB  (128 * ROWB)            // one operand tile: 10240 B
#define STAGE_B (4 * OPB)            // Ahi,Alo,Bhi,Blo : 40960 B
#define NSTAGE 3
#define GEMM_SMEM (NSTAGE * STAGE_B) // 122880 B

__device__ __forceinline__ void prefetch_chunk(
    uint32_t sbase, int stage, int c,
    const __nv_bfloat16* Ahi, const __nv_bfloat16* Alo,
    const __nv_bfloat16* Bhi, const __nv_bfloat16* Blo,
    int m0, int n0, int K, int tid)
{
    const int k0 = c * BK;
    const uint32_t sb = sbase + stage * STAGE_B;
    #pragma unroll
    for (int t = 0; t < 2; t++) {
        int seg = tid + 256 * t;          // 0..511
        int row = seg >> 2;               // 0..127
        int sc  = seg & 3;                // 16B segment within 64B row
        uint32_t soff = row * ROWB + sc * 16;
        size_t ga = (size_t)(m0 + row) * K + k0 + sc * 8;
        size_t gb = (size_t)(n0 + row) * K + k0 + sc * 8;
        cp_async16(sb + soff,           Ahi + ga);
        cp_async16(sb + OPB + soff,     Alo + ga);
        cp_async16(sb + 2 * OPB + soff, Bhi + gb);
        cp_async16(sb + 3 * OPB + soff, Blo + gb);
    }
}

__global__ __launch_bounds__(256, 1) void gemm_mma(
    const __nv_bfloat16* __restrict__ Ahi, const __nv_bfloat16* __restrict__ Alo,
    const __nv_bfloat16* __restrict__ Bhi, const __nv_bfloat16* __restrict__ Blo,
    const float* __restrict__ bias, float* __restrict__ C,
    int M, int N, int K, int mode)
{
    extern __shared__ char smem[];
    const uint32_t sbase = smem_u32(smem);
    const int tid = threadIdx.x;
    const int wid = tid >> 5, lane = tid & 31;
    const int wm = wid >> 1;             // 0..3 -> M offset wm*32
    const int wn = wid & 1;              // 0..1 -> N offset wn*64
    const int m0 = blockIdx.y * BM, n0 = blockIdx.x * BN;
    const int NC = K / BK;

    float acc[2][8][4];
    #pragma unroll
    for (int i = 0; i < 2; i++)
        #pragma unroll
        for (int j = 0; j < 8; j++)
            #pragma unroll
            for (int x = 0; x < 4; x++) acc[i][j][x] = 0.f;

    prefetch_chunk(sbase, 0, 0, Ahi, Alo, Bhi, Blo, m0, n0, K, tid); CP_COMMIT();
    prefetch_chunk(sbase, 1, 1, Ahi, Alo, Bhi, Blo, m0, n0, K, tid); CP_COMMIT();

    // ldmatrix lane address pattern: (lane&15) = row-within-16, (lane>>4) = +8 cols (16B)
    const uint32_t lrow = (lane & 15);
    const uint32_t lcol = (lane >> 4) * 16;

    for (int c = 0; c < NC; c++) {
        const int sc = c % NSTAGE;
        if (c + 2 < NC) { asm volatile("cp.async.wait_group 1;" ::: "memory"); }
        else            { asm volatile("cp.async.wait_group 0;" ::: "memory"); }
        __syncthreads();

        const uint32_t stg = sbase + sc * STAGE_B;
        const uint32_t aBase = stg + (wm * 32) * ROWB + lrow * ROWB + lcol;
        const uint32_t bBase = stg + 2 * OPB + (wn * 64) * ROWB + lrow * ROWB + lcol;

        #pragma unroll
        for (int kk = 0; kk < 2; kk++) {              // two k16 steps per BK=32
            const uint32_t kb = kk * 32;              // 16 bf16 = 32 bytes
            uint32_t ah[2][4], al[2][4];
            #pragma unroll
            for (int mt = 0; mt < 2; mt++) {
                ldmx4(ah[mt], aBase + mt * 16 * ROWB + kb);
                ldmx4(al[mt], aBase + OPB + mt * 16 * ROWB + kb);
            }
            uint32_t bh[4][4], bl[4][4];
            #pragma unroll
            for (int p = 0; p < 4; p++) {
                ldmx4(bh[p], bBase + p * 16 * ROWB + kb);
                ldmx4(bl[p], bBase + OPB + p * 16 * ROWB + kb);
            }
            // matrices from B x4: r0 = ntile(2p) k0-7, r1 = ntile(2p+1) k0-7,
            //                     r2 = ntile(2p) k8-15, r3 = ntile(2p+1) k8-15
            #pragma unroll
            for (int mt = 0; mt < 2; mt++) {
                #pragma unroll
                for (int p = 0; p < 4; p++) {
                    mma_bf16(acc[mt][2*p],   ah[mt], bh[p][0], bh[p][2]);
                    mma_bf16(acc[mt][2*p+1], ah[mt], bh[p][1], bh[p][3]);
                    mma_bf16(acc[mt][2*p],   ah[mt], bl[p][0], bl[p][2]);
                    mma_bf16(acc[mt][2*p+1], ah[mt], bl[p][1], bl[p][3]);
                    mma_bf16(acc[mt][2*p],   al[mt], bh[p][0], bh[p][2]);
                    mma_bf16(acc[mt][2*p+1], al[mt], bh[p][1], bh[p][3]);
                }
            }
        }
        __syncthreads();
        if (c + 2 < NC) {
            prefetch_chunk(sbase, (c + 2) % NSTAGE, c + 2, Ahi, Alo, Bhi, Blo, m0, n0, K, tid);
            CP_COMMIT();
        }
    }

    // ---- epilogue: registers -> gmem, fused bias / relu / head-permute ----
    const int rbase = m0 + wm * 32 + (lane >> 2);
    const int cbase = n0 + wn * 64 + (lane & 3) * 2;
    #pragma unroll
    for (int mt = 0; mt < 2; mt++) {
        #pragma unroll
        for (int nt = 0; nt < 8; nt++) {
            const int col = cbase + nt * 8;
            const float bz0 = bias[col], bz1 = bias[col + 1];
            #pragma unroll
            for (int h = 0; h < 2; h++) {
                const int row = rbase + mt * 16 + h * 8;
                float v0 = acc[mt][nt][2*h]   + bz0;
                float v1 = acc[mt][nt][2*h+1] + bz1;
                if (mode == 1) { v0 = fmaxf(v0, 0.f); v1 = fmaxf(v1, 0.f); }
                if (mode == 2) {
                    const int b = row >> 11, s = row & (SEQ - 1);
                    const int hh = col >> 7, d = col & (HD - 1);
                    float* dst = C + (((size_t)b * NHEAD + hh) * SEQ + s) * HD + d;
                    dst[0] = v0; dst[1] = v1;
                } else {
                    float* dst = C + (size_t)row * N + col;
                    dst[0] = v0; dst[1] = v1;
                }
            }
        }
    }
}

// =====================================================================
// Attention: per (b,h), flash-style fp32 (unchanged)
// =====================================================================
#define ALDQ 132
#define ALDP 68
#define ATTN_SMEM ((64*ALDQ*2 + 64*ALDP) * 4)

__global__ __launch_bounds__(256) void attn_kernel(
    const float* __restrict__ Q, const float* __restrict__ K,
    const float* __restrict__ V, float* __restrict__ mh)
{
    extern __shared__ float sm[];
    float* Qs  = sm;
    float* KVs = Qs + 64 * ALDQ;
    float* Ps  = KVs + 64 * ALDQ;

    const int tid = threadIdx.x;
    const int ty  = tid >> 4;
    const int tx  = tid & 15;
    const int qb  = blockIdx.x;
    const int bh  = blockIdx.y;
    const float scale = 0.08838834764831845f;

    const float* Qg = Q + ((size_t)bh * SEQ + qb * 64) * HD;
    for (int i = tid; i < 64 * (HD / 4); i += 256) {
        int r = i >> 5;
        int c4 = (i & 31) * 4;
        float4 v4 = *(const float4*)(Qg + (size_t)r * HD + c4);
        Qs[r * ALDQ + c4 + 0] = v4.x * scale;
        Qs[r * ALDQ + c4 + 1] = v4.y * scale;
        Qs[r * ALDQ + c4 + 2] = v4.z * scale;
        Qs[r * ALDQ + c4 + 3] = v4.w * scale;
    }

    float m_i[4], l_i[4], o[4][8];
    #pragma unroll
    for (int i = 0; i < 4; i++) {
        m_i[i] = -1e30f; l_i[i] = 0.f;
        #pragma unroll
        for (int c = 0; c < 8; c++) o[i][c] = 0.f;
    }
    __syncthreads();

    for (int kt = 0; kt < SEQ / 64; kt++) {
        const float* Kg = K + ((size_t)bh * SEQ + kt * 64) * HD;
        for (int i = tid; i < 64 * (HD / 4); i += 256) {
            int r = i >> 5;
            int c4 = (i & 31) * 4;
            *(float4*)&KVs[r * ALDQ + c4] = *(const float4*)(Kg + (size_t)r * HD + c4);
        }
        __syncthreads();

        float s[4][4];
        #pragma unroll
        for (int i = 0; i < 4; i++)
            #pragma unroll
            for (int j = 0; j < 4; j++) s[i][j] = 0.f;

        #pragma unroll 4
        for (int kk = 0; kk < HD; kk++) {
            float qr[4], kr[4];
            #pragma unroll
            for (int i = 0; i < 4; i++) qr[i] = Qs[(4 * ty + i) * ALDQ + kk];
            #pragma unroll
            for (int j = 0; j < 4; j++) kr[j] = KVs[(4 * tx + j) * ALDQ + kk];
            #pragma unroll
            for (int i = 0; i < 4; i++)
                #pragma unroll
                for (int j = 0; j < 4; j++)
                    s[i][j] = fmaf(qr[i], kr[j], s[i][j]);
        }

        #pragma unroll
        for (int i = 0; i < 4; i++) {
            float mt = fmaxf(fmaxf(s[i][0], s[i][1]), fmaxf(s[i][2], s[i][3]));
            #pragma unroll
            for (int off = 8; off > 0; off >>= 1)
                mt = fmaxf(mt, __shfl_xor_sync(0xffffffffu, mt, off, 16));
            float mnew = fmaxf(m_i[i], mt);
            float alpha = __expf(m_i[i] - mnew);
            m_i[i] = mnew;
            float rs = 0.f;
            #pragma unroll
            for (int j = 0; j < 4; j++) {
                float p = __expf(s[i][j] - mnew);
                Ps[(4 * ty + i) * ALDP + 4 * tx + j] = p;
                rs += p;
            }
            #pragma unroll
            for (int off = 8; off > 0; off >>= 1)
                rs += __shfl_xor_sync(0xffffffffu, rs, off, 16);
            l_i[i] = l_i[i] * alpha + rs;
            #pragma unroll
            for (int c = 0; c < 8; c++) o[i][c] *= alpha;
        }
        __syncthreads();

        const float* Vg = V + ((size_t)bh * SEQ + kt * 64) * HD;
        for (int i = tid; i < 64 * (HD / 4); i += 256) {
            int r = i >> 5;
            int c4 = (i & 31) * 4;
            *(float4*)&KVs[r * ALDQ + c4] = *(const float4*)(Vg + (size_t)r * HD + c4);
        }
        __syncthreads();

        #pragma unroll 4
        for (int jj = 0; jj < 64; jj++) {
            float vr[8];
            #pragma unroll
            for (int c = 0; c < 8; c++) vr[c] = KVs[jj * ALDQ + tx + 16 * c];
            #pragma unroll
            for (int i = 0; i < 4; i++) {
                float p = Ps[(4 * ty + i) * ALDP + jj];
                #pragma unroll
                for (int c = 0; c < 8; c++) o[i][c] = fmaf(p, vr[c], o[i][c]);
            }
        }
        __syncthreads();
    }

    const int b = bh >> 3, h = bh & 7;
    #pragma unroll
    for (int i = 0; i < 4; i++) {
        float inv = 1.f / l_i[i];
        int srow = qb * 64 + 4 * ty + i;
        float* dst = mh + ((size_t)b * SEQ + srow) * DMODEL + h * HD;
        #pragma unroll
        for (int c = 0; c < 8; c++) dst[tx + 16 * c] = o[i][c] * inv;
    }
}

// =====================================================================
// LayerNorm (ddof=1, no eps) + residual (unchanged)
// =====================================================================
__global__ __launch_bounds__(256) void ln_res_kernel(
    const float* __restrict__ x, const float* __restrict__ res,
    float* __restrict__ out)
{
    const int D = DMODEL;
    const size_t row = blockIdx.x;
    const float* xr = x + row * D;

    float s = 0.f, ss = 0.f;
    for (int i = threadIdx.x; i < D; i += 256) {
        float v = xr[i];
        s += v; ss = fmaf(v, v, ss);
    }
    #pragma unroll
    for (int off = 16; off > 0; off >>= 1) {
        s  += __shfl_xor_sync(0xffffffffu, s, off);
        ss += __shfl_xor_sync(0xffffffffu, ss, off);
    }
    __shared__ float sa[8], sb[8];
    int w = threadIdx.x >> 5, l = threadIdx.x & 31;
    if (l == 0) { sa[w] = s; sb[w] = ss; }
    __syncthreads();
    if (threadIdx.x < 32) {
        s  = (l < 8) ? sa[l] : 0.f;
        ss = (l < 8) ? sb[l] : 0.f;
        #pragma unroll
        for (int off = 4; off > 0; off >>= 1) {
            s  += __shfl_xor_sync(0xffffffffu, s, off);
            ss += __shfl_xor_sync(0xffffffffu, ss, off);
        }
        if (l == 0) { sa[0] = s; sb[0] = ss; }
    }
    __syncthreads();
    s = sa[0]; ss = sb[0];

    float mean = s / (float)D;
    float var  = (ss - s * s / (float)D) / (float)(D - 1);
    float rstd = rsqrtf(var);

    const float* rr = res + row * D;
    float* orow = out + row * D;
    for (int i = threadIdx.x; i < D; i += 256)
        orow[i] = rr[i] + (xr[i] - mean) * rstd;
}

// =====================================================================
extern "C" void kernel_launch(void* const* d_in, const int* in_sizes, int n_in,
                              void* d_out, int out_size)
{
    const float* q  = (const float*)d_in[0];
    const float* k  = (const float*)d_in[1];
    const float* v  = (const float*)d_in[2];
    const float* Wq = (const float*)d_in[3];
    const float* bq = (const float*)d_in[4];
    const float* Wk = (const float*)d_in[5];
    const float* bk = (const float*)d_in[6];
    const float* Wv = (const float*)d_in[7];
    const float* bv = (const float*)d_in[8];
    const float* W1 = (const float*)d_in[9];
    const float* b1 = (const float*)d_in[10];
    const float* W2 = (const float*)d_in[11];
    const float* b2 = (const float*)d_in[12];

    float *Qp, *Kp, *Vp, *mh, *res1, *ff1;
    __nv_bfloat16 *Ahi, *Alo, *Bhi, *Blo;
    cudaGetSymbolAddress((void**)&Qp,   g_Q);
    cudaGetSymbolAddress((void**)&Kp,   g_K);
    cudaGetSymbolAddress((void**)&Vp,   g_V);
    cudaGetSymbolAddress((void**)&mh,   g_mh);
    cudaGetSymbolAddress((void**)&res1, g_res1);
    cudaGetSymbolAddress((void**)&ff1,  g_ff1);
    cudaGetSymbolAddress((void**)&Ahi,  g_Ahi);
    cudaGetSymbolAddress((void**)&Alo,  g_Alo);
    cudaGetSymbolAddress((void**)&Bhi,  g_Bhi);
    cudaGetSymbolAddress((void**)&Blo,  g_Blo);

    cudaFuncSetAttribute(attn_kernel,
                         cudaFuncAttributeMaxDynamicSharedMemorySize, ATTN_SMEM);
    cudaFuncSetAttribute(gemm_mma,
                         cudaFuncAttributeMaxDynamicSharedMemorySize, GEMM_SMEM);

    dim3 blk(256);
    const int nD  = MROWS * DMODEL;        // 8M
    const int nFF = MROWS * DFF;           // 32M
    dim3 gProj(DMODEL / BN, MROWS / BM);   // (8, 64)
    dim3 gFF1(DFF / BN, MROWS / BM);       // (32, 64)

    // Encoder calls multihead(v, q, k): Q-in=v, K-in=q, V-in=k
    conv_split<<<nD / 4 / 256, blk>>>(v, Ahi, Alo, nD / 4);
    conv_wt_T<<<dim3(DMODEL / 32, DMODEL / 32), blk>>>(Wq, Bhi, Blo, DMODEL, DMODEL);
    gemm_mma<<<gProj, blk, GEMM_SMEM>>>(Ahi, Alo, Bhi, Blo, bq, Qp, MROWS, DMODEL, DMODEL, 2);

    conv_split<<<nD / 4 / 256, blk>>>(q, Ahi, Alo, nD / 4);
    conv_wt_T<<<dim3(DMODEL / 32, DMODEL / 32), blk>>>(Wk, Bhi, Blo, DMODEL, DMODEL);
    gemm_mma<<<gProj, blk, GEMM_SMEM>>>(Ahi, Alo, Bhi, Blo, bk, Kp, MROWS, DMODEL, DMODEL, 2);

    conv_split<<<nD / 4 / 256, blk>>>(k, Ahi, Alo, nD / 4);
    conv_wt_T<<<dim3(DMODEL / 32, DMODEL / 32), blk>>>(Wv, Bhi, Blo, DMODEL, DMODEL);
    gemm_mma<<<gProj, blk, GEMM_SMEM>>>(Ahi, Alo, Bhi, Blo, bv, Vp, MROWS, DMODEL, DMODEL, 2);

    attn_kernel<<<dim3(SEQ / 64, BATCH * NHEAD), blk, ATTN_SMEM>>>(Qp, Kp, Vp, mh);

    ln_res_kernel<<<MROWS, blk>>>(mh, q, res1);

    conv_split<<<nD / 4 / 256, blk>>>(res1, Ahi, Alo, nD / 4);
    conv_wt_T<<<dim3(DFF / 32, DMODEL / 32), blk>>>(W1, Bhi, Blo, DMODEL, DFF);
    gemm_mma<<<gFF1, blk, GEMM_SMEM>>>(Ahi, Alo, Bhi, Blo, b1, ff1, MROWS, DFF, DMODEL, 1);

    conv_split<<<nFF / 4 / 256, blk>>>(ff1, Ahi, Alo, nFF / 4);
    conv_wt_T<<<dim3(DMODEL / 32, DFF / 32), blk>>>(W2, Bhi, Blo, DFF, DMODEL);
    gemm_mma<<<gProj, blk, GEMM_SMEM>>>(Ahi, Alo, Bhi, Blo, b2, Qp, MROWS, DMODEL, DFF, 0);

    ln_res_kernel<<<MROWS, blk>>>(Qp, res1, (float*)d_out);
}

// round 4
// speedup vs baseline: 3.7498x; 2.0785x over previous
#include <cuda_runtime.h>
#include <cuda_bf16.h>
#include <cuda_fp16.h>
#include <cstdint>

// Problem constants
#define BATCH 4
#define SEQ   2048
#define DMODEL 1024
#define NHEAD 8
#define HD    128
#define MROWS (BATCH*SEQ)        // 8192
#define DFF   4096
#define QKSCALE 0.08838834764831845f   // 1/sqrt(128)

// ---------------- scratch (no allocations allowed) ----------------
__device__ float g_tmp[(size_t)MROWS * DMODEL];
__device__ float g_mh[(size_t)MROWS * DMODEL];
__device__ float g_res1[(size_t)MROWS * DMODEL];
__device__ __nv_bfloat16 g_Ahi[(size_t)MROWS * DMODEL];
__device__ __nv_bfloat16 g_Alo[(size_t)MROWS * DMODEL];
__device__ __nv_bfloat16 g_Bhi[(size_t)DFF * DMODEL];
__device__ __nv_bfloat16 g_Blo[(size_t)DFF * DMODEL];
__device__ __nv_bfloat16 g_Fh[(size_t)MROWS * DFF];
__device__ __nv_bfloat16 g_Fl[(size_t)MROWS * DFF];
__device__ __half g_Qh[(size_t)MROWS * DMODEL];
__device__ __half g_Kh[(size_t)MROWS * DMODEL];
__device__ __half g_Vh[(size_t)MROWS * DMODEL];

// ======================= PTX helpers =======================
__device__ __forceinline__ uint32_t smem_u32(const void* p) {
    uint32_t a;
    asm("{ .reg .u64 t; cvta.to.shared.u64 t, %1; cvt.u32.u64 %0, t; }" : "=r"(a) : "l"(p));
    return a;
}
__device__ __forceinline__ void cp_async16(uint32_t saddr, const void* gaddr) {
    asm volatile("cp.async.cg.shared.global [%0], [%1], 16;" :: "r"(saddr), "l"(gaddr) : "memory");
}
#define CP_COMMIT() asm volatile("cp.async.commit_group;" ::: "memory")

__device__ __forceinline__ void ldmx4(uint32_t* r, uint32_t addr) {
    asm volatile("ldmatrix.sync.aligned.m8n8.x4.shared.b16 {%0,%1,%2,%3}, [%4];"
                 : "=r"(r[0]), "=r"(r[1]), "=r"(r[2]), "=r"(r[3]) : "r"(addr));
}
__device__ __forceinline__ void ldmx4t(uint32_t* r, uint32_t addr) {
    asm volatile("ldmatrix.sync.aligned.m8n8.x4.trans.shared.b16 {%0,%1,%2,%3}, [%4];"
                 : "=r"(r[0]), "=r"(r[1]), "=r"(r[2]), "=r"(r[3]) : "r"(addr));
}
__device__ __forceinline__ void mma_bf16(float* c, const uint32_t* a,
                                         uint32_t b0, uint32_t b1) {
    asm volatile(
        "mma.sync.aligned.m16n8k16.row.col.f32.bf16.bf16.f32 "
        "{%0,%1,%2,%3}, {%4,%5,%6,%7}, {%8,%9}, {%0,%1,%2,%3};"
        : "+f"(c[0]), "+f"(c[1]), "+f"(c[2]), "+f"(c[3])
        : "r"(a[0]), "r"(a[1]), "r"(a[2]), "r"(a[3]), "r"(b0), "r"(b1));
}
__device__ __forceinline__ void mma_f16(float* c, const uint32_t* a,
                                        uint32_t b0, uint32_t b1) {
    asm volatile(
        "mma.sync.aligned.m16n8k16.row.col.f32.f16.f16.f32 "
        "{%0,%1,%2,%3}, {%4,%5,%6,%7}, {%8,%9}, {%0,%1,%2,%3};"
        : "+f"(c[0]), "+f"(c[1]), "+f"(c[2]), "+f"(c[3])
        : "r"(a[0]), "r"(a[1]), "r"(a[2]), "r"(a[3]), "r"(b0), "r"(b1));
}
__device__ __forceinline__ uint32_t packh2(float a, float b) {
    __half2 h = __floats2half2_rn(a, b);
    return *(uint32_t*)&h;
}

// =====================================================================
// split conversion: x -> (hi, lo) bf16  (for the 3 raw inputs)
// =====================================================================
__global__ __launch_bounds__(256) void conv_split(
    const float* __restrict__ x, __nv_bfloat16* __restrict__ hi,
    __nv_bfloat16* __restrict__ lo, int n4)
{
    int i = blockIdx.x * 256 + threadIdx.x;
    if (i >= n4) return;
    float4 v = ((const float4*)x)[i];
    __nv_bfloat16 h0 = __float2bfloat16(v.x), h1 = __float2bfloat16(v.y);
    __nv_bfloat16 h2 = __float2bfloat16(v.z), h3 = __float2bfloat16(v.w);
    __nv_bfloat16 l0 = __float2bfloat16(v.x - __bfloat162float(h0));
    __nv_bfloat16 l1 = __float2bfloat16(v.y - __bfloat162float(h1));
    __nv_bfloat16 l2 = __float2bfloat16(v.z - __bfloat162float(h2));
    __nv_bfloat16 l3 = __float2bfloat16(v.w - __bfloat162float(h3));
    __nv_bfloat162* hp = (__nv_bfloat162*)(hi + (size_t)i * 4);
    __nv_bfloat162* lp = (__nv_bfloat162*)(lo + (size_t)i * 4);
    hp[0] = __nv_bfloat162(h0, h1); hp[1] = __nv_bfloat162(h2, h3);
    lp[0] = __nv_bfloat162(l0, l1); lp[1] = __nv_bfloat162(l2, l3);
}

// =====================================================================
// weight transpose + split: W[K,N] -> Bt[N,K] hi/lo
// =====================================================================
__global__ __launch_bounds__(256) void conv_wt_T(
    const float* __restrict__ W, __nv_bfloat16* __restrict__ hi,
    __nv_bfloat16* __restrict__ lo, int K, int N)
{
    __shared__ float t[32][33];
    int k0 = blockIdx.y * 32, n0 = blockIdx.x * 32;
    int tx = threadIdx.x & 31, ty = threadIdx.x >> 5;   // 32 x 8
    #pragma unroll
    for (int i = ty; i < 32; i += 8)
        t[i][tx] = W[(size_t)(k0 + i) * N + n0 + tx];
    __syncthreads();
    #pragma unroll
    for (int i = ty; i < 32; i += 8) {
        float v = t[tx][i];
        __nv_bfloat16 h = __float2bfloat16(v);
        __nv_bfloat16 l = __float2bfloat16(v - __bfloat162float(h));
        size_t idx = (size_t)(n0 + i) * K + k0 + tx;
        hi[idx] = h; lo[idx] = l;
    }
}

// =====================================================================
// mma.sync split-bf16 GEMM: C = A[M,K] @ Bt[N,K]^T + bias
// mode 0: f32 out   mode 1: ReLU + split-bf16 out (C1 hi, C2 lo)
// mode 2: fp16 out, head-permuted to [B,H,S,hd], scaled
// =====================================================================
#define BM 128
#define BN 128
#define BK 32
#define ROWB 80
#define OPB  (128 * ROWB)
#define STAGE_B (4 * OPB)
#define NSTAGE 3
#define GEMM_SMEM (NSTAGE * STAGE_B)

__device__ __forceinline__ void prefetch_chunk(
    uint32_t sbase, int stage, int c,
    const __nv_bfloat16* Ahi, const __nv_bfloat16* Alo,
    const __nv_bfloat16* Bhi, const __nv_bfloat16* Blo,
    int m0, int n0, int K, int tid)
{
    const int k0 = c * BK;
    const uint32_t sb = sbase + stage * STAGE_B;
    #pragma unroll
    for (int t = 0; t < 2; t++) {
        int seg = tid + 256 * t;
        int row = seg >> 2;
        int sc  = seg & 3;
        uint32_t soff = row * ROWB + sc * 16;
        size_t ga = (size_t)(m0 + row) * K + k0 + sc * 8;
        size_t gb = (size_t)(n0 + row) * K + k0 + sc * 8;
        cp_async16(sb + soff,           Ahi + ga);
        cp_async16(sb + OPB + soff,     Alo + ga);
        cp_async16(sb + 2 * OPB + soff, Bhi + gb);
        cp_async16(sb + 3 * OPB + soff, Blo + gb);
    }
}

__global__ __launch_bounds__(256, 1) void gemm_mma(
    const __nv_bfloat16* __restrict__ Ahi, const __nv_bfloat16* __restrict__ Alo,
    const __nv_bfloat16* __restrict__ Bhi, const __nv_bfloat16* __restrict__ Blo,
    const float* __restrict__ bias, float* __restrict__ Cf,
    void* __restrict__ C1, void* __restrict__ C2,
    int M, int N, int K, int mode, float scale)
{
    extern __shared__ char smem[];
    const uint32_t sbase = smem_u32(smem);
    const int tid = threadIdx.x;
    const int wid = tid >> 5, lane = tid & 31;
    const int wm = wid >> 1;
    const int wn = wid & 1;
    const int m0 = blockIdx.y * BM, n0 = blockIdx.x * BN;
    const int NC = K / BK;

    float acc[2][8][4];
    #pragma unroll
    for (int i = 0; i < 2; i++)
        #pragma unroll
        for (int j = 0; j < 8; j++)
            #pragma unroll
            for (int x = 0; x < 4; x++) acc[i][j][x] = 0.f;

    prefetch_chunk(sbase, 0, 0, Ahi, Alo, Bhi, Blo, m0, n0, K, tid); CP_COMMIT();
    prefetch_chunk(sbase, 1, 1, Ahi, Alo, Bhi, Blo, m0, n0, K, tid); CP_COMMIT();

    const uint32_t lrow = (lane & 15);
    const uint32_t lcol = (lane >> 4) * 16;

    for (int c = 0; c < NC; c++) {
        const int sc = c % NSTAGE;
        if (c + 2 < NC) { asm volatile("cp.async.wait_group 1;" ::: "memory"); }
        else            { asm volatile("cp.async.wait_group 0;" ::: "memory"); }
        __syncthreads();

        const uint32_t stg = sbase + sc * STAGE_B;
        const uint32_t aBase = stg + (wm * 32) * ROWB + lrow * ROWB + lcol;
        const uint32_t bBase = stg + 2 * OPB + (wn * 64) * ROWB + lrow * ROWB + lcol;

        #pragma unroll
        for (int kk = 0; kk < 2; kk++) {
            const uint32_t kb = kk * 32;
            uint32_t ah[2][4], al[2][4];
            #pragma unroll
            for (int mt = 0; mt < 2; mt++) {
                ldmx4(ah[mt], aBase + mt * 16 * ROWB + kb);
                ldmx4(al[mt], aBase + OPB + mt * 16 * ROWB + kb);
            }
            uint32_t bh[4][4], bl[4][4];
            #pragma unroll
            for (int p = 0; p < 4; p++) {
                ldmx4(bh[p], bBase + p * 16 * ROWB + kb);
                ldmx4(bl[p], bBase + OPB + p * 16 * ROWB + kb);
            }
            #pragma unroll
            for (int mt = 0; mt < 2; mt++) {
                #pragma unroll
                for (int p = 0; p < 4; p++) {
                    mma_bf16(acc[mt][2*p],   ah[mt], bh[p][0], bh[p][2]);
                    mma_bf16(acc[mt][2*p+1], ah[mt], bh[p][1], bh[p][3]);
                    mma_bf16(acc[mt][2*p],   ah[mt], bl[p][0], bl[p][2]);
                    mma_bf16(acc[mt][2*p+1], ah[mt], bl[p][1], bl[p][3]);
                    mma_bf16(acc[mt][2*p],   al[mt], bh[p][0], bh[p][2]);
                    mma_bf16(acc[mt][2*p+1], al[mt], bh[p][1], bh[p][3]);
                }
            }
        }
        __syncthreads();
        if (c + 2 < NC) {
            prefetch_chunk(sbase, (c + 2) % NSTAGE, c + 2, Ahi, Alo, Bhi, Blo, m0, n0, K, tid);
            CP_COMMIT();
        }
    }

    // ---- epilogue ----
    const int rbase = m0 + wm * 32 + (lane >> 2);
    const int cbase = n0 + wn * 64 + (lane & 3) * 2;
    #pragma unroll
    for (int mt = 0; mt < 2; mt++) {
        #pragma unroll
        for (int nt = 0; nt < 8; nt++) {
            const int col = cbase + nt * 8;
            const float bz0 = bias[col], bz1 = bias[col + 1];
            #pragma unroll
            for (int h = 0; h < 2; h++) {
                const int row = rbase + mt * 16 + h * 8;
                float v0 = acc[mt][nt][2*h]   + bz0;
                float v1 = acc[mt][nt][2*h+1] + bz1;
                if (mode == 0) {
                    float* dst = Cf + (size_t)row * N + col;
                    dst[0] = v0; dst[1] = v1;
                } else if (mode == 1) {
                    v0 = fmaxf(v0, 0.f); v1 = fmaxf(v1, 0.f);
                    __nv_bfloat162 hh = __floats2bfloat162_rn(v0, v1);
                    float2 hf = __bfloat1622float2(hh);
                    __nv_bfloat162 ll = __floats2bfloat162_rn(v0 - hf.x, v1 - hf.y);
                    *(__nv_bfloat162*)((__nv_bfloat16*)C1 + (size_t)row * N + col) = hh;
                    *(__nv_bfloat162*)((__nv_bfloat16*)C2 + (size_t)row * N + col) = ll;
                } else {
                    v0 *= scale; v1 *= scale;
                    const int b = row >> 11, s = row & (SEQ - 1);
                    const int hh = col >> 7, d = col & (HD - 1);
                    __half2* dst = (__half2*)((__half*)C1 +
                        (((size_t)b * NHEAD + hh) * SEQ + s) * HD + d);
                    *dst = __floats2half2_rn(v0, v1);
                }
            }
        }
    }
}

// =====================================================================
// fp16 flash attention. Per block: one (b,h), 128 queries.
// K/V 64-key tiles double-buffered. Q kept as register fragments.
// 8 warps: warp w owns query rows w*16..w*16+15.
// =====================================================================
#define ASTRIDE 272
#define SQH 0
#define SKBASE 34816                 // 128*272
#define KTILE_B (64 * ASTRIDE)       // 17408
#define STAGE_SZ (2 * KTILE_B)       // Kh + Vh
#define ATT_SMEM (SKBASE + 2 * STAGE_SZ)   // 104448

__device__ __forceinline__ void attn_prefetch(
    uint32_t sb, int stage, int kt,
    const __half* Kgb, const __half* Vgb, int tid)
{
    #pragma unroll
    for (int t = 0; t < 8; t++) {
        int idx = tid + t * 256;          // 0..2047
        int tensor = idx >> 10;           // 0: K, 1: V
        int row = (idx >> 4) & 63;
        int c   = idx & 15;
        uint32_t dst = sb + SKBASE + stage * STAGE_SZ + tensor * KTILE_B
                     + row * ASTRIDE + c * 16;
        const __half* src = (tensor ? Vgb : Kgb) + (size_t)(kt * 64 + row) * HD + c * 8;
        cp_async16(dst, src);
    }
}

__global__ __launch_bounds__(256, 1) void attn_mma(
    const __half* __restrict__ Qg, const __half* __restrict__ Kg,
    const __half* __restrict__ Vg, float* __restrict__ mh)
{
    extern __shared__ char smem[];
    const uint32_t sb = smem_u32(smem);
    const int tid = threadIdx.x;
    const int wid = tid >> 5, lane = tid & 31;
    const int qb = blockIdx.x;      // 16 q-tiles
    const int bh = blockIdx.y;      // 32
    const int b = bh >> 3, h = bh & 7;

    // load Q tile (128 rows x 256B)
    const __half* Qgb = Qg + ((size_t)bh * SEQ + qb * 128) * HD;
    #pragma unroll
    for (int t = 0; t < 8; t++) {
        int idx = tid + t * 256;
        int row = idx >> 4, c = idx & 15;
        cp_async16(sb + SQH + row * ASTRIDE + c * 16, Qgb + (size_t)row * HD + c * 8);
    }
    const __half* Kgb = Kg + (size_t)bh * SEQ * HD;
    const __half* Vgb = Vg + (size_t)bh * SEQ * HD;
    attn_prefetch(sb, 0, 0, Kgb, Vgb, tid);
    CP_COMMIT();
    attn_prefetch(sb, 1, 1, Kgb, Vgb, tid);
    CP_COMMIT();

    asm volatile("cp.async.wait_group 1;" ::: "memory");
    __syncthreads();

    // Q register fragments (m16 x k128)
    uint32_t qf[8][4];
    {
        const uint32_t qbase = sb + SQH + (wid * 16 + (lane & 15)) * ASTRIDE + (lane >> 4) * 16;
        #pragma unroll
        for (int ks = 0; ks < 8; ks++) ldmx4(qf[ks], qbase + ks * 32);
    }

    float oacc[16][4];
    #pragma unroll
    for (int i = 0; i < 16; i++)
        #pragma unroll
        for (int j = 0; j < 4; j++) oacc[i][j] = 0.f;
    float m0 = -1e30f, m1 = -1e30f, l0 = 0.f, l1 = 0.f;

    for (int kt = 0; kt < 32; kt++) {
        const int cur = kt & 1;
        if (kt > 0) {
            if (kt + 1 < 32) {
                attn_prefetch(sb, (kt + 1) & 1, kt + 1, Kgb, Vgb, tid);
                CP_COMMIT();
                asm volatile("cp.async.wait_group 1;" ::: "memory");
            } else {
                asm volatile("cp.async.wait_group 0;" ::: "memory");
            }
            __syncthreads();
        }

        const uint32_t kbase = sb + SKBASE + cur * STAGE_SZ;
        const uint32_t vbase = kbase + KTILE_B;

        // ---- S = Q K^T ----
        float sacc[8][4];
        #pragma unroll
        for (int i = 0; i < 8; i++)
            #pragma unroll
            for (int j = 0; j < 4; j++) sacc[i][j] = 0.f;

        #pragma unroll
        for (int ks = 0; ks < 8; ks++) {
            const uint32_t colb = ks * 32 + (lane >> 4) * 16;
            #pragma unroll
            for (int p = 0; p < 4; p++) {
                uint32_t kf[4];
                ldmx4(kf, kbase + (p * 16 + (lane & 15)) * ASTRIDE + colb);
                mma_f16(sacc[2*p],   qf[ks], kf[0], kf[2]);
                mma_f16(sacc[2*p+1], qf[ks], kf[1], kf[3]);
            }
        }

        // ---- online softmax (rows r0 = lane>>2, r0+8) ----
        float mx0 = -1e30f, mx1 = -1e30f;
        #pragma unroll
        for (int n = 0; n < 8; n++) {
            mx0 = fmaxf(mx0, fmaxf(sacc[n][0], sacc[n][1]));
            mx1 = fmaxf(mx1, fmaxf(sacc[n][2], sacc[n][3]));
        }
        mx0 = fmaxf(mx0, __shfl_xor_sync(0xffffffffu, mx0, 1));
        mx0 = fmaxf(mx0, __shfl_xor_sync(0xffffffffu, mx0, 2));
        mx1 = fmaxf(mx1, __shfl_xor_sync(0xffffffffu, mx1, 1));
        mx1 = fmaxf(mx1, __shfl_xor_sync(0xffffffffu, mx1, 2));
        const float mn0 = fmaxf(m0, mx0), mn1 = fmaxf(m1, mx1);
        const float a0 = __expf(m0 - mn0), a1 = __expf(m1 - mn1);
        m0 = mn0; m1 = mn1;
        float sum0 = 0.f, sum1 = 0.f;
        #pragma unroll
        for (int n = 0; n < 8; n++) {
            sacc[n][0] = __expf(sacc[n][0] - mn0);
            sacc[n][1] = __expf(sacc[n][1] - mn0);
            sacc[n][2] = __expf(sacc[n][2] - mn1);
            sacc[n][3] = __expf(sacc[n][3] - mn1);
            sum0 += sacc[n][0] + sacc[n][1];
            sum1 += sacc[n][2] + sacc[n][3];
        }
        sum0 += __shfl_xor_sync(0xffffffffu, sum0, 1);
        sum0 += __shfl_xor_sync(0xffffffffu, sum0, 2);
        sum1 += __shfl_xor_sync(0xffffffffu, sum1, 1);
        sum1 += __shfl_xor_sync(0xffffffffu, sum1, 2);
        l0 = l0 * a0 + sum0; l1 = l1 * a1 + sum1;
        #pragma unroll
        for (int i = 0; i < 16; i++) {
            oacc[i][0] *= a0; oacc[i][1] *= a0;
            oacc[i][2] *= a1; oacc[i][3] *= a1;
        }

        // ---- pack P to fp16 A-fragments ----
        uint32_t ph[4][4];
        #pragma unroll
        for (int t = 0; t < 4; t++) {
            ph[t][0] = packh2(sacc[2*t][0],   sacc[2*t][1]);
            ph[t][1] = packh2(sacc[2*t][2],   sacc[2*t][3]);
            ph[t][2] = packh2(sacc[2*t+1][0], sacc[2*t+1][1]);
            ph[t][3] = packh2(sacc[2*t+1][2], sacc[2*t+1][3]);
        }

        // ---- O += P V ----
        #pragma unroll
        for (int t = 0; t < 4; t++) {
            const uint32_t vrow = vbase + (t * 16 + (lane & 15)) * ASTRIDE + (lane >> 4) * 16;
            #pragma unroll
            for (int g = 0; g < 8; g++) {
                uint32_t vf[4];
                ldmx4t(vf, vrow + g * 32);
                mma_f16(oacc[2*g],   ph[t], vf[0], vf[1]);
                mma_f16(oacc[2*g+1], ph[t], vf[2], vf[3]);
            }
        }
        __syncthreads();
    }

    // ---- write O / l to mh[B,S,D] ----
    const float inv0 = 1.f / l0, inv1 = 1.f / l1;
    const int row0 = qb * 128 + wid * 16 + (lane >> 2);
    float* base0 = mh + ((size_t)b * SEQ + row0) * DMODEL + h * HD + (lane & 3) * 2;
    float* base1 = base0 + 8 * DMODEL;
    #pragma unroll
    for (int nt = 0; nt < 16; nt++) {
        *(float2*)(base0 + nt * 8) = make_float2(oacc[nt][0] * inv0, oacc[nt][1] * inv0);
        *(float2*)(base1 + nt * 8) = make_float2(oacc[nt][2] * inv1, oacc[nt][3] * inv1);
    }
}

// =====================================================================
// LayerNorm (ddof=1, no eps) + residual; split variant also emits bf16 hi/lo
// =====================================================================
template<int SPLIT>
__global__ __launch_bounds__(256) void ln_res_k(
    const float* __restrict__ x, const float* __restrict__ res,
    float* __restrict__ out, __nv_bfloat16* __restrict__ hi,
    __nv_bfloat16* __restrict__ lo)
{
    const int D = DMODEL;
    const size_t row = blockIdx.x;
    const float* xr = x + row * D;

    float s = 0.f, ss = 0.f;
    for (int i = threadIdx.x; i < D; i += 256) {
        float v = xr[i];
        s += v; ss = fmaf(v, v, ss);
    }
    #pragma unroll
    for (int off = 16; off > 0; off >>= 1) {
        s  += __shfl_xor_sync(0xffffffffu, s, off);
        ss += __shfl_xor_sync(0xffffffffu, ss, off);
    }
    __shared__ float sa[8], sbuf[8];
    int w = threadIdx.x >> 5, l = threadIdx.x & 31;
    if (l == 0) { sa[w] = s; sbuf[w] = ss; }
    __syncthreads();
    if (threadIdx.x < 32) {
        s  = (l < 8) ? sa[l] : 0.f;
        ss = (l < 8) ? sbuf[l] : 0.f;
        #pragma unroll
        for (int off = 4; off > 0; off >>= 1) {
            s  += __shfl_xor_sync(0xffffffffu, s, off);
            ss += __shfl_xor_sync(0xffffffffu, ss, off);
        }
        if (l == 0) { sa[0] = s; sbuf[0] = ss; }
    }
    __syncthreads();
    s = sa[0]; ss = sbuf[0];

    float mean = s / (float)D;
    float var  = (ss - s * s / (float)D) / (float)(D - 1);
    float rstd = rsqrtf(var);

    const float* rr = res + row * D;
    float* orow = out + row * D;
    for (int i = threadIdx.x; i < D; i += 256) {
        float o = rr[i] + (xr[i] - mean) * rstd;
        orow[i] = o;
        if (SPLIT) {
            __nv_bfloat16 hh = __float2bfloat16(o);
            hi[row * D + i] = hh;
            lo[row * D + i] = __float2bfloat16(o - __bfloat162float(hh));
        }
    }
}

// =====================================================================
extern "C" void kernel_launch(void* const* d_in, const int* in_sizes, int n_in,
                              void* d_out, int out_size)
{
    const float* q  = (const float*)d_in[0];
    const float* k  = (const float*)d_in[1];
    const float* v  = (const float*)d_in[2];
    const float* Wq = (const float*)d_in[3];
    const float* bq = (const float*)d_in[4];
    const float* Wk = (const float*)d_in[5];
    const float* bk = (const float*)d_in[6];
    const float* Wv = (const float*)d_in[7];
    const float* bv = (const float*)d_in[8];
    const float* W1 = (const float*)d_in[9];
    const float* b1 = (const float*)d_in[10];
    const float* W2 = (const float*)d_in[11];
    const float* b2 = (const float*)d_in[12];

    float *tmp, *mh, *res1;
    __nv_bfloat16 *Ahi, *Alo, *Bhi, *Blo, *Fh, *Fl;
    __half *Qh, *Kh, *Vh;
    cudaGetSymbolAddress((void**)&tmp,  g_tmp);
    cudaGetSymbolAddress((void**)&mh,   g_mh);
    cudaGetSymbolAddress((void**)&res1, g_res1);
    cudaGetSymbolAddress((void**)&Ahi,  g_Ahi);
    cudaGetSymbolAddress((void**)&Alo,  g_Alo);
    cudaGetSymbolAddress((void**)&Bhi,  g_Bhi);
    cudaGetSymbolAddress((void**)&Blo,  g_Blo);
    cudaGetSymbolAddress((void**)&Fh,   g_Fh);
    cudaGetSymbolAddress((void**)&Fl,   g_Fl);
    cudaGetSymbolAddress((void**)&Qh,   g_Qh);
    cudaGetSymbolAddress((void**)&Kh,   g_Kh);
    cudaGetSymbolAddress((void**)&Vh,   g_Vh);

    cudaFuncSetAttribute(gemm_mma,
                         cudaFuncAttributeMaxDynamicSharedMemorySize, GEMM_SMEM);
    cudaFuncSetAttribute(attn_mma,
                         cudaFuncAttributeMaxDynamicSharedMemorySize, ATT_SMEM);

    dim3 blk(256);
    const int nD = MROWS * DMODEL;
    dim3 gProj(DMODEL / BN, MROWS / BM);
    dim3 gFF1(DFF / BN, MROWS / BM);

    // Encoder calls multihead(v, q, k): Q-in=v, K-in=q, V-in=k
    conv_split<<<nD / 4 / 256, blk>>>(v, Ahi, Alo, nD / 4);
    conv_wt_T<<<dim3(DMODEL / 32, DMODEL / 32), blk>>>(Wq, Bhi, Blo, DMODEL, DMODEL);
    gemm_mma<<<gProj, blk, GEMM_SMEM>>>(Ahi, Alo, Bhi, Blo, bq, nullptr, Qh, nullptr,
                                        MROWS, DMODEL, DMODEL, 2, QKSCALE);

    conv_split<<<nD / 4 / 256, blk>>>(q, Ahi, Alo, nD / 4);
    conv_wt_T<<<dim3(DMODEL / 32, DMODEL / 32), blk>>>(Wk, Bhi, Blo, DMODEL, DMODEL);
    gemm_mma<<<gProj, blk, GEMM_SMEM>>>(Ahi, Alo, Bhi, Blo, bk, nullptr, Kh, nullptr,
                                        MROWS, DMODEL, DMODEL, 2, 1.0f);

    conv_split<<<nD / 4 / 256, blk>>>(k, Ahi, Alo, nD / 4);
    conv_wt_T<<<dim3(DMODEL / 32, DMODEL / 32), blk>>>(Wv, Bhi, Blo, DMODEL, DMODEL);
    gemm_mma<<<gProj, blk, GEMM_SMEM>>>(Ahi, Alo, Bhi, Blo, bv, nullptr, Vh, nullptr,
                                        MROWS, DMODEL, DMODEL, 2, 1.0f);

    attn_mma<<<dim3(SEQ / 128, BATCH * NHEAD), blk, ATT_SMEM>>>(Qh, Kh, Vh, mh);

    // res1 = q + LN(mh), also emit split-bf16 for FF1
    ln_res_k<1><<<MROWS, blk>>>(mh, q, res1, Ahi, Alo);

    conv_wt_T<<<dim3(DFF / 32, DMODEL / 32), blk>>>(W1, Bhi, Blo, DMODEL, DFF);
    gemm_mma<<<gFF1, blk, GEMM_SMEM>>>(Ahi, Alo, Bhi, Blo, b1, nullptr, Fh, Fl,
                                       MROWS, DFF, DMODEL, 1, 1.0f);

    conv_wt_T<<<dim3(DMODEL / 32, DFF / 32), blk>>>(W2, Bhi, Blo, DFF, DMODEL);
    gemm_mma<<<gProj, blk, GEMM_SMEM>>>(Fh, Fl, Bhi, Blo, b2, tmp, nullptr, nullptr,
                                        MROWS, DMODEL, DFF, 0, 1.0f);

    ln_res_k<0><<<MROWS, blk>>>(tmp, res1, (float*)d_out, nullptr, nullptr);
}

// round 5
// speedup vs baseline: 6.2461x; 1.6657x over previous
#include <cuda_runtime.h>
#include <cuda_bf16.h>
#include <cuda_fp16.h>
#include <cstdint>

// Problem constants
#define BATCH 4
#define SEQ   2048
#define DMODEL 1024
#define NHEAD 8
#define HD    128
#define MROWS (BATCH*SEQ)        // 8192
#define DFF   4096
#define QKSCALE 0.08838834764831845f   // 1/sqrt(128)

// ---------------- scratch (no allocations allowed) ----------------
__device__ float g_tmp[(size_t)MROWS * DMODEL];
__device__ float g_mh[(size_t)MROWS * DMODEL];
__device__ float g_res1[(size_t)MROWS * DMODEL];
__device__ __nv_bfloat16 g_Ahi[(size_t)MROWS * DMODEL];
__device__ __nv_bfloat16 g_Alo[(size_t)MROWS * DMODEL];
__device__ __nv_bfloat16 g_Bhi[(size_t)DMODEL * DMODEL];
__device__ __nv_bfloat16 g_Blo[(size_t)DMODEL * DMODEL];
__device__ __half g_A16[(size_t)MROWS * DMODEL];     // LN1 out fp16
__device__ __half g_W16[(size_t)DFF * DMODEL];       // FF weight fp16 (transposed)
__device__ __half g_F16[(size_t)MROWS * DFF];        // FF1 out fp16
__device__ __half g_Qh[(size_t)MROWS * DMODEL];
__device__ __half g_Kh[(size_t)MROWS * DMODEL];
__device__ __half g_Vh[(size_t)MROWS * DMODEL];

// ======================= PTX helpers =======================
__device__ __forceinline__ uint32_t smem_u32(const void* p) {
    uint32_t a;
    asm("{ .reg .u64 t; cvta.to.shared.u64 t, %1; cvt.u32.u64 %0, t; }" : "=r"(a) : "l"(p));
    return a;
}
__device__ __forceinline__ void cp_async16(uint32_t saddr, const void* gaddr) {
    asm volatile("cp.async.cg.shared.global [%0], [%1], 16;" :: "r"(saddr), "l"(gaddr) : "memory");
}
#define CP_COMMIT() asm volatile("cp.async.commit_group;" ::: "memory")

__device__ __forceinline__ void ldmx4(uint32_t* r, uint32_t addr) {
    asm volatile("ldmatrix.sync.aligned.m8n8.x4.shared.b16 {%0,%1,%2,%3}, [%4];"
                 : "=r"(r[0]), "=r"(r[1]), "=r"(r[2]), "=r"(r[3]) : "r"(addr));
}
__device__ __forceinline__ void ldmx4t(uint32_t* r, uint32_t addr) {
    asm volatile("ldmatrix.sync.aligned.m8n8.x4.trans.shared.b16 {%0,%1,%2,%3}, [%4];"
                 : "=r"(r[0]), "=r"(r[1]), "=r"(r[2]), "=r"(r[3]) : "r"(addr));
}
__device__ __forceinline__ void mma_bf16(float* c, const uint32_t* a,
                                         uint32_t b0, uint32_t b1) {
    asm volatile(
        "mma.sync.aligned.m16n8k16.row.col.f32.bf16.bf16.f32 "
        "{%0,%1,%2,%3}, {%4,%5,%6,%7}, {%8,%9}, {%0,%1,%2,%3};"
        : "+f"(c[0]), "+f"(c[1]), "+f"(c[2]), "+f"(c[3])
        : "r"(a[0]), "r"(a[1]), "r"(a[2]), "r"(a[3]), "r"(b0), "r"(b1));
}
__device__ __forceinline__ void mma_f16(float* c, const uint32_t* a,
                                        uint32_t b0, uint32_t b1) {
    asm volatile(
        "mma.sync.aligned.m16n8k16.row.col.f32.f16.f16.f32 "
        "{%0,%1,%2,%3}, {%4,%5,%6,%7}, {%8,%9}, {%0,%1,%2,%3};"
        : "+f"(c[0]), "+f"(c[1]), "+f"(c[2]), "+f"(c[3])
        : "r"(a[0]), "r"(a[1]), "r"(a[2]), "r"(a[3]), "r"(b0), "r"(b1));
}
__device__ __forceinline__ uint32_t packh2(float a, float b) {
    __half2 h = __floats2half2_rn(a, b);
    return *(uint32_t*)&h;
}

// =====================================================================
// split conversion: x -> (hi, lo) bf16  (for the 3 raw inputs)
// =====================================================================
__global__ __launch_bounds__(256) void conv_split(
    const float* __restrict__ x, __nv_bfloat16* __restrict__ hi,
    __nv_bfloat16* __restrict__ lo, int n4)
{
    int i = blockIdx.x * 256 + threadIdx.x;
    if (i >= n4) return;
    float4 v = ((const float4*)x)[i];
    __nv_bfloat16 h0 = __float2bfloat16(v.x), h1 = __float2bfloat16(v.y);
    __nv_bfloat16 h2 = __float2bfloat16(v.z), h3 = __float2bfloat16(v.w);
    __nv_bfloat16 l0 = __float2bfloat16(v.x - __bfloat162float(h0));
    __nv_bfloat16 l1 = __float2bfloat16(v.y - __bfloat162float(h1));
    __nv_bfloat16 l2 = __float2bfloat16(v.z - __bfloat162float(h2));
    __nv_bfloat16 l3 = __float2bfloat16(v.w - __bfloat162float(h3));
    __nv_bfloat162* hp = (__nv_bfloat162*)(hi + (size_t)i * 4);
    __nv_bfloat162* lp = (__nv_bfloat162*)(lo + (size_t)i * 4);
    hp[0] = __nv_bfloat162(h0, h1); hp[1] = __nv_bfloat162(h2, h3);
    lp[0] = __nv_bfloat162(l0, l1); lp[1] = __nv_bfloat162(l2, l3);
}

// =====================================================================
// weight transpose + split: W[K,N] -> Bt[N,K] hi/lo (bf16)
// =====================================================================
__global__ __launch_bounds__(256) void conv_wt_T(
    const float* __restrict__ W, __nv_bfloat16* __restrict__ hi,
    __nv_bfloat16* __restrict__ lo, int K, int N)
{
    __shared__ float t[32][33];
    int k0 = blockIdx.y * 32, n0 = blockIdx.x * 32;
    int tx = threadIdx.x & 31, ty = threadIdx.x >> 5;
    #pragma unroll
    for (int i = ty; i < 32; i += 8)
        t[i][tx] = W[(size_t)(k0 + i) * N + n0 + tx];
    __syncthreads();
    #pragma unroll
    for (int i = ty; i < 32; i += 8) {
        float v = t[tx][i];
        __nv_bfloat16 h = __float2bfloat16(v);
        __nv_bfloat16 l = __float2bfloat16(v - __bfloat162float(h));
        size_t idx = (size_t)(n0 + i) * K + k0 + tx;
        hi[idx] = h; lo[idx] = l;
    }
}

// =====================================================================
// weight transpose fp16: W[K,N] -> Wt[N,K] half
// =====================================================================
__global__ __launch_bounds__(256) void conv_wt_T16(
    const float* __restrict__ W, __half* __restrict__ out, int K, int N)
{
    __shared__ float t[32][33];
    int k0 = blockIdx.y * 32, n0 = blockIdx.x * 32;
    int tx = threadIdx.x & 31, ty = threadIdx.x >> 5;
    #pragma unroll
    for (int i = ty; i < 32; i += 8)
        t[i][tx] = W[(size_t)(k0 + i) * N + n0 + tx];
    __syncthreads();
    #pragma unroll
    for (int i = ty; i < 32; i += 8)
        out[(size_t)(n0 + i) * K + k0 + tx] = __float2half(t[tx][i]);
}

// =====================================================================
// shared tiling constants
// =====================================================================
#define BM 128
#define BN 128
#define BK 32
#define ROWB 80
#define OPB  (128 * ROWB)
#define NSTAGE 3

// ============ split-bf16 GEMM (projections only) ============
#define STAGE_B (4 * OPB)
#define GEMM_SMEM (NSTAGE * STAGE_B)

__device__ __forceinline__ void prefetch_chunk(
    uint32_t sbase, int stage, int c,
    const __nv_bfloat16* Ahi, const __nv_bfloat16* Alo,
    const __nv_bfloat16* Bhi, const __nv_bfloat16* Blo,
    int m0, int n0, int K, int tid)
{
    const int k0 = c * BK;
    const uint32_t sb = sbase + stage * STAGE_B;
    #pragma unroll
    for (int t = 0; t < 2; t++) {
        int seg = tid + 256 * t;
        int row = seg >> 2;
        int sc  = seg & 3;
        uint32_t soff = row * ROWB + sc * 16;
        size_t ga = (size_t)(m0 + row) * K + k0 + sc * 8;
        size_t gb = (size_t)(n0 + row) * K + k0 + sc * 8;
        cp_async16(sb + soff,           Ahi + ga);
        cp_async16(sb + OPB + soff,     Alo + ga);
        cp_async16(sb + 2 * OPB + soff, Bhi + gb);
        cp_async16(sb + 3 * OPB + soff, Blo + gb);
    }
}

// out: fp16 head-permuted [B,H,S,hd], scaled (projection use only)
__global__ __launch_bounds__(256, 1) void gemm_mma(
    const __nv_bfloat16* __restrict__ Ahi, const __nv_bfloat16* __restrict__ Alo,
    const __nv_bfloat16* __restrict__ Bhi, const __nv_bfloat16* __restrict__ Blo,
    const float* __restrict__ bias, __half* __restrict__ Ch,
    int M, int N, int K, float scale)
{
    extern __shared__ char smem[];
    const uint32_t sbase = smem_u32(smem);
    const int tid = threadIdx.x;
    const int wid = tid >> 5, lane = tid & 31;
    const int wm = wid >> 1;
    const int wn = wid & 1;
    const int m0 = blockIdx.y * BM, n0 = blockIdx.x * BN;
    const int NC = K / BK;

    float acc[2][8][4];
    #pragma unroll
    for (int i = 0; i < 2; i++)
        #pragma unroll
        for (int j = 0; j < 8; j++)
            #pragma unroll
            for (int x = 0; x < 4; x++) acc[i][j][x] = 0.f;

    prefetch_chunk(sbase, 0, 0, Ahi, Alo, Bhi, Blo, m0, n0, K, tid); CP_COMMIT();
    prefetch_chunk(sbase, 1, 1, Ahi, Alo, Bhi, Blo, m0, n0, K, tid); CP_COMMIT();

    const uint32_t lrow = (lane & 15);
    const uint32_t lcol = (lane >> 4) * 16;

    for (int c = 0; c < NC; c++) {
        const int sc = c % NSTAGE;
        if (c + 2 < NC) { asm volatile("cp.async.wait_group 1;" ::: "memory"); }
        else            { asm volatile("cp.async.wait_group 0;" ::: "memory"); }
        __syncthreads();

        const uint32_t stg = sbase + sc * STAGE_B;
        const uint32_t aBase = stg + (wm * 32) * ROWB + lrow * ROWB + lcol;
        const uint32_t bBase = stg + 2 * OPB + (wn * 64) * ROWB + lrow * ROWB + lcol;

        #pragma unroll
        for (int kk = 0; kk < 2; kk++) {
            const uint32_t kb = kk * 32;
            uint32_t ah[2][4], al[2][4];
            #pragma unroll
            for (int mt = 0; mt < 2; mt++) {
                ldmx4(ah[mt], aBase + mt * 16 * ROWB + kb);
                ldmx4(al[mt], aBase + OPB + mt * 16 * ROWB + kb);
            }
            uint32_t bh[4][4], bl[4][4];
            #pragma unroll
            for (int p = 0; p < 4; p++) {
                ldmx4(bh[p], bBase + p * 16 * ROWB + kb);
                ldmx4(bl[p], bBase + OPB + p * 16 * ROWB + kb);
            }
            #pragma unroll
            for (int mt = 0; mt < 2; mt++) {
                #pragma unroll
                for (int p = 0; p < 4; p++) {
                    mma_bf16(acc[mt][2*p],   ah[mt], bh[p][0], bh[p][2]);
                    mma_bf16(acc[mt][2*p+1], ah[mt], bh[p][1], bh[p][3]);
                    mma_bf16(acc[mt][2*p],   ah[mt], bl[p][0], bl[p][2]);
                    mma_bf16(acc[mt][2*p+1], ah[mt], bl[p][1], bl[p][3]);
                    mma_bf16(acc[mt][2*p],   al[mt], bh[p][0], bh[p][2]);
                    mma_bf16(acc[mt][2*p+1], al[mt], bh[p][1], bh[p][3]);
                }
            }
        }
        __syncthreads();
        if (c + 2 < NC) {
            prefetch_chunk(sbase, (c + 2) % NSTAGE, c + 2, Ahi, Alo, Bhi, Blo, m0, n0, K, tid);
            CP_COMMIT();
        }
    }

    const int rbase = m0 + wm * 32 + (lane >> 2);
    const int cbase = n0 + wn * 64 + (lane & 3) * 2;
    #pragma unroll
    for (int mt = 0; mt < 2; mt++) {
        #pragma unroll
        for (int nt = 0; nt < 8; nt++) {
            const int col = cbase + nt * 8;
            const float bz0 = bias[col], bz1 = bias[col + 1];
            #pragma unroll
            for (int h = 0; h < 2; h++) {
                const int row = rbase + mt * 16 + h * 8;
                float v0 = (acc[mt][nt][2*h]   + bz0) * scale;
                float v1 = (acc[mt][nt][2*h+1] + bz1) * scale;
                const int b = row >> 11, s = row & (SEQ - 1);
                const int hh = col >> 7, d = col & (HD - 1);
                __half2* dst = (__half2*)(Ch +
                    (((size_t)b * NHEAD + hh) * SEQ + s) * HD + d);
                *dst = __floats2half2_rn(v0, v1);
            }
        }
    }
}

// ============ single-product fp16 GEMM (FF layers) ============
#define STAGE16 (2 * OPB)
#define GEMM16_SMEM (NSTAGE * STAGE16)

__device__ __forceinline__ void prefetch16(
    uint32_t sbase, int stage, int c,
    const __half* A, const __half* B, int m0, int n0, int K, int tid)
{
    const int k0 = c * BK;
    const uint32_t sb = sbase + stage * STAGE16;
    #pragma unroll
    for (int t = 0; t < 2; t++) {
        int seg = tid + 256 * t;
        int row = seg >> 2;
        int sc  = seg & 3;
        uint32_t soff = row * ROWB + sc * 16;
        cp_async16(sb + soff,       A + (size_t)(m0 + row) * K + k0 + sc * 8);
        cp_async16(sb + OPB + soff, B + (size_t)(n0 + row) * K + k0 + sc * 8);
    }
}

// mode 0: f32 out   mode 1: ReLU + fp16 out
__global__ __launch_bounds__(256, 1) void gemm_f16(
    const __half* __restrict__ A, const __half* __restrict__ B,
    const float* __restrict__ bias, float* __restrict__ Cf,
    __half* __restrict__ Ch, int M, int N, int K, int mode)
{
    extern __shared__ char smem[];
    const uint32_t sbase = smem_u32(smem);
    const int tid = threadIdx.x;
    const int wid = tid >> 5, lane = tid & 31;
    const int wm = wid >> 1;
    const int wn = wid & 1;
    const int m0 = blockIdx.y * BM, n0 = blockIdx.x * BN;
    const int NC = K / BK;

    float acc[2][8][4];
    #pragma unroll
    for (int i = 0; i < 2; i++)
        #pragma unroll
        for (int j = 0; j < 8; j++)
            #pragma unroll
            for (int x = 0; x < 4; x++) acc[i][j][x] = 0.f;

    prefetch16(sbase, 0, 0, A, B, m0, n0, K, tid); CP_COMMIT();
    prefetch16(sbase, 1, 1, A, B, m0, n0, K, tid); CP_COMMIT();

    const uint32_t lrow = (lane & 15);
    const uint32_t lcol = (lane >> 4) * 16;

    for (int c = 0; c < NC; c++) {
        const int sc = c % NSTAGE;
        if (c + 2 < NC) { asm volatile("cp.async.wait_group 1;" ::: "memory"); }
        else            { asm volatile("cp.async.wait_group 0;" ::: "memory"); }
        __syncthreads();

        const uint32_t stg = sbase + sc * STAGE16;
        const uint32_t aBase = stg + (wm * 32) * ROWB + lrow * ROWB + lcol;
        const uint32_t bBase = stg + OPB + (wn * 64) * ROWB + lrow * ROWB + lcol;

        #pragma unroll
        for (int kk = 0; kk < 2; kk++) {
            const uint32_t kb = kk * 32;
            uint32_t ah[2][4];
            #pragma unroll
            for (int mt = 0; mt < 2; mt++)
                ldmx4(ah[mt], aBase + mt * 16 * ROWB + kb);
            #pragma unroll
            for (int p = 0; p < 4; p++) {
                uint32_t bh[4];
                ldmx4(bh, bBase + p * 16 * ROWB + kb);
                #pragma unroll
                for (int mt = 0; mt < 2; mt++) {
                    mma_f16(acc[mt][2*p],   ah[mt], bh[0], bh[2]);
                    mma_f16(acc[mt][2*p+1], ah[mt], bh[1], bh[3]);
                }
            }
        }
        __syncthreads();
        if (c + 2 < NC) {
            prefetch16(sbase, (c + 2) % NSTAGE, c + 2, A, B, m0, n0, K, tid);
            CP_COMMIT();
        }
    }

    const int rbase = m0 + wm * 32 + (lane >> 2);
    const int cbase = n0 + wn * 64 + (lane & 3) * 2;
    #pragma unroll
    for (int mt = 0; mt < 2; mt++) {
        #pragma unroll
        for (int nt = 0; nt < 8; nt++) {
            const int col = cbase + nt * 8;
            const float bz0 = bias[col], bz1 = bias[col + 1];
            #pragma unroll
            for (int h = 0; h < 2; h++) {
                const int row = rbase + mt * 16 + h * 8;
                float v0 = acc[mt][nt][2*h]   + bz0;
                float v1 = acc[mt][nt][2*h+1] + bz1;
                if (mode == 0) {
                    float* dst = Cf + (size_t)row * N + col;
                    dst[0] = v0; dst[1] = v1;
                } else {
                    v0 = fmaxf(v0, 0.f); v1 = fmaxf(v1, 0.f);
                    *(__half2*)(Ch + (size_t)row * N + col) = __floats2half2_rn(v0, v1);
                }
            }
        }
    }
}

// =====================================================================
// fp16 flash attention (unchanged from R4)
// =====================================================================
#define ASTRIDE 272
#define SQH 0
#define SKBASE 34816
#define KTILE_B (64 * ASTRIDE)
#define STAGE_SZ (2 * KTILE_B)
#define ATT_SMEM (SKBASE + 2 * STAGE_SZ)

__device__ __forceinline__ void attn_prefetch(
    uint32_t sb, int stage, int kt,
    const __half* Kgb, const __half* Vgb, int tid)
{
    #pragma unroll
    for (int t = 0; t < 8; t++) {
        int idx = tid + t * 256;
        int tensor = idx >> 10;
        int row = (idx >> 4) & 63;
        int c   = idx & 15;
        uint32_t dst = sb + SKBASE + stage * STAGE_SZ + tensor * KTILE_B
                     + row * ASTRIDE + c * 16;
        const __half* src = (tensor ? Vgb : Kgb) + (size_t)(kt * 64 + row) * HD + c * 8;
        cp_async16(dst, src);
    }
}

__global__ __launch_bounds__(256, 1) void attn_mma(
    const __half* __restrict__ Qg, const __half* __restrict__ Kg,
    const __half* __restrict__ Vg, float* __restrict__ mh)
{
    extern __shared__ char smem[];
    const uint32_t sb = smem_u32(smem);
    const int tid = threadIdx.x;
    const int wid = tid >> 5, lane = tid & 31;
    const int qb = blockIdx.x;
    const int bh = blockIdx.y;
    const int b = bh >> 3, h = bh & 7;

    const __half* Qgb = Qg + ((size_t)bh * SEQ + qb * 128) * HD;
    #pragma unroll
    for (int t = 0; t < 8; t++) {
        int idx = tid + t * 256;
        int row = idx >> 4, c = idx & 15;
        cp_async16(sb + SQH + row * ASTRIDE + c * 16, Qgb + (size_t)row * HD + c * 8);
    }
    const __half* Kgb = Kg + (size_t)bh * SEQ * HD;
    const __half* Vgb = Vg + (size_t)bh * SEQ * HD;
    attn_prefetch(sb, 0, 0, Kgb, Vgb, tid);
    CP_COMMIT();
    attn_prefetch(sb, 1, 1, Kgb, Vgb, tid);
    CP_COMMIT();

    asm volatile("cp.async.wait_group 1;" ::: "memory");
    __syncthreads();

    uint32_t qf[8][4];
    {
        const uint32_t qbase = sb + SQH + (wid * 16 + (lane & 15)) * ASTRIDE + (lane >> 4) * 16;
        #pragma unroll
        for (int ks = 0; ks < 8; ks++) ldmx4(qf[ks], qbase + ks * 32);
    }

    float oacc[16][4];
    #pragma unroll
    for (int i = 0; i < 16; i++)
        #pragma unroll
        for (int j = 0; j < 4; j++) oacc[i][j] = 0.f;
    float m0 = -1e30f, m1 = -1e30f, l0 = 0.f, l1 = 0.f;

    for (int kt = 0; kt < 32; kt++) {
        const int cur = kt & 1;
        if (kt > 0) {
            if (kt + 1 < 32) {
                attn_prefetch(sb, (kt + 1) & 1, kt + 1, Kgb, Vgb, tid);
                CP_COMMIT();
                asm volatile("cp.async.wait_group 1;" ::: "memory");
            } else {
                asm volatile("cp.async.wait_group 0;" ::: "memory");
            }
            __syncthreads();
        }

        const uint32_t kbase = sb + SKBASE + cur * STAGE_SZ;
        const uint32_t vbase = kbase + KTILE_B;

        float sacc[8][4];
        #pragma unroll
        for (int i = 0; i < 8; i++)
            #pragma unroll
            for (int j = 0; j < 4; j++) sacc[i][j] = 0.f;

        #pragma unroll
        for (int ks = 0; ks < 8; ks++) {
            const uint32_t colb = ks * 32 + (lane >> 4) * 16;
            #pragma unroll
            for (int p = 0; p < 4; p++) {
                uint32_t kf[4];
                ldmx4(kf, kbase + (p * 16 + (lane & 15)) * ASTRIDE + colb);
                mma_f16(sacc[2*p],   qf[ks], kf[0], kf[2]);
                mma_f16(sacc[2*p+1], qf[ks], kf[1], kf[3]);
            }
        }

        float mx0 = -1e30f, mx1 = -1e30f;
        #pragma unroll
        for (int n = 0; n < 8; n++) {
            mx0 = fmaxf(mx0, fmaxf(sacc[n][0], sacc[n][1]));
            mx1 = fmaxf(mx1, fmaxf(sacc[n][2], sacc[n][3]));
        }
        mx0 = fmaxf(mx0, __shfl_xor_sync(0xffffffffu, mx0, 1));
        mx0 = fmaxf(mx0, __shfl_xor_sync(0xffffffffu, mx0, 2));
        mx1 = fmaxf(mx1, __shfl_xor_sync(0xffffffffu, mx1, 1));
        mx1 = fmaxf(mx1, __shfl_xor_sync(0xffffffffu, mx1, 2));
        const float mn0 = fmaxf(m0, mx0), mn1 = fmaxf(m1, mx1);
        const float a0 = __expf(m0 - mn0), a1 = __expf(m1 - mn1);
        m0 = mn0; m1 = mn1;
        float sum0 = 0.f, sum1 = 0.f;
        #pragma unroll
        for (int n = 0; n < 8; n++) {
            sacc[n][0] = __expf(sacc[n][0] - mn0);
            sacc[n][1] = __expf(sacc[n][1] - mn0);
            sacc[n][2] = __expf(sacc[n][2] - mn1);
            sacc[n][3] = __expf(sacc[n][3] - mn1);
            sum0 += sacc[n][0] + sacc[n][1];
            sum1 += sacc[n][2] + sacc[n][3];
        }
        sum0 += __shfl_xor_sync(0xffffffffu, sum0, 1);
        sum0 += __shfl_xor_sync(0xffffffffu, sum0, 2);
        sum1 += __shfl_xor_sync(0xffffffffu, sum1, 1);
        sum1 += __shfl_xor_sync(0xffffffffu, sum1, 2);
        l0 = l0 * a0 + sum0; l1 = l1 * a1 + sum1;
        #pragma unroll
        for (int i = 0; i < 16; i++) {
            oacc[i][0] *= a0; oacc[i][1] *= a0;
            oacc[i][2] *= a1; oacc[i][3] *= a1;
        }

        uint32_t ph[4][4];
        #pragma unroll
        for (int t = 0; t < 4; t++) {
            ph[t][0] = packh2(sacc[2*t][0],   sacc[2*t][1]);
            ph[t][1] = packh2(sacc[2*t][2],   sacc[2*t][3]);
            ph[t][2] = packh2(sacc[2*t+1][0], sacc[2*t+1][1]);
            ph[t][3] = packh2(sacc[2*t+1][2], sacc[2*t+1][3]);
        }

        #pragma unroll
        for (int t = 0; t < 4; t++) {
            const uint32_t vrow = vbase + (t * 16 + (lane & 15)) * ASTRIDE + (lane >> 4) * 16;
            #pragma unroll
            for (int g = 0; g < 8; g++) {
                uint32_t vf[4];
                ldmx4t(vf, vrow + g * 32);
                mma_f16(oacc[2*g],   ph[t], vf[0], vf[1]);
                mma_f16(oacc[2*g+1], ph[t], vf[2], vf[3]);
            }
        }
        __syncthreads();
    }

    const float inv0 = 1.f / l0, inv1 = 1.f / l1;
    const int row0 = qb * 128 + wid * 16 + (lane >> 2);
    float* base0 = mh + ((size_t)b * SEQ + row0) * DMODEL + h * HD + (lane & 3) * 2;
    float* base1 = base0 + 8 * DMODEL;
    #pragma unroll
    for (int nt = 0; nt < 16; nt++) {
        *(float2*)(base0 + nt * 8) = make_float2(oacc[nt][0] * inv0, oacc[nt][1] * inv0);
        *(float2*)(base1 + nt * 8) = make_float2(oacc[nt][2] * inv1, oacc[nt][3] * inv1);
    }
}

// =====================================================================
// LayerNorm (ddof=1, no eps) + residual; F16OUT also emits fp16 copy
// =====================================================================
template<int F16OUT>
__global__ __launch_bounds__(256) void ln_res_k(
    const float* __restrict__ x, const float* __restrict__ res,
    float* __restrict__ out, __half* __restrict__ h16)
{
    const int D = DMODEL;
    const size_t row = blockIdx.x;
    const float* xr = x + row * D;

    float s = 0.f, ss = 0.f;
    for (int i = threadIdx.x; i < D; i += 256) {
        float v = xr[i];
        s += v; ss = fmaf(v, v, ss);
    }
    #pragma unroll
    for (int off = 16; off > 0; off >>= 1) {
        s  += __shfl_xor_sync(0xffffffffu, s, off);
        ss += __shfl_xor_sync(0xffffffffu, ss, off);
    }
    __shared__ float sa[8], sbuf[8];
    int w = threadIdx.x >> 5, l = threadIdx.x & 31;
    if (l == 0) { sa[w] = s; sbuf[w] = ss; }
    __syncthreads();
    if (threadIdx.x < 32) {
        s  = (l < 8) ? sa[l] : 0.f;
        ss = (l < 8) ? sbuf[l] : 0.f;
        #pragma unroll
        for (int off = 4; off > 0; off >>= 1) {
            s  += __shfl_xor_sync(0xffffffffu, s, off);
            ss += __shfl_xor_sync(0xffffffffu, ss, off);
        }
        if (l == 0) { sa[0] = s; sbuf[0] = ss; }
    }
    __syncthreads();
    s = sa[0]; ss = sbuf[0];

    float mean = s / (float)D;
    float var  = (ss - s * s / (float)D) / (float)(D - 1);
    float rstd = rsqrtf(var);

    const float* rr = res + row * D;
    float* orow = out + row * D;
    for (int i = threadIdx.x; i < D; i += 256) {
        float o = rr[i] + (xr[i] - mean) * rstd;
        orow[i] = o;
        if (F16OUT) h16[row * D + i] = __float2half(o);
    }
}

// =====================================================================
extern "C" void kernel_launch(void* const* d_in, const int* in_sizes, int n_in,
                              void* d_out, int out_size)
{
    const float* q  = (const float*)d_in[0];
    const float* k  = (const float*)d_in[1];
    const float* v  = (const float*)d_in[2];
    const float* Wq = (const float*)d_in[3];
    const float* bq = (const float*)d_in[4];
    const float* Wk = (const float*)d_in[5];
    const float* bk = (const float*)d_in[6];
    const float* Wv = (const float*)d_in[7];
    const float* bv = (const float*)d_in[8];
    const float* W1 = (const float*)d_in[9];
    const float* b1 = (const float*)d_in[10];
    const float* W2 = (const float*)d_in[11];
    const float* b2 = (const float*)d_in[12];

    float *tmp, *mh, *res1;
    __nv_bfloat16 *Ahi, *Alo, *Bhi, *Blo;
    __half *A16, *W16, *F16, *Qh, *Kh, *Vh;
    cudaGetSymbolAddress((void**)&tmp,  g_tmp);
    cudaGetSymbolAddress((void**)&mh,   g_mh);
    cudaGetSymbolAddress((void**)&res1, g_res1);
    cudaGetSymbolAddress((void**)&Ahi,  g_Ahi);
    cudaGetSymbolAddress((void**)&Alo,  g_Alo);
    cudaGetSymbolAddress((void**)&Bhi,  g_Bhi);
    cudaGetSymbolAddress((void**)&Blo,  g_Blo);
    cudaGetSymbolAddress((void**)&A16,  g_A16);
    cudaGetSymbolAddress((void**)&W16,  g_W16);
    cudaGetSymbolAddress((void**)&F16,  g_F16);
    cudaGetSymbolAddress((void**)&Qh,   g_Qh);
    cudaGetSymbolAddress((void**)&Kh,   g_Kh);
    cudaGetSymbolAddress((void**)&Vh,   g_Vh);

    cudaFuncSetAttribute(gemm_mma,
                         cudaFuncAttributeMaxDynamicSharedMemorySize, GEMM_SMEM);
    cudaFuncSetAttribute(gemm_f16,
                         cudaFuncAttributeMaxDynamicSharedMemorySize, GEMM16_SMEM);
    cudaFuncSetAttribute(attn_mma,
                         cudaFuncAttributeMaxDynamicSharedMemorySize, ATT_SMEM);

    dim3 blk(256);
    const int nD = MROWS * DMODEL;
    dim3 gProj(DMODEL / BN, MROWS / BM);
    dim3 gFF1(DFF / BN, MROWS / BM);

    // Encoder calls multihead(v, q, k): Q-in=v, K-in=q, V-in=k
    conv_split<<<nD / 4 / 256, blk>>>(v, Ahi, Alo, nD / 4);
    conv_wt_T<<<dim3(DMODEL / 32, DMODEL / 32), blk>>>(Wq, Bhi, Blo, DMODEL, DMODEL);
    gemm_mma<<<gProj, blk, GEMM_SMEM>>>(Ahi, Alo, Bhi, Blo, bq, Qh,
                                        MROWS, DMODEL, DMODEL, QKSCALE);

    conv_split<<<nD / 4 / 256, blk>>>(q, Ahi, Alo, nD / 4);
    conv_wt_T<<<dim3(DMODEL / 32, DMODEL / 32), blk>>>(Wk, Bhi, Blo, DMODEL, DMODEL);
    gemm_mma<<<gProj, blk, GEMM_SMEM>>>(Ahi, Alo, Bhi, Blo, bk, Kh,
                                        MROWS, DMODEL, DMODEL, 1.0f);

    conv_split<<<nD / 4 / 256, blk>>>(k, Ahi, Alo, nD / 4);
    conv_wt_T<<<dim3(DMODEL / 32, DMODEL / 32), blk>>>(Wv, Bhi, Blo, DMODEL, DMODEL);
    gemm_mma<<<gProj, blk, GEMM_SMEM>>>(Ahi, Alo, Bhi, Blo, bv, Vh,
                                        MROWS, DMODEL, DMODEL, 1.0f);

    attn_mma<<<dim3(SEQ / 128, BATCH * NHEAD), blk, ATT_SMEM>>>(Qh, Kh, Vh, mh);

    // res1 = q + LN(mh); also emit fp16 for FF1
    ln_res_k<1><<<MROWS, blk>>>(mh, q, res1, A16);

    conv_wt_T16<<<dim3(DFF / 32, DMODEL / 32), blk>>>(W1, W16, DMODEL, DFF);
    gemm_f16<<<gFF1, blk, GEMM16_SMEM>>>(A16, W16, b1, nullptr, F16,
                                         MROWS, DFF, DMODEL, 1);

    conv_wt_T16<<<dim3(DMODEL / 32, DFF / 32), blk>>>(W2, W16, DFF, DMODEL);
    gemm_f16<<<gProj, blk, GEMM16_SMEM>>>(F16, W16, b2, tmp, nullptr,
                                          MROWS, DMODEL, DFF, 0);

    ln_res_k<0><<<MROWS, blk>>>(tmp, res1, (float*)d_out, nullptr);
}

// round 6
// speedup vs baseline: 7.3763x; 1.1810x over previous
#include <cuda_runtime.h>
#include <cuda_fp16.h>
#include <cstdint>

// Problem constants
#define BATCH 4
#define SEQ   2048
#define DMODEL 1024
#define NHEAD 8
#define HD    128
#define MROWS (BATCH*SEQ)        // 8192
#define DFF   4096
#define QKSCALE 0.08838834764831845f   // 1/sqrt(128)

// ---------------- scratch (no allocations allowed) ----------------
__device__ float g_tmp[(size_t)MROWS * DMODEL];
__device__ float g_mh[(size_t)MROWS * DMODEL];
__device__ float g_res1[(size_t)MROWS * DMODEL];
__device__ __half g_A16[(size_t)MROWS * DMODEL];     // activation fp16 staging
__device__ __half g_W16[(size_t)DFF * DMODEL];       // weight fp16 (transposed)
__device__ __half g_F16[(size_t)MROWS * DFF];        // FF1 out fp16
__device__ __half g_Qh[(size_t)MROWS * DMODEL];
__device__ __half g_Kh[(size_t)MROWS * DMODEL];
__device__ __half g_Vh[(size_t)MROWS * DMODEL];

// ======================= PTX helpers =======================
__device__ __forceinline__ uint32_t smem_u32(const void* p) {
    uint32_t a;
    asm("{ .reg .u64 t; cvta.to.shared.u64 t, %1; cvt.u32.u64 %0, t; }" : "=r"(a) : "l"(p));
    return a;
}
__device__ __forceinline__ void cp_async16(uint32_t saddr, const void* gaddr) {
    asm volatile("cp.async.cg.shared.global [%0], [%1], 16;" :: "r"(saddr), "l"(gaddr) : "memory");
}
#define CP_COMMIT() asm volatile("cp.async.commit_group;" ::: "memory")

__device__ __forceinline__ void ldmx4(uint32_t* r, uint32_t addr) {
    asm volatile("ldmatrix.sync.aligned.m8n8.x4.shared.b16 {%0,%1,%2,%3}, [%4];"
                 : "=r"(r[0]), "=r"(r[1]), "=r"(r[2]), "=r"(r[3]) : "r"(addr));
}
__device__ __forceinline__ void ldmx4t(uint32_t* r, uint32_t addr) {
    asm volatile("ldmatrix.sync.aligned.m8n8.x4.trans.shared.b16 {%0,%1,%2,%3}, [%4];"
                 : "=r"(r[0]), "=r"(r[1]), "=r"(r[2]), "=r"(r[3]) : "r"(addr));
}
__device__ __forceinline__ void mma_f16(float* c, const uint32_t* a,
                                        uint32_t b0, uint32_t b1) {
    asm volatile(
        "mma.sync.aligned.m16n8k16.row.col.f32.f16.f16.f32 "
        "{%0,%1,%2,%3}, {%4,%5,%6,%7}, {%8,%9}, {%0,%1,%2,%3};"
        : "+f"(c[0]), "+f"(c[1]), "+f"(c[2]), "+f"(c[3])
        : "r"(a[0]), "r"(a[1]), "r"(a[2]), "r"(a[3]), "r"(b0), "r"(b1));
}
__device__ __forceinline__ uint32_t packh2(float a, float b) {
    __half2 h = __floats2half2_rn(a, b);
    return *(uint32_t*)&h;
}

// =====================================================================
// float -> fp16 conversion (inputs)
// =====================================================================
__global__ __launch_bounds__(256) void conv_h(
    const float* __restrict__ x, __half* __restrict__ out, int n4)
{
    int i = blockIdx.x * 256 + threadIdx.x;
    if (i >= n4) return;
    float4 v = ((const float4*)x)[i];
    __half2* op = (__half2*)(out + (size_t)i * 4);
    op[0] = __floats2half2_rn(v.x, v.y);
    op[1] = __floats2half2_rn(v.z, v.w);
}

// =====================================================================
// weight transpose fp16: W[K,N] -> Wt[N,K] half
// =====================================================================
__global__ __launch_bounds__(256) void conv_wt_T16(
    const float* __restrict__ W, __half* __restrict__ out, int K, int N)
{
    __shared__ float t[32][33];
    int k0 = blockIdx.y * 32, n0 = blockIdx.x * 32;
    int tx = threadIdx.x & 31, ty = threadIdx.x >> 5;
    #pragma unroll
    for (int i = ty; i < 32; i += 8)
        t[i][tx] = W[(size_t)(k0 + i) * N + n0 + tx];
    __syncthreads();
    #pragma unroll
    for (int i = ty; i < 32; i += 8)
        out[(size_t)(n0 + i) * K + k0 + tx] = __float2half(t[tx][i]);
}

// =====================================================================
// single-product fp16 GEMM: C = A[M,K] @ Bt[N,K]^T + bias
// mode 0: f32 out   mode 1: ReLU + fp16 out
// mode 2: fp16 out, head-permuted to [B,H,S,hd], scaled
// BM=128, BN=128, BK=32. 8 warps, each 32(M)x64(N).
// =====================================================================
#define BM 128
#define BN 128
#define BK 32
#define ROWB 80
#define OPB  (128 * ROWB)
#define NSTAGE 3
#define STAGE16 (2 * OPB)
#define GEMM16_SMEM (NSTAGE * STAGE16)

__device__ __forceinline__ void prefetch16(
    uint32_t sbase, int stage, int c,
    const __half* A, const __half* B, int m0, int n0, int K, int tid)
{
    const int k0 = c * BK;
    const uint32_t sb = sbase + stage * STAGE16;
    #pragma unroll
    for (int t = 0; t < 2; t++) {
        int seg = tid + 256 * t;
        int row = seg >> 2;
        int sc  = seg & 3;
        uint32_t soff = row * ROWB + sc * 16;
        cp_async16(sb + soff,       A + (size_t)(m0 + row) * K + k0 + sc * 8);
        cp_async16(sb + OPB + soff, B + (size_t)(n0 + row) * K + k0 + sc * 8);
    }
}

__global__ __launch_bounds__(256, 1) void gemm_f16(
    const __half* __restrict__ A, const __half* __restrict__ B,
    const float* __restrict__ bias, float* __restrict__ Cf,
    __half* __restrict__ Ch, int M, int N, int K, int mode, float scale)
{
    extern __shared__ char smem[];
    const uint32_t sbase = smem_u32(smem);
    const int tid = threadIdx.x;
    const int wid = tid >> 5, lane = tid & 31;
    const int wm = wid >> 1;
    const int wn = wid & 1;
    const int m0 = blockIdx.y * BM, n0 = blockIdx.x * BN;
    const int NC = K / BK;

    float acc[2][8][4];
    #pragma unroll
    for (int i = 0; i < 2; i++)
        #pragma unroll
        for (int j = 0; j < 8; j++)
            #pragma unroll
            for (int x = 0; x < 4; x++) acc[i][j][x] = 0.f;

    prefetch16(sbase, 0, 0, A, B, m0, n0, K, tid); CP_COMMIT();
    prefetch16(sbase, 1, 1, A, B, m0, n0, K, tid); CP_COMMIT();

    const uint32_t lrow = (lane & 15);
    const uint32_t lcol = (lane >> 4) * 16;

    for (int c = 0; c < NC; c++) {
        const int sc = c % NSTAGE;
        if (c + 2 < NC) { asm volatile("cp.async.wait_group 1;" ::: "memory"); }
        else            { asm volatile("cp.async.wait_group 0;" ::: "memory"); }
        __syncthreads();

        const uint32_t stg = sbase + sc * STAGE16;
        const uint32_t aBase = stg + (wm * 32) * ROWB + lrow * ROWB + lcol;
        const uint32_t bBase = stg + OPB + (wn * 64) * ROWB + lrow * ROWB + lcol;

        #pragma unroll
        for (int kk = 0; kk < 2; kk++) {
            const uint32_t kb = kk * 32;
            uint32_t ah[2][4];
            #pragma unroll
            for (int mt = 0; mt < 2; mt++)
                ldmx4(ah[mt], aBase + mt * 16 * ROWB + kb);
            #pragma unroll
            for (int p = 0; p < 4; p++) {
                uint32_t bh[4];
                ldmx4(bh, bBase + p * 16 * ROWB + kb);
                #pragma unroll
                for (int mt = 0; mt < 2; mt++) {
                    mma_f16(acc[mt][2*p],   ah[mt], bh[0], bh[2]);
                    mma_f16(acc[mt][2*p+1], ah[mt], bh[1], bh[3]);
                }
            }
        }
        __syncthreads();
        if (c + 2 < NC) {
            prefetch16(sbase, (c + 2) % NSTAGE, c + 2, A, B, m0, n0, K, tid);
            CP_COMMIT();
        }
    }

    const int rbase = m0 + wm * 32 + (lane >> 2);
    const int cbase = n0 + wn * 64 + (lane & 3) * 2;
    #pragma unroll
    for (int mt = 0; mt < 2; mt++) {
        #pragma unroll
        for (int nt = 0; nt < 8; nt++) {
            const int col = cbase + nt * 8;
            const float bz0 = bias[col], bz1 = bias[col + 1];
            #pragma unroll
            for (int h = 0; h < 2; h++) {
                const int row = rbase + mt * 16 + h * 8;
                float v0 = acc[mt][nt][2*h]   + bz0;
                float v1 = acc[mt][nt][2*h+1] + bz1;
                if (mode == 0) {
                    float* dst = Cf + (size_t)row * N + col;
                    dst[0] = v0; dst[1] = v1;
                } else if (mode == 1) {
                    v0 = fmaxf(v0, 0.f); v1 = fmaxf(v1, 0.f);
                    *(__half2*)(Ch + (size_t)row * N + col) = __floats2half2_rn(v0, v1);
                } else {
                    v0 *= scale; v1 *= scale;
                    const int b = row >> 11, s = row & (SEQ - 1);
                    const int hh = col >> 7, d = col & (HD - 1);
                    __half2* dst = (__half2*)(Ch +
                        (((size_t)b * NHEAD + hh) * SEQ + s) * HD + d);
                    *dst = __floats2half2_rn(v0, v1);
                }
            }
        }
    }
}

// =====================================================================
// fp16 flash attention (unchanged)
// =====================================================================
#define ASTRIDE 272
#define SQH 0
#define SKBASE 34816
#define KTILE_B (64 * ASTRIDE)
#define STAGE_SZ (2 * KTILE_B)
#define ATT_SMEM (SKBASE + 2 * STAGE_SZ)

__device__ __forceinline__ void attn_prefetch(
    uint32_t sb, int stage, int kt,
    const __half* Kgb, const __half* Vgb, int tid)
{
    #pragma unroll
    for (int t = 0; t < 8; t++) {
        int idx = tid + t * 256;
        int tensor = idx >> 10;
        int row = (idx >> 4) & 63;
        int c   = idx & 15;
        uint32_t dst = sb + SKBASE + stage * STAGE_SZ + tensor * KTILE_B
                     + row * ASTRIDE + c * 16;
        const __half* src = (tensor ? Vgb : Kgb) + (size_t)(kt * 64 + row) * HD + c * 8;
        cp_async16(dst, src);
    }
}

__global__ __launch_bounds__(256, 1) void attn_mma(
    const __half* __restrict__ Qg, const __half* __restrict__ Kg,
    const __half* __restrict__ Vg, float* __restrict__ mh)
{
    extern __shared__ char smem[];
    const uint32_t sb = smem_u32(smem);
    const int tid = threadIdx.x;
    const int wid = tid >> 5, lane = tid & 31;
    const int qb = blockIdx.x;
    const int bh = blockIdx.y;
    const int b = bh >> 3, h = bh & 7;

    const __half* Qgb = Qg + ((size_t)bh * SEQ + qb * 128) * HD;
    #pragma unroll
    for (int t = 0; t < 8; t++) {
        int idx = tid + t * 256;
        int row = idx >> 4, c = idx & 15;
        cp_async16(sb + SQH + row * ASTRIDE + c * 16, Qgb + (size_t)row * HD + c * 8);
    }
    const __half* Kgb = Kg + (size_t)bh * SEQ * HD;
    const __half* Vgb = Vg + (size_t)bh * SEQ * HD;
    attn_prefetch(sb, 0, 0, Kgb, Vgb, tid);
    CP_COMMIT();
    attn_prefetch(sb, 1, 1, Kgb, Vgb, tid);
    CP_COMMIT();

    asm volatile("cp.async.wait_group 1;" ::: "memory");
    __syncthreads();

    uint32_t qf[8][4];
    {
        const uint32_t qbase = sb + SQH + (wid * 16 + (lane & 15)) * ASTRIDE + (lane >> 4) * 16;
        #pragma unroll
        for (int ks = 0; ks < 8; ks++) ldmx4(qf[ks], qbase + ks * 32);
    }

    float oacc[16][4];
    #pragma unroll
    for (int i = 0; i < 16; i++)
        #pragma unroll
        for (int j = 0; j < 4; j++) oacc[i][j] = 0.f;
    float m0 = -1e30f, m1 = -1e30f, l0 = 0.f, l1 = 0.f;

    for (int kt = 0; kt < 32; kt++) {
        const int cur = kt & 1;
        if (kt > 0) {
            if (kt + 1 < 32) {
                attn_prefetch(sb, (kt + 1) & 1, kt + 1, Kgb, Vgb, tid);
                CP_COMMIT();
                asm volatile("cp.async.wait_group 1;" ::: "memory");
            } else {
                asm volatile("cp.async.wait_group 0;" ::: "memory");
            }
            __syncthreads();
        }

        const uint32_t kbase = sb + SKBASE + cur * STAGE_SZ;
        const uint32_t vbase = kbase + KTILE_B;

        float sacc[8][4];
        #pragma unroll
        for (int i = 0; i < 8; i++)
            #pragma unroll
            for (int j = 0; j < 4; j++) sacc[i][j] = 0.f;

        #pragma unroll
        for (int ks = 0; ks < 8; ks++) {
            const uint32_t colb = ks * 32 + (lane >> 4) * 16;
            #pragma unroll
            for (int p = 0; p < 4; p++) {
                uint32_t kf[4];
                ldmx4(kf, kbase + (p * 16 + (lane & 15)) * ASTRIDE + colb);
                mma_f16(sacc[2*p],   qf[ks], kf[0], kf[2]);
                mma_f16(sacc[2*p+1], qf[ks], kf[1], kf[3]);
            }
        }

        float mx0 = -1e30f, mx1 = -1e30f;
        #pragma unroll
        for (int n = 0; n < 8; n++) {
            mx0 = fmaxf(mx0, fmaxf(sacc[n][0], sacc[n][1]));
            mx1 = fmaxf(mx1, fmaxf(sacc[n][2], sacc[n][3]));
        }
        mx0 = fmaxf(mx0, __shfl_xor_sync(0xffffffffu, mx0, 1));
        mx0 = fmaxf(mx0, __shfl_xor_sync(0xffffffffu, mx0, 2));
        mx1 = fmaxf(mx1, __shfl_xor_sync(0xffffffffu, mx1, 1));
        mx1 = fmaxf(mx1, __shfl_xor_sync(0xffffffffu, mx1, 2));
        const float mn0 = fmaxf(m0, mx0), mn1 = fmaxf(m1, mx1);
        const float a0 = __expf(m0 - mn0), a1 = __expf(m1 - mn1);
        m0 = mn0; m1 = mn1;
        float sum0 = 0.f, sum1 = 0.f;
        #pragma unroll
        for (int n = 0; n < 8; n++) {
            sacc[n][0] = __expf(sacc[n][0] - mn0);
            sacc[n][1] = __expf(sacc[n][1] - mn0);
            sacc[n][2] = __expf(sacc[n][2] - mn1);
            sacc[n][3] = __expf(sacc[n][3] - mn1);
            sum0 += sacc[n][0] + sacc[n][1];
            sum1 += sacc[n][2] + sacc[n][3];
        }
        sum0 += __shfl_xor_sync(0xffffffffu, sum0, 1);
        sum0 += __shfl_xor_sync(0xffffffffu, sum0, 2);
        sum1 += __shfl_xor_sync(0xffffffffu, sum1, 1);
        sum1 += __shfl_xor_sync(0xffffffffu, sum1, 2);
        l0 = l0 * a0 + sum0; l1 = l1 * a1 + sum1;
        #pragma unroll
        for (int i = 0; i < 16; i++) {
            oacc[i][0] *= a0; oacc[i][1] *= a0;
            oacc[i][2] *= a1; oacc[i][3] *= a1;
        }

        uint32_t ph[4][4];
        #pragma unroll
        for (int t = 0; t < 4; t++) {
            ph[t][0] = packh2(sacc[2*t][0],   sacc[2*t][1]);
            ph[t][1] = packh2(sacc[2*t][2],   sacc[2*t][3]);
            ph[t][2] = packh2(sacc[2*t+1][0], sacc[2*t+1][1]);
            ph[t][3] = packh2(sacc[2*t+1][2], sacc[2*t+1][3]);
        }

        #pragma unroll
        for (int t = 0; t < 4; t++) {
            const uint32_t vrow = vbase + (t * 16 + (lane & 15)) * ASTRIDE + (lane >> 4) * 16;
            #pragma unroll
            for (int g = 0; g < 8; g++) {
                uint32_t vf[4];
                ldmx4t(vf, vrow + g * 32);
                mma_f16(oacc[2*g],   ph[t], vf[0], vf[1]);
                mma_f16(oacc[2*g+1], ph[t], vf[2], vf[3]);
            }
        }
        __syncthreads();
    }

    const float inv0 = 1.f / l0, inv1 = 1.f / l1;
    const int row0 = qb * 128 + wid * 16 + (lane >> 2);
    float* base0 = mh + ((size_t)b * SEQ + row0) * DMODEL + h * HD + (lane & 3) * 2;
    float* base1 = base0 + 8 * DMODEL;
    #pragma unroll
    for (int nt = 0; nt < 16; nt++) {
        *(float2*)(base0 + nt * 8) = make_float2(oacc[nt][0] * inv0, oacc[nt][1] * inv0);
        *(float2*)(base1 + nt * 8) = make_float2(oacc[nt][2] * inv1, oacc[nt][3] * inv1);
    }
}

// =====================================================================
// LayerNorm (ddof=1, no eps) + residual; F16OUT also emits fp16 copy
// =====================================================================
template<int F16OUT>
__global__ __launch_bounds__(256) void ln_res_k(
    const float* __restrict__ x, const float* __restrict__ res,
    float* __restrict__ out, __half* __restrict__ h16)
{
    const int D = DMODEL;
    const size_t row = blockIdx.x;
    const float* xr = x + row * D;

    float s = 0.f, ss = 0.f;
    for (int i = threadIdx.x; i < D; i += 256) {
        float v = xr[i];
        s += v; ss = fmaf(v, v, ss);
    }
    #pragma unroll
    for (int off = 16; off > 0; off >>= 1) {
        s  += __shfl_xor_sync(0xffffffffu, s, off);
        ss += __shfl_xor_sync(0xffffffffu, ss, off);
    }
    __shared__ float sa[8], sbuf[8];
    int w = threadIdx.x >> 5, l = threadIdx.x & 31;
    if (l == 0) { sa[w] = s; sbuf[w] = ss; }
    __syncthreads();
    if (threadIdx.x < 32) {
        s  = (l < 8) ? sa[l] : 0.f;
        ss = (l < 8) ? sbuf[l] : 0.f;
        #pragma unroll
        for (int off = 4; off > 0; off >>= 1) {
            s  += __shfl_xor_sync(0xffffffffu, s, off);
            ss += __shfl_xor_sync(0xffffffffu, ss, off);
        }
        if (l == 0) { sa[0] = s; sbuf[0] = ss; }
    }
    __syncthreads();
    s = sa[0]; ss = sbuf[0];

    float mean = s / (float)D;
    float var  = (ss - s * s / (float)D) / (float)(D - 1);
    float rstd = rsqrtf(var);

    const float* rr = res + row * D;
    float* orow = out + row * D;
    for (int i = threadIdx.x; i < D; i += 256) {
        float o = rr[i] + (xr[i] - mean) * rstd;
        orow[i] = o;
        if (F16OUT) h16[row * D + i] = __float2half(o);
    }
}

// =====================================================================
extern "C" void kernel_launch(void* const* d_in, const int* in_sizes, int n_in,
                              void* d_out, int out_size)
{
    const float* q  = (const float*)d_in[0];
    const float* k  = (const float*)d_in[1];
    const float* v  = (const float*)d_in[2];
    const float* Wq = (const float*)d_in[3];
    const float* bq = (const float*)d_in[4];
    const float* Wk = (const float*)d_in[5];
    const float* bk = (const float*)d_in[6];
    const float* Wv = (const float*)d_in[7];
    const float* bv = (const float*)d_in[8];
    const float* W1 = (const float*)d_in[9];
    const float* b1 = (const float*)d_in[10];
    const float* W2 = (const float*)d_in[11];
    const float* b2 = (const float*)d_in[12];

    float *tmp, *mh, *res1;
    __half *A16, *W16, *F16, *Qh, *Kh, *Vh;
    cudaGetSymbolAddress((void**)&tmp,  g_tmp);
    cudaGetSymbolAddress((void**)&mh,   g_mh);
    cudaGetSymbolAddress((void**)&res1, g_res1);
    cudaGetSymbolAddress((void**)&A16,  g_A16);
    cudaGetSymbolAddress((void**)&W16,  g_W16);
    cudaGetSymbolAddress((void**)&F16,  g_F16);
    cudaGetSymbolAddress((void**)&Qh,   g_Qh);
    cudaGetSymbolAddress((void**)&Kh,   g_Kh);
    cudaGetSymbolAddress((void**)&Vh,   g_Vh);

    cudaFuncSetAttribute(gemm_f16,
                         cudaFuncAttributeMaxDynamicSharedMemorySize, GEMM16_SMEM);
    cudaFuncSetAttribute(attn_mma,
                         cudaFuncAttributeMaxDynamicSharedMemorySize, ATT_SMEM);

    dim3 blk(256);
    const int nD = MROWS * DMODEL;
    dim3 gProj(DMODEL / BN, MROWS / BM);
    dim3 gFF1(DFF / BN, MROWS / BM);

    // Encoder calls multihead(v, q, k): Q-in=v, K-in=q, V-in=k
    conv_h<<<nD / 4 / 256, blk>>>(v, A16, nD / 4);
    conv_wt_T16<<<dim3(DMODEL / 32, DMODEL / 32), blk>>>(Wq, W16, DMODEL, DMODEL);
    gemm_f16<<<gProj, blk, GEMM16_SMEM>>>(A16, W16, bq, nullptr, Qh,
                                          MROWS, DMODEL, DMODEL, 2, QKSCALE);

    conv_h<<<nD / 4 / 256, blk>>>(q, A16, nD / 4);
    conv_wt_T16<<<dim3(DMODEL / 32, DMODEL / 32), blk>>>(Wk, W16, DMODEL, DMODEL);
    gemm_f16<<<gProj, blk, GEMM16_SMEM>>>(A16, W16, bk, nullptr, Kh,
                                          MROWS, DMODEL, DMODEL, 2, 1.0f);

    conv_h<<<nD / 4 / 256, blk>>>(k, A16, nD / 4);
    conv_wt_T16<<<dim3(DMODEL / 32, DMODEL / 32), blk>>>(Wv, W16, DMODEL, DMODEL);
    gemm_f16<<<gProj, blk, GEMM16_SMEM>>>(A16, W16, bv, nullptr, Vh,
                                          MROWS, DMODEL, DMODEL, 2, 1.0f);

    attn_mma<<<dim3(SEQ / 128, BATCH * NHEAD), blk, ATT_SMEM>>>(Qh, Kh, Vh, mh);

    // res1 = q + LN(mh); also emit fp16 for FF1
    ln_res_k<1><<<MROWS, blk>>>(mh, q, res1, A16);

    conv_wt_T16<<<dim3(DFF / 32, DMODEL / 32), blk>>>(W1, W16, DMODEL, DFF);
    gemm_f16<<<gFF1, blk, GEMM16_SMEM>>>(A16, W16, b1, nullptr, F16,
                                         MROWS, DFF, DMODEL, 1, 1.0f);

    conv_wt_T16<<<dim3(DMODEL / 32, DFF / 32), blk>>>(W2, W16, DFF, DMODEL);
    gemm_f16<<<gProj, blk, GEMM16_SMEM>>>(F16, W16, b2, tmp, nullptr,
                                          MROWS, DMODEL, DFF, 0, 1.0f);

    ln_res_k<0><<<MROWS, blk>>>(tmp, res1, (float*)d_out, nullptr);
}

// round 7
// speedup vs baseline: 8.7419x; 1.1851x over previous
#include <cuda_runtime.h>
#include <cuda_fp16.h>
#include <cstdint>

// Problem constants
#define BATCH 4
#define SEQ   2048
#define DMODEL 1024
#define NHEAD 8
#define HD    128
#define MROWS (BATCH*SEQ)        // 8192
#define DFF   4096
#define QKSCALE 0.08838834764831845f   // 1/sqrt(128)

// ---------------- scratch (no allocations allowed) ----------------
__device__ float g_tmp[(size_t)MROWS * DMODEL];
__device__ float g_mh[(size_t)MROWS * DMODEL];
__device__ float g_res1[(size_t)MROWS * DMODEL];
__device__ __half g_A16[(size_t)MROWS * DMODEL];     // v16, later LN1 fp16 out
__device__ __half g_F16[(size_t)MROWS * DFF];        // q16+k16 early, FF1 out later
__device__ __half g_W1t[(size_t)DFF * DMODEL];
__device__ __half g_W2t[(size_t)DFF * DMODEL];
__device__ __half g_Wq16[(size_t)DMODEL * DMODEL];
__device__ __half g_Wk16[(size_t)DMODEL * DMODEL];
__device__ __half g_Wv16[(size_t)DMODEL * DMODEL];
__device__ __half g_Qh[(size_t)MROWS * DMODEL];
__device__ __half g_Kh[(size_t)MROWS * DMODEL];
__device__ __half g_Vh[(size_t)MROWS * DMODEL];

// ======================= PTX helpers =======================
__device__ __forceinline__ uint32_t smem_u32(const void* p) {
    uint32_t a;
    asm("{ .reg .u64 t; cvta.to.shared.u64 t, %1; cvt.u32.u64 %0, t; }" : "=r"(a) : "l"(p));
    return a;
}
__device__ __forceinline__ void cp_async16(uint32_t saddr, const void* gaddr) {
    asm volatile("cp.async.cg.shared.global [%0], [%1], 16;" :: "r"(saddr), "l"(gaddr) : "memory");
}
#define CP_COMMIT() asm volatile("cp.async.commit_group;" ::: "memory")

__device__ __forceinline__ void ldmx4(uint32_t* r, uint32_t addr) {
    asm volatile("ldmatrix.sync.aligned.m8n8.x4.shared.b16 {%0,%1,%2,%3}, [%4];"
                 : "=r"(r[0]), "=r"(r[1]), "=r"(r[2]), "=r"(r[3]) : "r"(addr));
}
__device__ __forceinline__ void ldmx4t(uint32_t* r, uint32_t addr) {
    asm volatile("ldmatrix.sync.aligned.m8n8.x4.trans.shared.b16 {%0,%1,%2,%3}, [%4];"
                 : "=r"(r[0]), "=r"(r[1]), "=r"(r[2]), "=r"(r[3]) : "r"(addr));
}
__device__ __forceinline__ void mma_f16(float* c, const uint32_t* a,
                                        uint32_t b0, uint32_t b1) {
    asm volatile(
        "mma.sync.aligned.m16n8k16.row.col.f32.f16.f16.f32 "
        "{%0,%1,%2,%3}, {%4,%5,%6,%7}, {%8,%9}, {%0,%1,%2,%3};"
        : "+f"(c[0]), "+f"(c[1]), "+f"(c[2]), "+f"(c[3])
        : "r"(a[0]), "r"(a[1]), "r"(a[2]), "r"(a[3]), "r"(b0), "r"(b1));
}
__device__ __forceinline__ uint32_t packh2(float a, float b) {
    __half2 h = __floats2half2_rn(a, b);
    return *(uint32_t*)&h;
}

// =====================================================================
// fused fp16 conversion of the three inputs (one launch)
// =====================================================================
#define N4SEG (MROWS * DMODEL / 4)     // 2M float4 per tensor
__global__ __launch_bounds__(256) void conv_h3(
    const float* __restrict__ x0, const float* __restrict__ x1,
    const float* __restrict__ x2,
    __half* __restrict__ o0, __half* __restrict__ o1, __half* __restrict__ o2)
{
    int i = blockIdx.x * 256 + threadIdx.x;     // 0 .. 3*N4SEG
    int seg = i / N4SEG;
    int j   = i - seg * N4SEG;
    const float* x = (seg == 0) ? x0 : (seg == 1) ? x1 : x2;
    __half* o      = (seg == 0) ? o0 : (seg == 1) ? o1 : o2;
    float4 v = ((const float4*)x)[j];
    __half2* op = (__half2*)(o + (size_t)j * 4);
    op[0] = __floats2half2_rn(v.x, v.y);
    op[1] = __floats2half2_rn(v.z, v.w);
}

// =====================================================================
// fused weight transpose fp16 for all 5 weights (one launch)
// segments (32x32 tiles): [0,1024) Wq, [1024,2048) Wk, [2048,3072) Wv,
//                         [3072,7168) W1 (gx=128), [7168,11264) W2 (gx=32)
// =====================================================================
#define WT_BLOCKS 11264
__global__ __launch_bounds__(256) void wt_all(
    const float* __restrict__ Wq, const float* __restrict__ Wk,
    const float* __restrict__ Wv, const float* __restrict__ W1,
    const float* __restrict__ W2,
    __half* __restrict__ oQ, __half* __restrict__ oK, __half* __restrict__ oV,
    __half* __restrict__ o1, __half* __restrict__ o2)
{
    const int bid = blockIdx.x;
    const float* W; __half* out; int K, N, l, gx;
    if (bid < 3072) {
        l = bid & 1023; gx = 32; K = DMODEL; N = DMODEL;
        int w = bid >> 10;
        W   = (w == 0) ? Wq : (w == 1) ? Wk : Wv;
        out = (w == 0) ? oQ : (w == 1) ? oK : oV;
    } else if (bid < 7168) {
        l = bid - 3072; gx = 128; K = DMODEL; N = DFF;  W = W1; out = o1;
    } else {
        l = bid - 7168; gx = 32;  K = DFF; N = DMODEL;  W = W2; out = o2;
    }
    const int bx = l % gx, by = l / gx;
    const int k0 = by * 32, n0 = bx * 32;

    __shared__ float t[32][33];
    int tx = threadIdx.x & 31, ty = threadIdx.x >> 5;
    #pragma unroll
    for (int i = ty; i < 32; i += 8)
        t[i][tx] = W[(size_t)(k0 + i) * N + n0 + tx];
    __syncthreads();
    #pragma unroll
    for (int i = ty; i < 32; i += 8)
        out[(size_t)(n0 + i) * K + k0 + tx] = __float2half(t[tx][i]);
}

// =====================================================================
// fp16 GEMM core (shared by projections and FF)
// =====================================================================
#define BM 128
#define BN 128
#define BK 32
#define ROWB 80
#define OPB  (128 * ROWB)
#define NSTAGE 3
#define STAGE16 (2 * OPB)
#define GEMM16_SMEM (NSTAGE * STAGE16)

__device__ __forceinline__ void prefetch16(
    uint32_t sbase, int stage, int c,
    const __half* A, const __half* B, int m0, int n0, int K, int tid)
{
    const int k0 = c * BK;
    const uint32_t sb = sbase + stage * STAGE16;
    #pragma unroll
    for (int t = 0; t < 2; t++) {
        int seg = tid + 256 * t;
        int row = seg >> 2;
        int sc  = seg & 3;
        uint32_t soff = row * ROWB + sc * 16;
        cp_async16(sb + soff,       A + (size_t)(m0 + row) * K + k0 + sc * 8);
        cp_async16(sb + OPB + soff, B + (size_t)(n0 + row) * K + k0 + sc * 8);
    }
}

// mainloop producing acc; returns nothing (acc by ref)
__device__ __forceinline__ void gemm_core(
    uint32_t sbase, const __half* A, const __half* B,
    int m0, int n0, int K, int tid, int wid, int lane,
    float acc[2][8][4])
{
    const int wm = wid >> 1;
    const int wn = wid & 1;
    const int NC = K / BK;

    prefetch16(sbase, 0, 0, A, B, m0, n0, K, tid); CP_COMMIT();
    prefetch16(sbase, 1, 1, A, B, m0, n0, K, tid); CP_COMMIT();

    const uint32_t lrow = (lane & 15);
    const uint32_t lcol = (lane >> 4) * 16;

    for (int c = 0; c < NC; c++) {
        const int sc = c % NSTAGE;
        if (c + 2 < NC) { asm volatile("cp.async.wait_group 1;" ::: "memory"); }
        else            { asm volatile("cp.async.wait_group 0;" ::: "memory"); }
        __syncthreads();

        const uint32_t stg = sbase + sc * STAGE16;
        const uint32_t aBase = stg + (wm * 32) * ROWB + lrow * ROWB + lcol;
        const uint32_t bBase = stg + OPB + (wn * 64) * ROWB + lrow * ROWB + lcol;

        #pragma unroll
        for (int kk = 0; kk < 2; kk++) {
            const uint32_t kb = kk * 32;
            uint32_t ah[2][4];
            #pragma unroll
            for (int mt = 0; mt < 2; mt++)
                ldmx4(ah[mt], aBase + mt * 16 * ROWB + kb);
            #pragma unroll
            for (int p = 0; p < 4; p++) {
                uint32_t bh[4];
                ldmx4(bh, bBase + p * 16 * ROWB + kb);
                #pragma unroll
                for (int mt = 0; mt < 2; mt++) {
                    mma_f16(acc[mt][2*p],   ah[mt], bh[0], bh[2]);
                    mma_f16(acc[mt][2*p+1], ah[mt], bh[1], bh[3]);
                }
            }
        }
        __syncthreads();
        if (c + 2 < NC) {
            prefetch16(sbase, (c + 2) % NSTAGE, c + 2, A, B, m0, n0, K, tid);
            CP_COMMIT();
        }
    }
}

// ---- z-batched QKV projection: out fp16 head-permuted [B,H,S,hd] ----
__global__ __launch_bounds__(256, 2) void gemm_proj(
    const __half* __restrict__ A0, const __half* __restrict__ A1,
    const __half* __restrict__ A2,
    const float* __restrict__ b0c, const float* __restrict__ b1c,
    const float* __restrict__ b2c,
    __half* __restrict__ o0, __half* __restrict__ o1, __half* __restrict__ o2)
{
    extern __shared__ char smem[];
    const uint32_t sbase = smem_u32(smem);
    const int tid = threadIdx.x;
    const int wid = tid >> 5, lane = tid & 31;
    const int z = blockIdx.z;
    const int m0 = blockIdx.y * BM, n0 = blockIdx.x * BN;

    const __half* A  = (z == 0) ? A0 : (z == 1) ? A1 : A2;
    const float* bias = (z == 0) ? b0c : (z == 1) ? b1c : b2c;
    __half* Ch       = (z == 0) ? o0 : (z == 1) ? o1 : o2;
    const float scale = (z == 0) ? QKSCALE : 1.0f;

    float acc[2][8][4];
    #pragma unroll
    for (int i = 0; i < 2; i++)
        #pragma unroll
        for (int j = 0; j < 8; j++)
            #pragma unroll
            for (int x = 0; x < 4; x++) acc[i][j][x] = 0.f;

    const __half* B = (z == 0) ? g_Wq16 : (z == 1) ? g_Wk16 : g_Wv16;
    gemm_core(sbase, A, B, m0, n0, DMODEL, tid, wid, lane, acc);

    const int wm = wid >> 1, wn = wid & 1;
    const int rbase = m0 + wm * 32 + (lane >> 2);
    const int cbase = n0 + wn * 64 + (lane & 3) * 2;
    #pragma unroll
    for (int mt = 0; mt < 2; mt++) {
        #pragma unroll
        for (int nt = 0; nt < 8; nt++) {
            const int col = cbase + nt * 8;
            const float bz0 = bias[col], bz1 = bias[col + 1];
            #pragma unroll
            for (int h = 0; h < 2; h++) {
                const int row = rbase + mt * 16 + h * 8;
                float v0 = (acc[mt][nt][2*h]   + bz0) * scale;
                float v1 = (acc[mt][nt][2*h+1] + bz1) * scale;
                const int b = row >> 11, s = row & (SEQ - 1);
                const int hh = col >> 7, d = col & (HD - 1);
                *(__half2*)(Ch + (((size_t)b * NHEAD + hh) * SEQ + s) * HD + d)
                    = __floats2half2_rn(v0, v1);
            }
        }
    }
}

// ---- generic FF GEMM: mode 0 f32 out, mode 1 ReLU + fp16 out ----
__global__ __launch_bounds__(256, 2) void gemm_f16(
    const __half* __restrict__ A, const __half* __restrict__ B,
    const float* __restrict__ bias, float* __restrict__ Cf,
    __half* __restrict__ Ch, int M, int N, int K, int mode)
{
    extern __shared__ char smem[];
    const uint32_t sbase = smem_u32(smem);
    const int tid = threadIdx.x;
    const int wid = tid >> 5, lane = tid & 31;
    const int m0 = blockIdx.y * BM, n0 = blockIdx.x * BN;

    float acc[2][8][4];
    #pragma unroll
    for (int i = 0; i < 2; i++)
        #pragma unroll
        for (int j = 0; j < 8; j++)
            #pragma unroll
            for (int x = 0; x < 4; x++) acc[i][j][x] = 0.f;

    gemm_core(sbase, A, B, m0, n0, K, tid, wid, lane, acc);

    const int wm = wid >> 1, wn = wid & 1;
    const int rbase = m0 + wm * 32 + (lane >> 2);
    const int cbase = n0 + wn * 64 + (lane & 3) * 2;
    #pragma unroll
    for (int mt = 0; mt < 2; mt++) {
        #pragma unroll
        for (int nt = 0; nt < 8; nt++) {
            const int col = cbase + nt * 8;
            const float bz0 = bias[col], bz1 = bias[col + 1];
            #pragma unroll
            for (int h = 0; h < 2; h++) {
                const int row = rbase + mt * 16 + h * 8;
                float v0 = acc[mt][nt][2*h]   + bz0;
                float v1 = acc[mt][nt][2*h+1] + bz1;
                if (mode == 0) {
                    float* dst = Cf + (size_t)row * N + col;
                    dst[0] = v0; dst[1] = v1;
                } else {
                    v0 = fmaxf(v0, 0.f); v1 = fmaxf(v1, 0.f);
                    *(__half2*)(Ch + (size_t)row * N + col) = __floats2half2_rn(v0, v1);
                }
            }
        }
    }
}

// =====================================================================
// fp16 flash attention (unchanged from R6)
// =====================================================================
#define ASTRIDE 272
#define SQH 0
#define SKBASE 34816
#define KTILE_B (64 * ASTRIDE)
#define STAGE_SZ (2 * KTILE_B)
#define ATT_SMEM (SKBASE + 2 * STAGE_SZ)

__device__ __forceinline__ void attn_prefetch(
    uint32_t sb, int stage, int kt,
    const __half* Kgb, const __half* Vgb, int tid)
{
    #pragma unroll
    for (int t = 0; t < 8; t++) {
        int idx = tid + t * 256;
        int tensor = idx >> 10;
        int row = (idx >> 4) & 63;
        int c   = idx & 15;
        uint32_t dst = sb + SKBASE + stage * STAGE_SZ + tensor * KTILE_B
                     + row * ASTRIDE + c * 16;
        const __half* src = (tensor ? Vgb : Kgb) + (size_t)(kt * 64 + row) * HD + c * 8;
        cp_async16(dst, src);
    }
}

__global__ __launch_bounds__(256, 1) void attn_mma(
    const __half* __restrict__ Qg, const __half* __restrict__ Kg,
    const __half* __restrict__ Vg, float* __restrict__ mh)
{
    extern __shared__ char smem[];
    const uint32_t sb = smem_u32(smem);
    const int tid = threadIdx.x;
    const int wid = tid >> 5, lane = tid & 31;
    const int qb = blockIdx.x;
    const int bh = blockIdx.y;
    const int b = bh >> 3, h = bh & 7;

    const __half* Qgb = Qg + ((size_t)bh * SEQ + qb * 128) * HD;
    #pragma unroll
    for (int t = 0; t < 8; t++) {
        int idx = tid + t * 256;
        int row = idx >> 4, c = idx & 15;
        cp_async16(sb + SQH + row * ASTRIDE + c * 16, Qgb + (size_t)row * HD + c * 8);
    }
    const __half* Kgb = Kg + (size_t)bh * SEQ * HD;
    const __half* Vgb = Vg + (size_t)bh * SEQ * HD;
    attn_prefetch(sb, 0, 0, Kgb, Vgb, tid);
    CP_COMMIT();
    attn_prefetch(sb, 1, 1, Kgb, Vgb, tid);
    CP_COMMIT();

    asm volatile("cp.async.wait_group 1;" ::: "memory");
    __syncthreads();

    uint32_t qf[8][4];
    {
        const uint32_t qbase = sb + SQH + (wid * 16 + (lane & 15)) * ASTRIDE + (lane >> 4) * 16;
        #pragma unroll
        for (int ks = 0; ks < 8; ks++) ldmx4(qf[ks], qbase + ks * 32);
    }

    float oacc[16][4];
    #pragma unroll
    for (int i = 0; i < 16; i++)
        #pragma unroll
        for (int j = 0; j < 4; j++) oacc[i][j] = 0.f;
    float m0 = -1e30f, m1 = -1e30f, l0 = 0.f, l1 = 0.f;

    for (int kt = 0; kt < 32; kt++) {
        const int cur = kt & 1;
        if (kt > 0) {
            if (kt + 1 < 32) {
                attn_prefetch(sb, (kt + 1) & 1, kt + 1, Kgb, Vgb, tid);
                CP_COMMIT();
                asm volatile("cp.async.wait_group 1;" ::: "memory");
            } else {
                asm volatile("cp.async.wait_group 0;" ::: "memory");
            }
            __syncthreads();
        }

        const uint32_t kbase = sb + SKBASE + cur * STAGE_SZ;
        const uint32_t vbase = kbase + KTILE_B;

        float sacc[8][4];
        #pragma unroll
        for (int i = 0; i < 8; i++)
            #pragma unroll
            for (int j = 0; j < 4; j++) sacc[i][j] = 0.f;

        #pragma unroll
        for (int ks = 0; ks < 8; ks++) {
            const uint32_t colb = ks * 32 + (lane >> 4) * 16;
            #pragma unroll
            for (int p = 0; p < 4; p++) {
                uint32_t kf[4];
                ldmx4(kf, kbase + (p * 16 + (lane & 15)) * ASTRIDE + colb);
                mma_f16(sacc[2*p],   qf[ks], kf[0], kf[2]);
                mma_f16(sacc[2*p+1], qf[ks], kf[1], kf[3]);
            }
        }

        float mx0 = -1e30f, mx1 = -1e30f;
        #pragma unroll
        for (int n = 0; n < 8; n++) {
            mx0 = fmaxf(mx0, fmaxf(sacc[n][0], sacc[n][1]));
            mx1 = fmaxf(mx1, fmaxf(sacc[n][2], sacc[n][3]));
        }
        mx0 = fmaxf(mx0, __shfl_xor_sync(0xffffffffu, mx0, 1));
        mx0 = fmaxf(mx0, __shfl_xor_sync(0xffffffffu, mx0, 2));
        mx1 = fmaxf(mx1, __shfl_xor_sync(0xffffffffu, mx1, 1));
        mx1 = fmaxf(mx1, __shfl_xor_sync(0xffffffffu, mx1, 2));
        const float mn0 = fmaxf(m0, mx0), mn1 = fmaxf(m1, mx1);
        const float a0 = __expf(m0 - mn0), a1 = __expf(m1 - mn1);
        m0 = mn0; m1 = mn1;
        float sum0 = 0.f, sum1 = 0.f;
        #pragma unroll
        for (int n = 0; n < 8; n++) {
            sacc[n][0] = __expf(sacc[n][0] - mn0);
            sacc[n][1] = __expf(sacc[n][1] - mn0);
            sacc[n][2] = __expf(sacc[n][2] - mn1);
            sacc[n][3] = __expf(sacc[n][3] - mn1);
            sum0 += sacc[n][0] + sacc[n][1];
            sum1 += sacc[n][2] + sacc[n][3];
        }
        sum0 += __shfl_xor_sync(0xffffffffu, sum0, 1);
        sum0 += __shfl_xor_sync(0xffffffffu, sum0, 2);
        sum1 += __shfl_xor_sync(0xffffffffu, sum1, 1);
        sum1 += __shfl_xor_sync(0xffffffffu, sum1, 2);
        l0 = l0 * a0 + sum0; l1 = l1 * a1 + sum1;
        #pragma unroll
        for (int i = 0; i < 16; i++) {
            oacc[i][0] *= a0; oacc[i][1] *= a0;
            oacc[i][2] *= a1; oacc[i][3] *= a1;
        }

        uint32_t ph[4][4];
        #pragma unroll
        for (int t = 0; t < 4; t++) {
            ph[t][0] = packh2(sacc[2*t][0],   sacc[2*t][1]);
            ph[t][1] = packh2(sacc[2*t][2],   sacc[2*t][3]);
            ph[t][2] = packh2(sacc[2*t+1][0], sacc[2*t+1][1]);
            ph[t][3] = packh2(sacc[2*t+1][2], sacc[2*t+1][3]);
        }

        #pragma unroll
        for (int t = 0; t < 4; t++) {
            const uint32_t vrow = vbase + (t * 16 + (lane & 15)) * ASTRIDE + (lane >> 4) * 16;
            #pragma unroll
            for (int g = 0; g < 8; g++) {
                uint32_t vf[4];
                ldmx4t(vf, vrow + g * 32);
                mma_f16(oacc[2*g],   ph[t], vf[0], vf[1]);
                mma_f16(oacc[2*g+1], ph[t], vf[2], vf[3]);
            }
        }
        __syncthreads();
    }

    const float inv0 = 1.f / l0, inv1 = 1.f / l1;
    const int row0 = qb * 128 + wid * 16 + (lane >> 2);
    float* base0 = mh + ((size_t)b * SEQ + row0) * DMODEL + h * HD + (lane & 3) * 2;
    float* base1 = base0 + 8 * DMODEL;
    #pragma unroll
    for (int nt = 0; nt < 16; nt++) {
        *(float2*)(base0 + nt * 8) = make_float2(oacc[nt][0] * inv0, oacc[nt][1] * inv0);
        *(float2*)(base1 + nt * 8) = make_float2(oacc[nt][2] * inv1, oacc[nt][3] * inv1);
    }
}

// =====================================================================
// LayerNorm (ddof=1, no eps) + residual; F16OUT also emits fp16 copy
// =====================================================================
template<int F16OUT>
__global__ __launch_bounds__(256) void ln_res_k(
    const float* __restrict__ x, const float* __restrict__ res,
    float* __restrict__ out, __half* __restrict__ h16)
{
    const int D = DMODEL;
    const size_t row = blockIdx.x;
    const float* xr = x + row * D;

    float s = 0.f, ss = 0.f;
    for (int i = threadIdx.x; i < D; i += 256) {
        float v = xr[i];
        s += v; ss = fmaf(v, v, ss);
    }
    #pragma unroll
    for (int off = 16; off > 0; off >>= 1) {
        s  += __shfl_xor_sync(0xffffffffu, s, off);
        ss += __shfl_xor_sync(0xffffffffu, ss, off);
    }
    __shared__ float sa[8], sbuf[8];
    int w = threadIdx.x >> 5, l = threadIdx.x & 31;
    if (l == 0) { sa[w] = s; sbuf[w] = ss; }
    __syncthreads();
    if (threadIdx.x < 32) {
        s  = (l < 8) ? sa[l] : 0.f;
        ss = (l < 8) ? sbuf[l] : 0.f;
        #pragma unroll
        for (int off = 4; off > 0; off >>= 1) {
            s  += __shfl_xor_sync(0xffffffffu, s, off);
            ss += __shfl_xor_sync(0xffffffffu, ss, off);
        }
        if (l == 0) { sa[0] = s; sbuf[0] = ss; }
    }
    __syncthreads();
    s = sa[0]; ss = sbuf[0];

    float mean = s / (float)D;
    float var  = (ss - s * s / (float)D) / (float)(D - 1);
    float rstd = rsqrtf(var);

    const float* rr = res + row * D;
    float* orow = out + row * D;
    for (int i = threadIdx.x; i < D; i += 256) {
        float o = rr[i] + (xr[i] - mean) * rstd;
        orow[i] = o;
        if (F16OUT) h16[row * D + i] = __float2half(o);
    }
}

// =====================================================================
extern "C" void kernel_launch(void* const* d_in, const int* in_sizes, int n_in,
                              void* d_out, int out_size)
{
    const float* q  = (const float*)d_in[0];
    const float* k  = (const float*)d_in[1];
    const float* v  = (const float*)d_in[2];
    const float* Wq = (const float*)d_in[3];
    const float* bq = (const float*)d_in[4];
    const float* Wk = (const float*)d_in[5];
    const float* bk = (const float*)d_in[6];
    const float* Wv = (const float*)d_in[7];
    const float* bv = (const float*)d_in[8];
    const float* W1 = (const float*)d_in[9];
    const float* b1 = (const float*)d_in[10];
    const float* W2 = (const float*)d_in[11];
    const float* b2 = (const float*)d_in[12];

    float *tmp, *mh, *res1;
    __half *A16, *F16, *W1t, *W2t, *Wq16, *Wk16, *Wv16, *Qh, *Kh, *Vh;
    cudaGetSymbolAddress((void**)&tmp,  g_tmp);
    cudaGetSymbolAddress((void**)&mh,   g_mh);
    cudaGetSymbolAddress((void**)&res1, g_res1);
    cudaGetSymbolAddress((void**)&A16,  g_A16);
    cudaGetSymbolAddress((void**)&F16,  g_F16);
    cudaGetSymbolAddress((void**)&W1t,  g_W1t);
    cudaGetSymbolAddress((void**)&W2t,  g_W2t);
    cudaGetSymbolAddress((void**)&Wq16, g_Wq16);
    cudaGetSymbolAddress((void**)&Wk16, g_Wk16);
    cudaGetSymbolAddress((void**)&Wv16, g_Wv16);
    cudaGetSymbolAddress((void**)&Qh,   g_Qh);
    cudaGetSymbolAddress((void**)&Kh,   g_Kh);
    cudaGetSymbolAddress((void**)&Vh,   g_Vh);

    // q16 / k16 staged in first/second half of F16 (free until FF1 output)
    __half* v16 = A16;
    __half* q16 = F16;
    __half* k16 = F16 + (size_t)MROWS * DMODEL;

    cudaFuncSetAttribute(gemm_proj,
                         cudaFuncAttributeMaxDynamicSharedMemorySize, GEMM16_SMEM);
    cudaFuncSetAttribute(gemm_f16,
                         cudaFuncAttributeMaxDynamicSharedMemorySize, GEMM16_SMEM);
    cudaFuncSetAttribute(attn_mma,
                         cudaFuncAttributeMaxDynamicSharedMemorySize, ATT_SMEM);

    dim3 blk(256);
    dim3 gProj(DMODEL / BN, MROWS / BM, 3);   // z-batched QKV
    dim3 gFF1(DFF / BN, MROWS / BM);
    dim3 gFF2(DMODEL / BN, MROWS / BM);

    // all format conversions up front (2 launches)
    conv_h3<<<3 * N4SEG / 256, blk>>>(v, q, k, v16, q16, k16);
    wt_all<<<WT_BLOCKS, blk>>>(Wq, Wk, Wv, W1, W2, Wq16, Wk16, Wv16, W1t, W2t);

    // Encoder calls multihead(v, q, k): Q-in=v, K-in=q, V-in=k
    gemm_proj<<<gProj, blk, GEMM16_SMEM>>>(v16, q16, k16, bq, bk, bv, Qh, Kh, Vh);

    attn_mma<<<dim3(SEQ / 128, BATCH * NHEAD), blk, ATT_SMEM>>>(Qh, Kh, Vh, mh);

    // res1 = q + LN(mh); also emit fp16 for FF1 (A16 reused)
    ln_res_k<1><<<MROWS, blk>>>(mh, q, res1, A16);

    gemm_f16<<<gFF1, blk, GEMM16_SMEM>>>(A16, W1t, b1, nullptr, F16,
                                         MROWS, DFF, DMODEL, 1);
    gemm_f16<<<gFF2, blk, GEMM16_SMEM>>>(F16, W2t, b2, tmp, nullptr,
                                         MROWS, DMODEL, DFF, 0);

    ln_res_k<0><<<MROWS, blk>>>(tmp, res1, (float*)d_out, nullptr);
}

// round 8
// speedup vs baseline: 9.3298x; 1.0672x over previous
#include <cuda_runtime.h>
#include <cuda_fp16.h>
#include <cstdint>

// Problem constants
#define BATCH 4
#define SEQ   2048
#define DMODEL 1024
#define NHEAD 8
#define HD    128
#define MROWS (BATCH*SEQ)        // 8192
#define DFF   4096
#define QKSCALE 0.08838834764831845f   // 1/sqrt(128)

// ---------------- scratch (no allocations allowed) ----------------
__device__ float g_tmp[(size_t)MROWS * DMODEL];
__device__ float g_mh[(size_t)MROWS * DMODEL];
__device__ float g_res1[(size_t)MROWS * DMODEL];
__device__ __half g_A16[(size_t)MROWS * DMODEL];     // v16, later LN1 fp16 out
__device__ __half g_F16[(size_t)MROWS * DFF];        // q16+k16 early, FF1 out later
__device__ __half g_W1t[(size_t)DFF * DMODEL];
__device__ __half g_W2t[(size_t)DFF * DMODEL];
__device__ __half g_Wq16[(size_t)DMODEL * DMODEL];
__device__ __half g_Wk16[(size_t)DMODEL * DMODEL];
__device__ __half g_Wv16[(size_t)DMODEL * DMODEL];
__device__ __half g_Qh[(size_t)MROWS * DMODEL];
__device__ __half g_Kh[(size_t)MROWS * DMODEL];
__device__ __half g_Vh[(size_t)MROWS * DMODEL];

// ======================= PTX helpers =======================
__device__ __forceinline__ uint32_t smem_u32(const void* p) {
    uint32_t a;
    asm("{ .reg .u64 t; cvta.to.shared.u64 t, %1; cvt.u32.u64 %0, t; }" : "=r"(a) : "l"(p));
    return a;
}
__device__ __forceinline__ void cp_async16(uint32_t saddr, const void* gaddr) {
    asm volatile("cp.async.cg.shared.global [%0], [%1], 16;" :: "r"(saddr), "l"(gaddr) : "memory");
}
#define CP_COMMIT() asm volatile("cp.async.commit_group;" ::: "memory")

__device__ __forceinline__ void ldmx4(uint32_t* r, uint32_t addr) {
    asm volatile("ldmatrix.sync.aligned.m8n8.x4.shared.b16 {%0,%1,%2,%3}, [%4];"
                 : "=r"(r[0]), "=r"(r[1]), "=r"(r[2]), "=r"(r[3]) : "r"(addr));
}
__device__ __forceinline__ void ldmx4t(uint32_t* r, uint32_t addr) {
    asm volatile("ldmatrix.sync.aligned.m8n8.x4.trans.shared.b16 {%0,%1,%2,%3}, [%4];"
                 : "=r"(r[0]), "=r"(r[1]), "=r"(r[2]), "=r"(r[3]) : "r"(addr));
}
__device__ __forceinline__ void mma_f16(float* c, const uint32_t* a,
                                        uint32_t b0, uint32_t b1) {
    asm volatile(
        "mma.sync.aligned.m16n8k16.row.col.f32.f16.f16.f32 "
        "{%0,%1,%2,%3}, {%4,%5,%6,%7}, {%8,%9}, {%0,%1,%2,%3};"
        : "+f"(c[0]), "+f"(c[1]), "+f"(c[2]), "+f"(c[3])
        : "r"(a[0]), "r"(a[1]), "r"(a[2]), "r"(a[3]), "r"(b0), "r"(b1));
}
__device__ __forceinline__ uint32_t packh2(float a, float b) {
    __half2 h = __floats2half2_rn(a, b);
    return *(uint32_t*)&h;
}

// =====================================================================
// fused conversions: inputs->fp16 AND all 5 weight transposes, ONE launch
// blocks [0, 24576): input conversion; [24576, 35840): weight transpose
// =====================================================================
#define N4SEG (MROWS * DMODEL / 4)     // 2M float4 per tensor
#define CONV_BLOCKS (3 * N4SEG / 256)  // 24576
#define WT_BLOCKS 11264
#define CW_BLOCKS (CONV_BLOCKS + WT_BLOCKS)

__global__ __launch_bounds__(256) void conv_wt_all(
    const float* __restrict__ x0, const float* __restrict__ x1,
    const float* __restrict__ x2,
    __half* __restrict__ o0c, __half* __restrict__ o1c, __half* __restrict__ o2c,
    const float* __restrict__ Wq, const float* __restrict__ Wk,
    const float* __restrict__ Wv, const float* __restrict__ W1,
    const float* __restrict__ W2,
    __half* __restrict__ oQ, __half* __restrict__ oK, __half* __restrict__ oV,
    __half* __restrict__ o1, __half* __restrict__ o2)
{
    __shared__ float t[32][33];
    if (blockIdx.x < CONV_BLOCKS) {
        int i = blockIdx.x * 256 + threadIdx.x;
        int seg = i / N4SEG;
        int j   = i - seg * N4SEG;
        const float* x = (seg == 0) ? x0 : (seg == 1) ? x1 : x2;
        __half* o      = (seg == 0) ? o0c : (seg == 1) ? o1c : o2c;
        float4 v = ((const float4*)x)[j];
        __half2* op = (__half2*)(o + (size_t)j * 4);
        op[0] = __floats2half2_rn(v.x, v.y);
        op[1] = __floats2half2_rn(v.z, v.w);
        return;
    }
    const int bid = blockIdx.x - CONV_BLOCKS;
    const float* W; __half* out; int K, N, l, gx;
    if (bid < 3072) {
        l = bid & 1023; gx = 32; K = DMODEL; N = DMODEL;
        int w = bid >> 10;
        W   = (w == 0) ? Wq : (w == 1) ? Wk : Wv;
        out = (w == 0) ? oQ : (w == 1) ? oK : oV;
    } else if (bid < 7168) {
        l = bid - 3072; gx = 128; K = DMODEL; N = DFF;  W = W1; out = o1;
    } else {
        l = bid - 7168; gx = 32;  K = DFF; N = DMODEL;  W = W2; out = o2;
    }
    const int bx = l % gx, by = l / gx;
    const int k0 = by * 32, n0 = bx * 32;
    int tx = threadIdx.x & 31, ty = threadIdx.x >> 5;
    #pragma unroll
    for (int i = ty; i < 32; i += 8)
        t[i][tx] = W[(size_t)(k0 + i) * N + n0 + tx];
    __syncthreads();
    #pragma unroll
    for (int i = ty; i < 32; i += 8)
        out[(size_t)(n0 + i) * K + k0 + tx] = __float2half(t[tx][i]);
}

// =====================================================================
// fp16 GEMM core: NSTAGE=4, prefetch depth 2, ONE barrier per chunk
// =====================================================================
#define BM 128
#define BN 128
#define BK 32
#define ROWB 80
#define OPB  (128 * ROWB)
#define NSTAGE 4
#define STAGE16 (2 * OPB)
#define GEMM16_SMEM (NSTAGE * STAGE16)   // 81920

__device__ __forceinline__ void prefetch16(
    uint32_t sbase, int stage, int c,
    const __half* A, const __half* B, int m0, int n0, int K, int tid)
{
    const int k0 = c * BK;
    const uint32_t sb = sbase + stage * STAGE16;
    #pragma unroll
    for (int t = 0; t < 2; t++) {
        int seg = tid + 256 * t;
        int row = seg >> 2;
        int sc  = seg & 3;
        uint32_t soff = row * ROWB + sc * 16;
        cp_async16(sb + soff,       A + (size_t)(m0 + row) * K + k0 + sc * 8);
        cp_async16(sb + OPB + soff, B + (size_t)(n0 + row) * K + k0 + sc * 8);
    }
}

__device__ __forceinline__ void gemm_core(
    uint32_t sbase, const __half* A, const __half* B,
    int m0, int n0, int K, int tid, int wid, int lane,
    float acc[2][8][4])
{
    const int wm = wid >> 1;
    const int wn = wid & 1;
    const int NC = K / BK;

    prefetch16(sbase, 0, 0, A, B, m0, n0, K, tid); CP_COMMIT();
    prefetch16(sbase, 1, 1, A, B, m0, n0, K, tid); CP_COMMIT();

    const uint32_t lrow = (lane & 15);
    const uint32_t lcol = (lane >> 4) * 16;

    for (int c = 0; c < NC; c++) {
        if (c + 2 < NC) {
            prefetch16(sbase, (c + 2) & 3, c + 2, A, B, m0, n0, K, tid);
            CP_COMMIT();
            asm volatile("cp.async.wait_group 2;" ::: "memory");
        } else {
            asm volatile("cp.async.wait_group 0;" ::: "memory");
        }
        __syncthreads();   // the only barrier per chunk (NS=4 > d+1 — safe)

        const uint32_t stg = sbase + (c & 3) * STAGE16;
        const uint32_t aBase = stg + (wm * 32) * ROWB + lrow * ROWB + lcol;
        const uint32_t bBase = stg + OPB + (wn * 64) * ROWB + lrow * ROWB + lcol;

        #pragma unroll
        for (int kk = 0; kk < 2; kk++) {
            const uint32_t kb = kk * 32;
            uint32_t ah[2][4];
            #pragma unroll
            for (int mt = 0; mt < 2; mt++)
                ldmx4(ah[mt], aBase + mt * 16 * ROWB + kb);
            #pragma unroll
            for (int p = 0; p < 4; p++) {
                uint32_t bh[4];
                ldmx4(bh, bBase + p * 16 * ROWB + kb);
                #pragma unroll
                for (int mt = 0; mt < 2; mt++) {
                    mma_f16(acc[mt][2*p],   ah[mt], bh[0], bh[2]);
                    mma_f16(acc[mt][2*p+1], ah[mt], bh[1], bh[3]);
                }
            }
        }
    }
}

// ---- z-batched QKV projection: out fp16 head-permuted [B,H,S,hd] ----
__global__ __launch_bounds__(256, 2) void gemm_proj(
    const __half* __restrict__ A0, const __half* __restrict__ A1,
    const __half* __restrict__ A2,
    const float* __restrict__ b0c, const float* __restrict__ b1c,
    const float* __restrict__ b2c,
    __half* __restrict__ o0, __half* __restrict__ o1, __half* __restrict__ o2)
{
    extern __shared__ char smem[];
    const uint32_t sbase = smem_u32(smem);
    const int tid = threadIdx.x;
    const int wid = tid >> 5, lane = tid & 31;
    const int z = blockIdx.z;
    const int m0 = blockIdx.y * BM, n0 = blockIdx.x * BN;

    const __half* A  = (z == 0) ? A0 : (z == 1) ? A1 : A2;
    const float* bias = (z == 0) ? b0c : (z == 1) ? b1c : b2c;
    __half* Ch       = (z == 0) ? o0 : (z == 1) ? o1 : o2;
    const float scale = (z == 0) ? QKSCALE : 1.0f;

    float acc[2][8][4];
    #pragma unroll
    for (int i = 0; i < 2; i++)
        #pragma unroll
        for (int j = 0; j < 8; j++)
            #pragma unroll
            for (int x = 0; x < 4; x++) acc[i][j][x] = 0.f;

    const __half* B = (z == 0) ? g_Wq16 : (z == 1) ? g_Wk16 : g_Wv16;
    gemm_core(sbase, A, B, m0, n0, DMODEL, tid, wid, lane, acc);

    const int wm = wid >> 1, wn = wid & 1;
    const int rbase = m0 + wm * 32 + (lane >> 2);
    const int cbase = n0 + wn * 64 + (lane & 3) * 2;
    #pragma unroll
    for (int mt = 0; mt < 2; mt++) {
        #pragma unroll
        for (int nt = 0; nt < 8; nt++) {
            const int col = cbase + nt * 8;
            const float bz0 = bias[col], bz1 = bias[col + 1];
            #pragma unroll
            for (int h = 0; h < 2; h++) {
                const int row = rbase + mt * 16 + h * 8;
                float v0 = (acc[mt][nt][2*h]   + bz0) * scale;
                float v1 = (acc[mt][nt][2*h+1] + bz1) * scale;
                const int b = row >> 11, s = row & (SEQ - 1);
                const int hh = col >> 7, d = col & (HD - 1);
                *(__half2*)(Ch + (((size_t)b * NHEAD + hh) * SEQ + s) * HD + d)
                    = __floats2half2_rn(v0, v1);
            }
        }
    }
}

// ---- generic FF GEMM: mode 0 f32 out, mode 1 ReLU + fp16 out ----
__global__ __launch_bounds__(256, 2) void gemm_f16(
    const __half* __restrict__ A, const __half* __restrict__ B,
    const float* __restrict__ bias, float* __restrict__ Cf,
    __half* __restrict__ Ch, int M, int N, int K, int mode)
{
    extern __shared__ char smem[];
    const uint32_t sbase = smem_u32(smem);
    const int tid = threadIdx.x;
    const int wid = tid >> 5, lane = tid & 31;
    const int m0 = blockIdx.y * BM, n0 = blockIdx.x * BN;

    float acc[2][8][4];
    #pragma unroll
    for (int i = 0; i < 2; i++)
        #pragma unroll
        for (int j = 0; j < 8; j++)
            #pragma unroll
            for (int x = 0; x < 4; x++) acc[i][j][x] = 0.f;

    gemm_core(sbase, A, B, m0, n0, K, tid, wid, lane, acc);

    const int wm = wid >> 1, wn = wid & 1;
    const int rbase = m0 + wm * 32 + (lane >> 2);
    const int cbase = n0 + wn * 64 + (lane & 3) * 2;
    #pragma unroll
    for (int mt = 0; mt < 2; mt++) {
        #pragma unroll
        for (int nt = 0; nt < 8; nt++) {
            const int col = cbase + nt * 8;
            const float bz0 = bias[col], bz1 = bias[col + 1];
            #pragma unroll
            for (int h = 0; h < 2; h++) {
                const int row = rbase + mt * 16 + h * 8;
                float v0 = acc[mt][nt][2*h]   + bz0;
                float v1 = acc[mt][nt][2*h+1] + bz1;
                if (mode == 0) {
                    float* dst = Cf + (size_t)row * N + col;
                    dst[0] = v0; dst[1] = v1;
                } else {
                    v0 = fmaxf(v0, 0.f); v1 = fmaxf(v1, 0.f);
                    *(__half2*)(Ch + (size_t)row * N + col) = __floats2half2_rn(v0, v1);
                }
            }
        }
    }
}

// =====================================================================
// fp16 flash attention: K/V 4-stage ring, prefetch depth 2,
// ONE barrier per key-tile.
// =====================================================================
#define ASTRIDE 272
#define SQH 0
#define SKBASE 34816                 // 128*272 (Q)
#define KTILE_B (64 * ASTRIDE)       // 17408
#define STAGE_SZ (2 * KTILE_B)       // K + V: 34816
#define ANSTAGE 4
#define ATT_SMEM (SKBASE + ANSTAGE * STAGE_SZ)   // 174080

__device__ __forceinline__ void attn_prefetch(
    uint32_t sb, int stage, int kt,
    const __half* Kgb, const __half* Vgb, int tid)
{
    #pragma unroll
    for (int t = 0; t < 8; t++) {
        int idx = tid + t * 256;
        int tensor = idx >> 10;
        int row = (idx >> 4) & 63;
        int c   = idx & 15;
        uint32_t dst = sb + SKBASE + stage * STAGE_SZ + tensor * KTILE_B
                     + row * ASTRIDE + c * 16;
        const __half* src = (tensor ? Vgb : Kgb) + (size_t)(kt * 64 + row) * HD + c * 8;
        cp_async16(dst, src);
    }
}

__global__ __launch_bounds__(256, 1) void attn_mma(
    const __half* __restrict__ Qg, const __half* __restrict__ Kg,
    const __half* __restrict__ Vg, float* __restrict__ mh)
{
    extern __shared__ char smem[];
    const uint32_t sb = smem_u32(smem);
    const int tid = threadIdx.x;
    const int wid = tid >> 5, lane = tid & 31;
    const int qb = blockIdx.x;
    const int bh = blockIdx.y;
    const int b = bh >> 3, h = bh & 7;

    // group 0: Q tile
    const __half* Qgb = Qg + ((size_t)bh * SEQ + qb * 128) * HD;
    #pragma unroll
    for (int t = 0; t < 8; t++) {
        int idx = tid + t * 256;
        int row = idx >> 4, c = idx & 15;
        cp_async16(sb + SQH + row * ASTRIDE + c * 16, Qgb + (size_t)row * HD + c * 8);
    }
    CP_COMMIT();
    const __half* Kgb = Kg + (size_t)bh * SEQ * HD;
    const __half* Vgb = Vg + (size_t)bh * SEQ * HD;
    attn_prefetch(sb, 0, 0, Kgb, Vgb, tid);   // group 1
    CP_COMMIT();
    attn_prefetch(sb, 1, 1, Kgb, Vgb, tid);   // group 2
    CP_COMMIT();

    asm volatile("cp.async.wait_group 2;" ::: "memory");   // Q ready
    __syncthreads();

    uint32_t qf[8][4];
    {
        const uint32_t qbase = sb + SQH + (wid * 16 + (lane & 15)) * ASTRIDE + (lane >> 4) * 16;
        #pragma unroll
        for (int ks = 0; ks < 8; ks++) ldmx4(qf[ks], qbase + ks * 32);
    }

    float oacc[16][4];
    #pragma unroll
    for (int i = 0; i < 16; i++)
        #pragma unroll
        for (int j = 0; j < 4; j++) oacc[i][j] = 0.f;
    float m0 = -1e30f, m1 = -1e30f, l0 = 0.f, l1 = 0.f;

    for (int kt = 0; kt < 32; kt++) {
        if (kt + 2 < 32) {
            attn_prefetch(sb, (kt + 2) & 3, kt + 2, Kgb, Vgb, tid);
            CP_COMMIT();
            asm volatile("cp.async.wait_group 2;" ::: "memory");
        } else {
            asm volatile("cp.async.wait_group 0;" ::: "memory");
        }
        __syncthreads();   // single barrier per tile (NS=4 > d+1 — safe)

        const uint32_t kbase = sb + SKBASE + (kt & 3) * STAGE_SZ;
        const uint32_t vbase = kbase + KTILE_B;

        float sacc[8][4];
        #pragma unroll
        for (int i = 0; i < 8; i++)
            #pragma unroll
            for (int j = 0; j < 4; j++) sacc[i][j] = 0.f;

        #pragma unroll
        for (int ks = 0; ks < 8; ks++) {
            const uint32_t colb = ks * 32 + (lane >> 4) * 16;
            #pragma unroll
            for (int p = 0; p < 4; p++) {
                uint32_t kf[4];
                ldmx4(kf, kbase + (p * 16 + (lane & 15)) * ASTRIDE + colb);
                mma_f16(sacc[2*p],   qf[ks], kf[0], kf[2]);
                mma_f16(sacc[2*p+1], qf[ks], kf[1], kf[3]);
            }
        }

        float mx0 = -1e30f, mx1 = -1e30f;
        #pragma unroll
        for (int n = 0; n < 8; n++) {
            mx0 = fmaxf(mx0, fmaxf(sacc[n][0], sacc[n][1]));
            mx1 = fmaxf(mx1, fmaxf(sacc[n][2], sacc[n][3]));
        }
        mx0 = fmaxf(mx0, __shfl_xor_sync(0xffffffffu, mx0, 1));
        mx0 = fmaxf(mx0, __shfl_xor_sync(0xffffffffu, mx0, 2));
        mx1 = fmaxf(mx1, __shfl_xor_sync(0xffffffffu, mx1, 1));
        mx1 = fmaxf(mx1, __shfl_xor_sync(0xffffffffu, mx1, 2));
        const float mn0 = fmaxf(m0, mx0), mn1 = fmaxf(m1, mx1);
        const float a0 = __expf(m0 - mn0), a1 = __expf(m1 - mn1);
        m0 = mn0; m1 = mn1;
        float sum0 = 0.f, sum1 = 0.f;
        #pragma unroll
        for (int n = 0; n < 8; n++) {
            sacc[n][0] = __expf(sacc[n][0] - mn0);
            sacc[n][1] = __expf(sacc[n][1] - mn0);
            sacc[n][2] = __expf(sacc[n][2] - mn1);
            sacc[n][3] = __expf(sacc[n][3] - mn1);
            sum0 += sacc[n][0] + sacc[n][1];
            sum1 += sacc[n][2] + sacc[n][3];
        }
        sum0 += __shfl_xor_sync(0xffffffffu, sum0, 1);
        sum0 += __shfl_xor_sync(0xffffffffu, sum0, 2);
        sum1 += __shfl_xor_sync(0xffffffffu, sum1, 1);
        sum1 += __shfl_xor_sync(0xffffffffu, sum1, 2);
        l0 = l0 * a0 + sum0; l1 = l1 * a1 + sum1;
        #pragma unroll
        for (int i = 0; i < 16; i++) {
            oacc[i][0] *= a0; oacc[i][1] *= a0;
            oacc[i][2] *= a1; oacc[i][3] *= a1;
        }

        uint32_t ph[4][4];
        #pragma unroll
        for (int t = 0; t < 4; t++) {
            ph[t][0] = packh2(sacc[2*t][0],   sacc[2*t][1]);
            ph[t][1] = packh2(sacc[2*t][2],   sacc[2*t][3]);
            ph[t][2] = packh2(sacc[2*t+1][0], sacc[2*t+1][1]);
            ph[t][3] = packh2(sacc[2*t+1][2], sacc[2*t+1][3]);
        }

        #pragma unroll
        for (int t = 0; t < 4; t++) {
            const uint32_t vrow = vbase + (t * 16 + (lane & 15)) * ASTRIDE + (lane >> 4) * 16;
            #pragma unroll
            for (int g = 0; g < 8; g++) {
                uint32_t vf[4];
                ldmx4t(vf, vrow + g * 32);
                mma_f16(oacc[2*g],   ph[t], vf[0], vf[1]);
                mma_f16(oacc[2*g+1], ph[t], vf[2], vf[3]);
            }
        }
        // no trailing barrier — 4-stage ring protects V reads
    }

    const float inv0 = 1.f / l0, inv1 = 1.f / l1;
    const int row0 = qb * 128 + wid * 16 + (lane >> 2);
    float* base0 = mh + ((size_t)b * SEQ + row0) * DMODEL + h * HD + (lane & 3) * 2;
    float* base1 = base0 + 8 * DMODEL;
    #pragma unroll
    for (int nt = 0; nt < 16; nt++) {
        *(float2*)(base0 + nt * 8) = make_float2(oacc[nt][0] * inv0, oacc[nt][1] * inv0);
        *(float2*)(base1 + nt * 8) = make_float2(oacc[nt][2] * inv1, oacc[nt][3] * inv1);
    }
}

// =====================================================================
// LayerNorm (ddof=1, no eps) + residual; F16OUT also emits fp16 copy
// =====================================================================
template<int F16OUT>
__global__ __launch_bounds__(256) void ln_res_k(
    const float* __restrict__ x, const float* __restrict__ res,
    float* __restrict__ out, __half* __restrict__ h16)
{
    const int D = DMODEL;
    const size_t row = blockIdx.x;
    const float* xr = x + row * D;

    float s = 0.f, ss = 0.f;
    for (int i = threadIdx.x; i < D; i += 256) {
        float v = xr[i];
        s += v; ss = fmaf(v, v, ss);
    }
    #pragma unroll
    for (int off = 16; off > 0; off >>= 1) {
        s  += __shfl_xor_sync(0xffffffffu, s, off);
        ss += __shfl_xor_sync(0xffffffffu, ss, off);
    }
    __shared__ float sa[8], sbuf[8];
    int w = threadIdx.x >> 5, l = threadIdx.x & 31;
    if (l == 0) { sa[w] = s; sbuf[w] = ss; }
    __syncthreads();
    if (threadIdx.x < 32) {
        s  = (l < 8) ? sa[l] : 0.f;
        ss = (l < 8) ? sbuf[l] : 0.f;
        #pragma unroll
        for (int off = 4; off > 0; off >>= 1) {
            s  += __shfl_xor_sync(0xffffffffu, s, off);
            ss += __shfl_xor_sync(0xffffffffu, ss, off);
        }
        if (l == 0) { sa[0] = s; sbuf[0] = ss; }
    }
    __syncthreads();
    s = sa[0]; ss = sbuf[0];

    float mean = s / (float)D;
    float var  = (ss - s * s / (float)D) / (float)(D - 1);
    float rstd = rsqrtf(var);

    const float* rr = res + row * D;
    float* orow = out + row * D;
    for (int i = threadIdx.x; i < D; i += 256) {
        float o = rr[i] + (xr[i] - mean) * rstd;
        orow[i] = o;
        if (F16OUT) h16[row * D + i] = __float2half(o);
    }
}

// =====================================================================
extern "C" void kernel_launch(void* const* d_in, const int* in_sizes, int n_in,
                              void* d_out, int out_size)
{
    const float* q  = (const float*)d_in[0];
    const float* k  = (const float*)d_in[1];
    const float* v  = (const float*)d_in[2];
    const float* Wq = (const float*)d_in[3];
    const float* bq = (const float*)d_in[4];
    const float* Wk = (const float*)d_in[5];
    const float* bk = (const float*)d_in[6];
    const float* Wv = (const float*)d_in[7];
    const float* bv = (const float*)d_in[8];
    const float* W1 = (const float*)d_in[9];
    const float* b1 = (const float*)d_in[10];
    const float* W2 = (const float*)d_in[11];
    const float* b2 = (const float*)d_in[12];

    float *tmp, *mh, *res1;
    __half *A16, *F16, *W1t, *W2t, *Wq16, *Wk16, *Wv16, *Qh, *Kh, *Vh;
    cudaGetSymbolAddress((void**)&tmp,  g_tmp);
    cudaGetSymbolAddress((void**)&mh,   g_mh);
    cudaGetSymbolAddress((void**)&res1, g_res1);
    cudaGetSymbolAddress((void**)&A16,  g_A16);
    cudaGetSymbolAddress((void**)&F16,  g_F16);
    cudaGetSymbolAddress((void**)&W1t,  g_W1t);
    cudaGetSymbolAddress((void**)&W2t,  g_W2t);
    cudaGetSymbolAddress((void**)&Wq16, g_Wq16);
    cudaGetSymbolAddress((void**)&Wk16, g_Wk16);
    cudaGetSymbolAddress((void**)&Wv16, g_Wv16);
    cudaGetSymbolAddress((void**)&Qh,   g_Qh);
    cudaGetSymbolAddress((void**)&Kh,   g_Kh);
    cudaGetSymbolAddress((void**)&Vh,   g_Vh);

    // q16 / k16 staged in first/second half of F16 (free until FF1 output)
    __half* v16 = A16;
    __half* q16 = F16;
    __half* k16 = F16 + (size_t)MROWS * DMODEL;

    cudaFuncSetAttribute(gemm_proj,
                         cudaFuncAttributeMaxDynamicSharedMemorySize, GEMM16_SMEM);
    cudaFuncSetAttribute(gemm_f16,
                         cudaFuncAttributeMaxDynamicSharedMemorySize, GEMM16_SMEM);
    cudaFuncSetAttribute(attn_mma,
                         cudaFuncAttributeMaxDynamicSharedMemorySize, ATT_SMEM);

    dim3 blk(256);
    dim3 gProj(DMODEL / BN, MROWS / BM, 3);   // z-batched QKV
    dim3 gFF1(DFF / BN, MROWS / BM);
    dim3 gFF2(DMODEL / BN, MROWS / BM);

    // all format conversions, one launch
    conv_wt_all<<<CW_BLOCKS, blk>>>(v, q, k, v16, q16, k16,
                                    Wq, Wk, Wv, W1, W2,
                                    Wq16, Wk16, Wv16, W1t, W2t);

    // Encoder calls multihead(v, q, k): Q-in=v, K-in=q, V-in=k
    gemm_proj<<<gProj, blk, GEMM16_SMEM>>>(v16, q16, k16, bq, bk, bv, Qh, Kh, Vh);

    attn_mma<<<dim3(SEQ / 128, BATCH * NHEAD), blk, ATT_SMEM>>>(Qh, Kh, Vh, mh);

    // res1 = q + LN(mh); also emit fp16 for FF1 (A16 reused)
    ln_res_k<1><<<MROWS, blk>>>(mh, q, res1, A16);

    gemm_f16<<<gFF1, blk, GEMM16_SMEM>>>(A16, W1t, b1, nullptr, F16,
                                         MROWS, DFF, DMODEL, 1);
    gemm_f16<<<gFF2, blk, GEMM16_SMEM>>>(F16, W2t, b2, tmp, nullptr,
                                         MROWS, DMODEL, DFF, 0);

    ln_res_k<0><<<MROWS, blk>>>(tmp, res1, (float*)d_out, nullptr);
}

// round 9
// speedup vs baseline: 10.2450x; 1.0981x over previous
#include <cuda_runtime.h>
#include <cuda_fp16.h>
#include <cstdint>

// Problem constants
#define BATCH 4
#define SEQ   2048
#define DMODEL 1024
#define NHEAD 8
#define HD    128
#define MROWS (BATCH*SEQ)        // 8192
#define DFF   4096
#define QKSCALE 0.08838834764831845f   // 1/sqrt(128)

// ---------------- scratch (no allocations allowed) ----------------
__device__ float g_tmp[(size_t)MROWS * DMODEL];
__device__ float g_mh[(size_t)MROWS * DMODEL];
__device__ float g_res1[(size_t)MROWS * DMODEL];
__device__ __half g_A16[(size_t)MROWS * DMODEL];     // v16, later LN1 fp16 out
__device__ __half g_F16[(size_t)MROWS * DFF];        // q16+k16 early, FF1 out later
__device__ __half g_W1t[(size_t)DFF * DMODEL];
__device__ __half g_W2t[(size_t)DFF * DMODEL];
__device__ __half g_Wq16[(size_t)DMODEL * DMODEL];
__device__ __half g_Wk16[(size_t)DMODEL * DMODEL];
__device__ __half g_Wv16[(size_t)DMODEL * DMODEL];
__device__ __half g_Qh[(size_t)MROWS * DMODEL];
__device__ __half g_Kh[(size_t)MROWS * DMODEL];
__device__ __half g_Vh[(size_t)MROWS * DMODEL];

// ======================= PTX helpers =======================
__device__ __forceinline__ uint32_t smem_u32(const void* p) {
    uint32_t a;
    asm("{ .reg .u64 t; cvta.to.shared.u64 t, %1; cvt.u32.u64 %0, t; }" : "=r"(a) : "l"(p));
    return a;
}
__device__ __forceinline__ void cp_async16(uint32_t saddr, const void* gaddr) {
    asm volatile("cp.async.cg.shared.global [%0], [%1], 16;" :: "r"(saddr), "l"(gaddr) : "memory");
}
#define CP_COMMIT() asm volatile("cp.async.commit_group;" ::: "memory")

__device__ __forceinline__ void ldmx4(uint32_t* r, uint32_t addr) {
    asm volatile("ldmatrix.sync.aligned.m8n8.x4.shared.b16 {%0,%1,%2,%3}, [%4];"
                 : "=r"(r[0]), "=r"(r[1]), "=r"(r[2]), "=r"(r[3]) : "r"(addr));
}
__device__ __forceinline__ void ldmx4t(uint32_t* r, uint32_t addr) {
    asm volatile("ldmatrix.sync.aligned.m8n8.x4.trans.shared.b16 {%0,%1,%2,%3}, [%4];"
                 : "=r"(r[0]), "=r"(r[1]), "=r"(r[2]), "=r"(r[3]) : "r"(addr));
}
__device__ __forceinline__ void mma_f16(float* c, const uint32_t* a,
                                        uint32_t b0, uint32_t b1) {
    asm volatile(
        "mma.sync.aligned.m16n8k16.row.col.f32.f16.f16.f32 "
        "{%0,%1,%2,%3}, {%4,%5,%6,%7}, {%8,%9}, {%0,%1,%2,%3};"
        : "+f"(c[0]), "+f"(c[1]), "+f"(c[2]), "+f"(c[3])
        : "r"(a[0]), "r"(a[1]), "r"(a[2]), "r"(a[3]), "r"(b0), "r"(b1));
}
__device__ __forceinline__ uint32_t packh2(float a, float b) {
    __half2 h = __floats2half2_rn(a, b);
    return *(uint32_t*)&h;
}

// =====================================================================
// fused conversions: inputs->fp16 AND all 5 weight transposes, ONE launch
// =====================================================================
#define N4SEG (MROWS * DMODEL / 4)     // 2M float4 per tensor
#define CONV_BLOCKS (3 * N4SEG / 256)  // 24576
#define WT_BLOCKS 11264
#define CW_BLOCKS (CONV_BLOCKS + WT_BLOCKS)

__global__ __launch_bounds__(256) void conv_wt_all(
    const float* __restrict__ x0, const float* __restrict__ x1,
    const float* __restrict__ x2,
    __half* __restrict__ o0c, __half* __restrict__ o1c, __half* __restrict__ o2c,
    const float* __restrict__ Wq, const float* __restrict__ Wk,
    const float* __restrict__ Wv, const float* __restrict__ W1,
    const float* __restrict__ W2,
    __half* __restrict__ oQ, __half* __restrict__ oK, __half* __restrict__ oV,
    __half* __restrict__ o1, __half* __restrict__ o2)
{
    __shared__ float t[32][33];
    if (blockIdx.x < CONV_BLOCKS) {
        int i = blockIdx.x * 256 + threadIdx.x;
        int seg = i / N4SEG;
        int j   = i - seg * N4SEG;
        const float* x = (seg == 0) ? x0 : (seg == 1) ? x1 : x2;
        __half* o      = (seg == 0) ? o0c : (seg == 1) ? o1c : o2c;
        float4 v = ((const float4*)x)[j];
        __half2* op = (__half2*)(o + (size_t)j * 4);
        op[0] = __floats2half2_rn(v.x, v.y);
        op[1] = __floats2half2_rn(v.z, v.w);
        return;
    }
    const int bid = blockIdx.x - CONV_BLOCKS;
    const float* W; __half* out; int K, N, l, gx;
    if (bid < 3072) {
        l = bid & 1023; gx = 32; K = DMODEL; N = DMODEL;
        int w = bid >> 10;
        W   = (w == 0) ? Wq : (w == 1) ? Wk : Wv;
        out = (w == 0) ? oQ : (w == 1) ? oK : oV;
    } else if (bid < 7168) {
        l = bid - 3072; gx = 128; K = DMODEL; N = DFF;  W = W1; out = o1;
    } else {
        l = bid - 7168; gx = 32;  K = DFF; N = DMODEL;  W = W2; out = o2;
    }
    const int bx = l % gx, by = l / gx;
    const int k0 = by * 32, n0 = bx * 32;
    int tx = threadIdx.x & 31, ty = threadIdx.x >> 5;
    #pragma unroll
    for (int i = ty; i < 32; i += 8)
        t[i][tx] = W[(size_t)(k0 + i) * N + n0 + tx];
    __syncthreads();
    #pragma unroll
    for (int i = ty; i < 32; i += 8)
        out[(size_t)(n0 + i) * K + k0 + tx] = __float2half(t[tx][i]);
}

// =====================================================================
// fp16 GEMM core: BK=64, NSTAGE=3, depth-1 prefetch, ONE barrier/chunk
// =====================================================================
#define BM 128
#define BN 128
#define BK 64
#define ROWB 144                       // 128B data + 16B pad
#define OPB  (128 * ROWB)              // 18432
#define NSTAGE 3
#define STAGE16 (2 * OPB)              // 36864
#define GEMM16_SMEM (NSTAGE * STAGE16) // 110592 (x2 blocks = 221184 <= 228KB)

__device__ __forceinline__ void prefetch16(
    uint32_t sbase, int stage, int c,
    const __half* A, const __half* B, int m0, int n0, int K, int tid)
{
    const int k0 = c * BK;
    const uint32_t sb = sbase + stage * STAGE16;
    #pragma unroll
    for (int t = 0; t < 4; t++) {
        int seg = tid + 256 * t;          // 0..1023
        int row = seg >> 3;               // 0..127
        int sc  = seg & 7;                // 16B segment in 128B row
        uint32_t soff = row * ROWB + sc * 16;
        cp_async16(sb + soff,       A + (size_t)(m0 + row) * K + k0 + sc * 8);
        cp_async16(sb + OPB + soff, B + (size_t)(n0 + row) * K + k0 + sc * 8);
    }
}

__device__ __forceinline__ void gemm_core(
    uint32_t sbase, const __half* A, const __half* B,
    int m0, int n0, int K, int tid, int wid, int lane,
    float acc[2][8][4])
{
    const int wm = wid >> 1;
    const int wn = wid & 1;
    const int NC = K / BK;

    prefetch16(sbase, 0, 0, A, B, m0, n0, K, tid); CP_COMMIT();

    const uint32_t lrow = (lane & 15);
    const uint32_t lcol = (lane >> 4) * 16;

    int stg_i = 0, stg_n = 1;
    for (int c = 0; c < NC; c++) {
        if (c + 1 < NC) {
            prefetch16(sbase, stg_n, c + 1, A, B, m0, n0, K, tid);
            CP_COMMIT();
            asm volatile("cp.async.wait_group 1;" ::: "memory");
        } else {
            asm volatile("cp.async.wait_group 0;" ::: "memory");
        }
        __syncthreads();   // single barrier per chunk (NS=3, depth-1 — safe)

        const uint32_t stg = sbase + stg_i * STAGE16;
        const uint32_t aBase = stg + (wm * 32) * ROWB + lrow * ROWB + lcol;
        const uint32_t bBase = stg + OPB + (wn * 64) * ROWB + lrow * ROWB + lcol;

        #pragma unroll
        for (int kk = 0; kk < 4; kk++) {          // four k16 steps per BK=64
            const uint32_t kb = kk * 32;
            uint32_t ah[2][4];
            #pragma unroll
            for (int mt = 0; mt < 2; mt++)
                ldmx4(ah[mt], aBase + mt * 16 * ROWB + kb);
            #pragma unroll
            for (int p = 0; p < 4; p++) {
                uint32_t bh[4];
                ldmx4(bh, bBase + p * 16 * ROWB + kb);
                #pragma unroll
                for (int mt = 0; mt < 2; mt++) {
                    mma_f16(acc[mt][2*p],   ah[mt], bh[0], bh[2]);
                    mma_f16(acc[mt][2*p+1], ah[mt], bh[1], bh[3]);
                }
            }
        }
        stg_i = stg_n;
        stg_n = (stg_n == 2) ? 0 : stg_n + 1;
    }
}

// ---- z-batched QKV projection: out fp16 head-permuted [B,H,S,hd] ----
__global__ __launch_bounds__(256, 2) void gemm_proj(
    const __half* __restrict__ A0, const __half* __restrict__ A1,
    const __half* __restrict__ A2,
    const float* __restrict__ b0c, const float* __restrict__ b1c,
    const float* __restrict__ b2c,
    __half* __restrict__ o0, __half* __restrict__ o1, __half* __restrict__ o2)
{
    extern __shared__ char smem[];
    const uint32_t sbase = smem_u32(smem);
    const int tid = threadIdx.x;
    const int wid = tid >> 5, lane = tid & 31;
    const int z = blockIdx.z;
    const int m0 = blockIdx.y * BM, n0 = blockIdx.x * BN;

    const __half* A  = (z == 0) ? A0 : (z == 1) ? A1 : A2;
    const float* bias = (z == 0) ? b0c : (z == 1) ? b1c : b2c;
    __half* Ch       = (z == 0) ? o0 : (z == 1) ? o1 : o2;
    const float scale = (z == 0) ? QKSCALE : 1.0f;

    float acc[2][8][4];
    #pragma unroll
    for (int i = 0; i < 2; i++)
        #pragma unroll
        for (int j = 0; j < 8; j++)
            #pragma unroll
            for (int x = 0; x < 4; x++) acc[i][j][x] = 0.f;

    const __half* B = (z == 0) ? g_Wq16 : (z == 1) ? g_Wk16 : g_Wv16;
    gemm_core(sbase, A, B, m0, n0, DMODEL, tid, wid, lane, acc);

    const int wm = wid >> 1, wn = wid & 1;
    const int rbase = m0 + wm * 32 + (lane >> 2);
    const int cbase = n0 + wn * 64 + (lane & 3) * 2;
    #pragma unroll
    for (int mt = 0; mt < 2; mt++) {
        #pragma unroll
        for (int nt = 0; nt < 8; nt++) {
            const int col = cbase + nt * 8;
            const float bz0 = bias[col], bz1 = bias[col + 1];
            #pragma unroll
            for (int h = 0; h < 2; h++) {
                const int row = rbase + mt * 16 + h * 8;
                float v0 = (acc[mt][nt][2*h]   + bz0) * scale;
                float v1 = (acc[mt][nt][2*h+1] + bz1) * scale;
                const int b = row >> 11, s = row & (SEQ - 1);
                const int hh = col >> 7, d = col & (HD - 1);
                *(__half2*)(Ch + (((size_t)b * NHEAD + hh) * SEQ + s) * HD + d)
                    = __floats2half2_rn(v0, v1);
            }
        }
    }
}

// ---- generic FF GEMM: mode 0 f32 out, mode 1 ReLU + fp16 out ----
__global__ __launch_bounds__(256, 2) void gemm_f16(
    const __half* __restrict__ A, const __half* __restrict__ B,
    const float* __restrict__ bias, float* __restrict__ Cf,
    __half* __restrict__ Ch, int M, int N, int K, int mode)
{
    extern __shared__ char smem[];
    const uint32_t sbase = smem_u32(smem);
    const int tid = threadIdx.x;
    const int wid = tid >> 5, lane = tid & 31;
    const int m0 = blockIdx.y * BM, n0 = blockIdx.x * BN;

    float acc[2][8][4];
    #pragma unroll
    for (int i = 0; i < 2; i++)
        #pragma unroll
        for (int j = 0; j < 8; j++)
            #pragma unroll
            for (int x = 0; x < 4; x++) acc[i][j][x] = 0.f;

    gemm_core(sbase, A, B, m0, n0, K, tid, wid, lane, acc);

    const int wm = wid >> 1, wn = wid & 1;
    const int rbase = m0 + wm * 32 + (lane >> 2);
    const int cbase = n0 + wn * 64 + (lane & 3) * 2;
    #pragma unroll
    for (int mt = 0; mt < 2; mt++) {
        #pragma unroll
        for (int nt = 0; nt < 8; nt++) {
            const int col = cbase + nt * 8;
            const float bz0 = bias[col], bz1 = bias[col + 1];
            #pragma unroll
            for (int h = 0; h < 2; h++) {
                const int row = rbase + mt * 16 + h * 8;
                float v0 = acc[mt][nt][2*h]   + bz0;
                float v1 = acc[mt][nt][2*h+1] + bz1;
                if (mode == 0) {
                    float* dst = Cf + (size_t)row * N + col;
                    dst[0] = v0; dst[1] = v1;
                } else {
                    v0 = fmaxf(v0, 0.f); v1 = fmaxf(v1, 0.f);
                    *(__half2*)(Ch + (size_t)row * N + col) = __floats2half2_rn(v0, v1);
                }
            }
        }
    }
}

// =====================================================================
// fp16 flash attention: K/V 4-stage ring, depth-2 prefetch, one barrier
// (unchanged from R8)
// =====================================================================
#define ASTRIDE 272
#define SQH 0
#define SKBASE 34816
#define KTILE_B (64 * ASTRIDE)
#define STAGE_SZ (2 * KTILE_B)
#define ANSTAGE 4
#define ATT_SMEM (SKBASE + ANSTAGE * STAGE_SZ)   // 174080

__device__ __forceinline__ void attn_prefetch(
    uint32_t sb, int stage, int kt,
    const __half* Kgb, const __half* Vgb, int tid)
{
    #pragma unroll
    for (int t = 0; t < 8; t++) {
        int idx = tid + t * 256;
        int tensor = idx >> 10;
        int row = (idx >> 4) & 63;
        int c   = idx & 15;
        uint32_t dst = sb + SKBASE + stage * STAGE_SZ + tensor * KTILE_B
                     + row * ASTRIDE + c * 16;
        const __half* src = (tensor ? Vgb : Kgb) + (size_t)(kt * 64 + row) * HD + c * 8;
        cp_async16(dst, src);
    }
}

__global__ __launch_bounds__(256, 1) void attn_mma(
    const __half* __restrict__ Qg, const __half* __restrict__ Kg,
    const __half* __restrict__ Vg, float* __restrict__ mh)
{
    extern __shared__ char smem[];
    const uint32_t sb = smem_u32(smem);
    const int tid = threadIdx.x;
    const int wid = tid >> 5, lane = tid & 31;
    const int qb = blockIdx.x;
    const int bh = blockIdx.y;
    const int b = bh >> 3, h = bh & 7;

    const __half* Qgb = Qg + ((size_t)bh * SEQ + qb * 128) * HD;
    #pragma unroll
    for (int t = 0; t < 8; t++) {
        int idx = tid + t * 256;
        int row = idx >> 4, c = idx & 15;
        cp_async16(sb + SQH + row * ASTRIDE + c * 16, Qgb + (size_t)row * HD + c * 8);
    }
    CP_COMMIT();
    const __half* Kgb = Kg + (size_t)bh * SEQ * HD;
    const __half* Vgb = Vg + (size_t)bh * SEQ * HD;
    attn_prefetch(sb, 0, 0, Kgb, Vgb, tid);
    CP_COMMIT();
    attn_prefetch(sb, 1, 1, Kgb, Vgb, tid);
    CP_COMMIT();

    asm volatile("cp.async.wait_group 2;" ::: "memory");
    __syncthreads();

    uint32_t qf[8][4];
    {
        const uint32_t qbase = sb + SQH + (wid * 16 + (lane & 15)) * ASTRIDE + (lane >> 4) * 16;
        #pragma unroll
        for (int ks = 0; ks < 8; ks++) ldmx4(qf[ks], qbase + ks * 32);
    }

    float oacc[16][4];
    #pragma unroll
    for (int i = 0; i < 16; i++)
        #pragma unroll
        for (int j = 0; j < 4; j++) oacc[i][j] = 0.f;
    float m0 = -1e30f, m1 = -1e30f, l0 = 0.f, l1 = 0.f;

    for (int kt = 0; kt < 32; kt++) {
        if (kt + 2 < 32) {
            attn_prefetch(sb, (kt + 2) & 3, kt + 2, Kgb, Vgb, tid);
            CP_COMMIT();
            asm volatile("cp.async.wait_group 2;" ::: "memory");
        } else {
            asm volatile("cp.async.wait_group 0;" ::: "memory");
        }
        __syncthreads();

        const uint32_t kbase = sb + SKBASE + (kt & 3) * STAGE_SZ;
        const uint32_t vbase = kbase + KTILE_B;

        float sacc[8][4];
        #pragma unroll
        for (int i = 0; i < 8; i++)
            #pragma unroll
            for (int j = 0; j < 4; j++) sacc[i][j] = 0.f;

        #pragma unroll
        for (int ks = 0; ks < 8; ks++) {
            const uint32_t colb = ks * 32 + (lane >> 4) * 16;
            #pragma unroll
            for (int p = 0; p < 4; p++) {
                uint32_t kf[4];
                ldmx4(kf, kbase + (p * 16 + (lane & 15)) * ASTRIDE + colb);
                mma_f16(sacc[2*p],   qf[ks], kf[0], kf[2]);
                mma_f16(sacc[2*p+1], qf[ks], kf[1], kf[3]);
            }
        }

        float mx0 = -1e30f, mx1 = -1e30f;
        #pragma unroll
        for (int n = 0; n < 8; n++) {
            mx0 = fmaxf(mx0, fmaxf(sacc[n][0], sacc[n][1]));
            mx1 = fmaxf(mx1, fmaxf(sacc[n][2], sacc[n][3]));
        }
        mx0 = fmaxf(mx0, __shfl_xor_sync(0xffffffffu, mx0, 1));
        mx0 = fmaxf(mx0, __shfl_xor_sync(0xffffffffu, mx0, 2));
        mx1 = fmaxf(mx1, __shfl_xor_sync(0xffffffffu, mx1, 1));
        mx1 = fmaxf(mx1, __shfl_xor_sync(0xffffffffu, mx1, 2));
        const float mn0 = fmaxf(m0, mx0), mn1 = fmaxf(m1, mx1);
        const float a0 = __expf(m0 - mn0), a1 = __expf(m1 - mn1);
        m0 = mn0; m1 = mn1;
        float sum0 = 0.f, sum1 = 0.f;
        #pragma unroll
        for (int n = 0; n < 8; n++) {
            sacc[n][0] = __expf(sacc[n][0] - mn0);
            sacc[n][1] = __expf(sacc[n][1] - mn0);
            sacc[n][2] = __expf(sacc[n][2] - mn1);
            sacc[n][3] = __expf(sacc[n][3] - mn1);
            sum0 += sacc[n][0] + sacc[n][1];
            sum1 += sacc[n][2] + sacc[n][3];
        }
        sum0 += __shfl_xor_sync(0xffffffffu, sum0, 1);
        sum0 += __shfl_xor_sync(0xffffffffu, sum0, 2);
        sum1 += __shfl_xor_sync(0xffffffffu, sum1, 1);
        sum1 += __shfl_xor_sync(0xffffffffu, sum1, 2);
        l0 = l0 * a0 + sum0; l1 = l1 * a1 + sum1;
        #pragma unroll
        for (int i = 0; i < 16; i++) {
            oacc[i][0] *= a0; oacc[i][1] *= a0;
            oacc[i][2] *= a1; oacc[i][3] *= a1;
        }

        uint32_t ph[4][4];
        #pragma unroll
        for (int t = 0; t < 4; t++) {
            ph[t][0] = packh2(sacc[2*t][0],   sacc[2*t][1]);
            ph[t][1] = packh2(sacc[2*t][2],   sacc[2*t][3]);
            ph[t][2] = packh2(sacc[2*t+1][0], sacc[2*t+1][1]);
            ph[t][3] = packh2(sacc[2*t+1][2], sacc[2*t+1][3]);
        }

        #pragma unroll
        for (int t = 0; t < 4; t++) {
            const uint32_t vrow = vbase + (t * 16 + (lane & 15)) * ASTRIDE + (lane >> 4) * 16;
            #pragma unroll
            for (int g = 0; g < 8; g++) {
                uint32_t vf[4];
                ldmx4t(vf, vrow + g * 32);
                mma_f16(oacc[2*g],   ph[t], vf[0], vf[1]);
                mma_f16(oacc[2*g+1], ph[t], vf[2], vf[3]);
            }
        }
    }

    const float inv0 = 1.f / l0, inv1 = 1.f / l1;
    const int row0 = qb * 128 + wid * 16 + (lane >> 2);
    float* base0 = mh + ((size_t)b * SEQ + row0) * DMODEL + h * HD + (lane & 3) * 2;
    float* base1 = base0 + 8 * DMODEL;
    #pragma unroll
    for (int nt = 0; nt < 16; nt++) {
        *(float2*)(base0 + nt * 8) = make_float2(oacc[nt][0] * inv0, oacc[nt][1] * inv0);
        *(float2*)(base1 + nt * 8) = make_float2(oacc[nt][2] * inv1, oacc[nt][3] * inv1);
    }
}

// =====================================================================
// LayerNorm (ddof=1, no eps) + residual — float4 vectorized.
// D=1024, 256 threads -> exactly one float4 per thread per pass.
// =====================================================================
template<int F16OUT>
__global__ __launch_bounds__(256) void ln_res_k(
    const float* __restrict__ x, const float* __restrict__ res,
    float* __restrict__ out, __half* __restrict__ h16)
{
    const int D = DMODEL;
    const size_t row = blockIdx.x;
    const float* xr = x + row * D;
    const int tid = threadIdx.x;

    float4 v4 = ((const float4*)xr)[tid];
    float s  = v4.x + v4.y + v4.z + v4.w;
    float ss = fmaf(v4.x, v4.x, fmaf(v4.y, v4.y, fmaf(v4.z, v4.z, v4.w * v4.w)));

    #pragma unroll
    for (int off = 16; off > 0; off >>= 1) {
        s  += __shfl_xor_sync(0xffffffffu, s, off);
        ss += __shfl_xor_sync(0xffffffffu, ss, off);
    }
    __shared__ float sa[8], sbuf[8];
    int w = tid >> 5, l = tid & 31;
    if (l == 0) { sa[w] = s; sbuf[w] = ss; }
    __syncthreads();
    if (tid < 32) {
        s  = (l < 8) ? sa[l] : 0.f;
        ss = (l < 8) ? sbuf[l] : 0.f;
        #pragma unroll
        for (int off = 4; off > 0; off >>= 1) {
            s  += __shfl_xor_sync(0xffffffffu, s, off);
            ss += __shfl_xor_sync(0xffffffffu, ss, off);
        }
        if (l == 0) { sa[0] = s; sbuf[0] = ss; }
    }
    __syncthreads();
    s = sa[0]; ss = sbuf[0];

    float mean = s / (float)D;
    float var  = (ss - s * s / (float)D) / (float)(D - 1);
    float rstd = rsqrtf(var);

    float4 r4 = ((const float4*)(res + row * D))[tid];
    float4 o4;
    o4.x = r4.x + (v4.x - mean) * rstd;
    o4.y = r4.y + (v4.y - mean) * rstd;
    o4.z = r4.z + (v4.z - mean) * rstd;
    o4.w = r4.w + (v4.w - mean) * rstd;
    ((float4*)(out + row * D))[tid] = o4;
    if (F16OUT) {
        __half2* hp = (__half2*)(h16 + row * D + tid * 4);
        hp[0] = __floats2half2_rn(o4.x, o4.y);
        hp[1] = __floats2half2_rn(o4.z, o4.w);
    }
}

// =====================================================================
extern "C" void kernel_launch(void* const* d_in, const int* in_sizes, int n_in,
                              void* d_out, int out_size)
{
    const float* q  = (const float*)d_in[0];
    const float* k  = (const float*)d_in[1];
    const float* v  = (const float*)d_in[2];
    const float* Wq = (const float*)d_in[3];
    const float* bq = (const float*)d_in[4];
    const float* Wk = (const float*)d_in[5];
    const float* bk = (const float*)d_in[6];
    const float* Wv = (const float*)d_in[7];
    const float* bv = (const float*)d_in[8];
    const float* W1 = (const float*)d_in[9];
    const float* b1 = (const float*)d_in[10];
    const float* W2 = (const float*)d_in[11];
    const float* b2 = (const float*)d_in[12];

    float *tmp, *mh, *res1;
    __half *A16, *F16, *W1t, *W2t, *Wq16, *Wk16, *Wv16, *Qh, *Kh, *Vh;
    cudaGetSymbolAddress((void**)&tmp,  g_tmp);
    cudaGetSymbolAddress((void**)&mh,   g_mh);
    cudaGetSymbolAddress((void**)&res1, g_res1);
    cudaGetSymbolAddress((void**)&A16,  g_A16);
    cudaGetSymbolAddress((void**)&F16,  g_F16);
    cudaGetSymbolAddress((void**)&W1t,  g_W1t);
    cudaGetSymbolAddress((void**)&W2t,  g_W2t);
    cudaGetSymbolAddress((void**)&Wq16, g_Wq16);
    cudaGetSymbolAddress((void**)&Wk16, g_Wk16);
    cudaGetSymbolAddress((void**)&Wv16, g_Wv16);
    cudaGetSymbolAddress((void**)&Qh,   g_Qh);
    cudaGetSymbolAddress((void**)&Kh,   g_Kh);
    cudaGetSymbolAddress((void**)&Vh,   g_Vh);

    // q16 / k16 staged in first/second half of F16 (free until FF1 output)
    __half* v16 = A16;
    __half* q16 = F16;
    __half* k16 = F16 + (size_t)MROWS * DMODEL;

    cudaFuncSetAttribute(gemm_proj,
                         cudaFuncAttributeMaxDynamicSharedMemorySize, GEMM16_SMEM);
    cudaFuncSetAttribute(gemm_f16,
                         cudaFuncAttributeMaxDynamicSharedMemorySize, GEMM16_SMEM);
    cudaFuncSetAttribute(attn_mma,
                         cudaFuncAttributeMaxDynamicSharedMemorySize, ATT_SMEM);

    dim3 blk(256);
    dim3 gProj(DMODEL / BN, MROWS / BM, 3);   // z-batched QKV
    dim3 gFF1(DFF / BN, MROWS / BM);
    dim3 gFF2(DMODEL / BN, MROWS / BM);

    // all format conversions, one launch
    conv_wt_all<<<CW_BLOCKS, blk>>>(v, q, k, v16, q16, k16,
                                    Wq, Wk, Wv, W1, W2,
                                    Wq16, Wk16, Wv16, W1t, W2t);

    // Encoder calls multihead(v, q, k): Q-in=v, K-in=q, V-in=k
    gemm_proj<<<gProj, blk, GEMM16_SMEM>>>(v16, q16, k16, bq, bk, bv, Qh, Kh, Vh);

    attn_mma<<<dim3(SEQ / 128, BATCH * NHEAD), blk, ATT_SMEM>>>(Qh, Kh, Vh, mh);

    // res1 = q + LN(mh); also emit fp16 for FF1 (A16 reused)
    ln_res_k<1><<<MROWS, blk>>>(mh, q, res1, A16);

    gemm_f16<<<gFF1, blk, GEMM16_SMEM>>>(A16, W1t, b1, nullptr, F16,
                                         MROWS, DFF, DMODEL, 1);
    gemm_f16<<<gFF2, blk, GEMM16_SMEM>>>(F16, W2t, b2, tmp, nullptr,
                                         MROWS, DMODEL, DFF, 0);

    ln_res_k<0><<<MROWS, blk>>>(tmp, res1, (float*)d_out, nullptr);
}